// round 4
// baseline (speedup 1.0000x reference)
#include <cuda_runtime.h>
#include <cuda_bf16.h>

#define NH   16
#define NN   64
#define CC   1024
#define BB   1024
#define PAD  68

typedef unsigned int u32;
typedef unsigned long long u64;
typedef unsigned short u16;

#define QKVSZ 67108864ull          // 1024*64*1024 elems

// Scratch (allocation-free rule: device globals)
__device__ u16   g_xhi [(size_t)BB * NN * CC];    // x transposed, bf16 hi [pixel][ch]
__device__ u16   g_xlo [(size_t)BB * NN * CC];
__device__ u16   g_whi [(size_t)4096 * CC];       // Wq,Wk,Wv,Wp fused rows
__device__ u16   g_wlo [(size_t)4096 * CC];
__device__ float g_qkv [3ull * QKVSZ];            // q,k,v fp32 [pixel][ch]
__device__ u16   g_ohi [(size_t)BB * NN * CC];    // attn out bf16 hi [pixel][ch]
__device__ u16   g_olo [(size_t)BB * NN * CC];
__device__ float g_proj[(size_t)BB * CC * NN];    // proj out [b][c][n]
__device__ float g_stats[2 * BB];

// ---------------------------------------------------------------------------
// helpers
// ---------------------------------------------------------------------------
__device__ __forceinline__ u32 smem_u32(const void* p) {
    u32 a;
    asm("{ .reg .u64 t; cvta.to.shared.u64 t, %1; cvt.u32.u64 %0, t; }" : "=r"(a) : "l"(p));
    return a;
}
__device__ __forceinline__ void cpa16(u32 dst, const void* src) {
    asm volatile("cp.async.cg.shared.global [%0], [%1], 16;" :: "r"(dst), "l"(src));
}
#define CP_COMMIT() asm volatile("cp.async.commit_group;" ::: "memory")
#define CP_WAIT1()  asm volatile("cp.async.wait_group 1;" ::: "memory")

__device__ __forceinline__ u32 lds32(u32 a) {
    u32 v; asm volatile("ld.shared.b32 %0, [%1];" : "=r"(v) : "r"(a)); return v;
}
__device__ __forceinline__ void mma16816(float* c, const u32* a, const u32* b) {
    asm volatile("mma.sync.aligned.m16n8k16.row.col.f32.bf16.bf16.f32 "
        "{%0,%1,%2,%3}, {%4,%5,%6,%7}, {%8,%9}, {%0,%1,%2,%3};"
        : "+f"(c[0]), "+f"(c[1]), "+f"(c[2]), "+f"(c[3])
        : "r"(a[0]), "r"(a[1]), "r"(a[2]), "r"(a[3]), "r"(b[0]), "r"(b[1]));
}
// swizzled smem byte address: rows of 64B (4 chunks), chunk ^= (row>>1)&3
__device__ __forceinline__ u32 sw_addr(u32 base, int row, int kbyte) {
    int chunk = kbyte >> 4, in = kbyte & 15;
    return base + row * 64 + ((chunk ^ ((row >> 1) & 3)) << 4) + in;
}
__device__ __forceinline__ u16 bf16hi_bits(float f) {
    return (u16)(__float_as_uint(f) >> 16);
}
__device__ __forceinline__ u16 bf16lo_bits(float f) {
    float hi = __uint_as_float(__float_as_uint(f) & 0xFFFF0000u);
    __nv_bfloat16 h = __float2bfloat16(f - hi);
    return *reinterpret_cast<u16*>(&h);
}

// FFMA2 helpers (attention)
typedef unsigned long long u64t;
__device__ __forceinline__ u64t pk2(float a, float b) {
    u64t r; asm("mov.b64 %0, {%1,%2};" : "=l"(r) : "f"(a), "f"(b)); return r;
}
__device__ __forceinline__ u64t ffma2(u64t a, u64t b, u64t c) {
    u64t d; asm("fma.rn.f32x2 %0, %1, %2, %3;" : "=l"(d) : "l"(a), "l"(b), "l"(c)); return d;
}
__device__ __forceinline__ float2 upk2(u64t v) {
    float lo, hi; asm("mov.b64 {%0,%1}, %2;" : "=f"(lo), "=f"(hi) : "l"(v));
    float2 f; f.x = lo; f.y = hi; return f;
}

// GEMM smem: 3 stages x 32KB (Ah 8K | Al 8K | Bh 8K | Bl 8K per stage)
#define STAGE_BYTES 32768
#define SM_GEMM     (3 * STAGE_BYTES)

// ---------------------------------------------------------------------------
// prep_w: 4 weight matrices -> fused hi/lo bf16 [4096][1024]
// ---------------------------------------------------------------------------
__global__ void __launch_bounds__(256) prep_w_kernel(
    const float* __restrict__ Wq, const float* __restrict__ Wk,
    const float* __restrict__ Wv, const float* __restrict__ Wp)
{
    int blk = blockIdx.x;
    int mat = blk >> 10;
    const float* src = (mat == 0) ? Wq : (mat == 1) ? Wk : (mat == 2) ? Wv : Wp;
    size_t idx = ((size_t)(blk & 1023) * 256 + threadIdx.x) * 4;
    float4 v = *(const float4*)(src + idx);
    size_t o = (size_t)mat * 1048576 + idx;
    ushort4 h, l;
    h.x = bf16hi_bits(v.x); h.y = bf16hi_bits(v.y);
    h.z = bf16hi_bits(v.z); h.w = bf16hi_bits(v.w);
    l.x = bf16lo_bits(v.x); l.y = bf16lo_bits(v.y);
    l.z = bf16lo_bits(v.z); l.w = bf16lo_bits(v.w);
    *(ushort4*)(g_whi + o) = h;
    *(ushort4*)(g_wlo + o) = l;
}

// ---------------------------------------------------------------------------
// prep_x: x[b][c][n] -> transposed hi/lo bf16 [pixel=b*64+n][c]
// ---------------------------------------------------------------------------
__global__ void __launch_bounds__(256) prep_x_kernel(const float* __restrict__ x) {
    __shared__ u16 hT[64][72];
    __shared__ u16 lT[64][72];
    const int b = blockIdx.x, t = threadIdx.x;
    const float* xb = x + (size_t)b * 65536;
    for (int ct = 0; ct < 16; ++ct) {
        #pragma unroll
        for (int i = 0; i < 16; ++i) {
            int idx = i * 256 + t, c = idx >> 6, n = idx & 63;
            float v = xb[(ct * 64 + c) * 64 + n];
            hT[n][c] = bf16hi_bits(v);
            lT[n][c] = bf16lo_bits(v);
        }
        __syncthreads();
        #pragma unroll
        for (int i = 0; i < 2; ++i) {
            int idx = i * 256 + t;
            int n = idx >> 3, c8 = (idx & 7) << 3;
            size_t o = (size_t)(b * 64 + n) * 1024 + ct * 64 + c8;
            *(uint4*)(g_xhi + o) = *(const uint4*)&hT[n][c8];
            *(uint4*)(g_xlo + o) = *(const uint4*)&lT[n][c8];
        }
        __syncthreads();
    }
}

// ---------------------------------------------------------------------------
// GEMM core: C[128 pix][128 ch] = A(hi+lo) x B(hi+lo)^T over K=1024.
// A,B bf16 [row][k] k-major, row stride 2048B. 8 warps, warp tile 64x32.
// 3-stage cp.async pipeline; 2 CTAs/SM.
// ---------------------------------------------------------------------------
__device__ __forceinline__ void gemm_issue_stage(
    u32 sb, int s, int c,
    const char* gAh, const char* gAl, const char* gBh, const char* gBl)
{
    const int t = threadIdx.x;
    const char* gsrc[4] = {gAh, gAl, gBh, gBl};
    u32 stb = sb + s * STAGE_BYTES;
    #pragma unroll
    for (int arr = 0; arr < 4; ++arr) {
        #pragma unroll
        for (int r2 = 0; r2 < 2; ++r2) {
            int ch = t + r2 * 256;
            int row = ch >> 2, part = ch & 3;
            u32 dst = stb + arr * 8192 + row * 64 + ((part ^ ((row >> 1) & 3)) << 4);
            const char* src = gsrc[arr] + (size_t)row * 2048 + c * 64 + part * 16;
            cpa16(dst, src);
        }
    }
    CP_COMMIT();
}

__device__ __forceinline__ void gemm_compute_stage(u32 sb, int s, float acc[4][4][4],
                                                   int wm, int wn, int grp, int tig)
{
    u32 stb = sb + s * STAGE_BYTES;
    u32 pAh = stb, pAl = stb + 8192, pBh = stb + 16384, pBl = stb + 24576;
    #pragma unroll
    for (int ks = 0; ks < 2; ++ks) {
        int kb = ks * 32 + tig * 4;
        u32 A[4][4], Bh[4][2], Bl[4][2];
        // pass 1: Ah x Bh
        #pragma unroll
        for (int i = 0; i < 4; ++i) {
            int r0 = wm + i * 16 + grp;
            A[i][0] = lds32(sw_addr(pAh, r0,     kb));
            A[i][1] = lds32(sw_addr(pAh, r0 + 8, kb));
            A[i][2] = lds32(sw_addr(pAh, r0,     kb + 16));
            A[i][3] = lds32(sw_addr(pAh, r0 + 8, kb + 16));
        }
        #pragma unroll
        for (int j = 0; j < 4; ++j) {
            int rn = wn + j * 8 + grp;
            Bh[j][0] = lds32(sw_addr(pBh, rn, kb));
            Bh[j][1] = lds32(sw_addr(pBh, rn, kb + 16));
        }
        #pragma unroll
        for (int i = 0; i < 4; ++i)
            #pragma unroll
            for (int j = 0; j < 4; ++j) mma16816(acc[i][j], A[i], Bh[j]);
        // pass 2: Ah x Bl (A kept in regs)
        #pragma unroll
        for (int j = 0; j < 4; ++j) {
            int rn = wn + j * 8 + grp;
            Bl[j][0] = lds32(sw_addr(pBl, rn, kb));
            Bl[j][1] = lds32(sw_addr(pBl, rn, kb + 16));
        }
        #pragma unroll
        for (int i = 0; i < 4; ++i)
            #pragma unroll
            for (int j = 0; j < 4; ++j) mma16816(acc[i][j], A[i], Bl[j]);
        // pass 3: Al x Bh (Bh kept in regs, A overwritten with Al)
        #pragma unroll
        for (int i = 0; i < 4; ++i) {
            int r0 = wm + i * 16 + grp;
            A[i][0] = lds32(sw_addr(pAl, r0,     kb));
            A[i][1] = lds32(sw_addr(pAl, r0 + 8, kb));
            A[i][2] = lds32(sw_addr(pAl, r0,     kb + 16));
            A[i][3] = lds32(sw_addr(pAl, r0 + 8, kb + 16));
        }
        #pragma unroll
        for (int i = 0; i < 4; ++i)
            #pragma unroll
            for (int j = 0; j < 4; ++j) mma16816(acc[i][j], A[i], Bh[j]);
    }
}

#define GEMM_MAINLOOP(gAh, gAl, gBh, gBl, acc)                                  \
    do {                                                                        \
        gemm_issue_stage(sb, 0, 0, gAh, gAl, gBh, gBl);                         \
        gemm_issue_stage(sb, 1, 1, gAh, gAl, gBh, gBl);                         \
        for (int c = 0; c < 32; ++c) {                                          \
            CP_WAIT1();                                                         \
            __syncthreads();                                                    \
            gemm_compute_stage(sb, c % 3, acc, wm, wn, grp, tig);               \
            if (c + 2 < 32) gemm_issue_stage(sb, (c + 2) % 3, c + 2, gAh, gAl, gBh, gBl); \
            else CP_COMMIT();                                                   \
        }                                                                       \
    } while (0)

// ---------------------------------------------------------------------------
// QKV GEMM: grid (24 ntiles, 512 pixel-groups). out fp32 q/k/v [pixel][ch]+bias
// ---------------------------------------------------------------------------
__global__ void __launch_bounds__(256, 2) qkv_gemm_kernel(
    const float* __restrict__ bq, const float* __restrict__ bk,
    const float* __restrict__ bv)
{
    extern __shared__ char smc[];
    const u32 sb = smem_u32(smc);
    const int t = threadIdx.x, wid = t >> 5, lane = t & 31;
    const int grp = lane >> 2, tig = lane & 3;
    const int wm = (wid & 1) << 6, wn = (wid >> 1) << 5;
    const int nt = blockIdx.x, mg = blockIdx.y;

    const char* gAh = (const char*)g_xhi + (size_t)mg * 128 * 2048;
    const char* gAl = (const char*)g_xlo + (size_t)mg * 128 * 2048;
    const char* gBh = (const char*)g_whi + (size_t)nt * 128 * 2048;
    const char* gBl = (const char*)g_wlo + (size_t)nt * 128 * 2048;

    float acc[4][4][4];
    #pragma unroll
    for (int i = 0; i < 4; ++i)
        #pragma unroll
        for (int j = 0; j < 4; ++j) { acc[i][j][0]=0.f; acc[i][j][1]=0.f; acc[i][j][2]=0.f; acc[i][j][3]=0.f; }

    GEMM_MAINLOOP(gAh, gAl, gBh, gBl, acc);

    const int sel = nt >> 3;
    const int cbase = (nt & 7) * 128;
    const float* bias = (sel == 0) ? bq : (sel == 1) ? bk : bv;
    float* out = g_qkv + (size_t)sel * QKVSZ;
    #pragma unroll
    for (int i = 0; i < 4; ++i) {
        int prow = mg * 128 + wm + i * 16 + grp;
        #pragma unroll
        for (int j = 0; j < 4; ++j) {
            int col = cbase + wn + j * 8 + tig * 2;
            float b0 = bias[col], b1 = bias[col + 1];
            float* o = out + (size_t)prow * 1024 + col;
            *(float2*)o = make_float2(acc[i][j][0] + b0, acc[i][j][1] + b1);
            *(float2*)(o + 8 * 1024) = make_float2(acc[i][j][2] + b0, acc[i][j][3] + b1);
        }
    }
}

// ---------------------------------------------------------------------------
// Proj GEMM: grid (8 ntiles, 512 pixel-groups). A = attn out (hi/lo).
// Epilogue: smem transpose -> g_proj [b][c][n] + bias.
// ---------------------------------------------------------------------------
__global__ void __launch_bounds__(256, 2) proj_gemm_kernel(const float* __restrict__ bp)
{
    extern __shared__ char smc[];
    const u32 sb = smem_u32(smc);
    const int t = threadIdx.x, wid = t >> 5, lane = t & 31;
    const int grp = lane >> 2, tig = lane & 3;
    const int wm = (wid & 1) << 6, wn = (wid >> 1) << 5;
    const int nt = blockIdx.x, mg = blockIdx.y;

    const char* gAh = (const char*)g_ohi + (size_t)mg * 128 * 2048;
    const char* gAl = (const char*)g_olo + (size_t)mg * 128 * 2048;
    const char* gBh = (const char*)g_whi + (size_t)(3072 + nt * 128) * 2048;
    const char* gBl = (const char*)g_wlo + (size_t)(3072 + nt * 128) * 2048;

    float acc[4][4][4];
    #pragma unroll
    for (int i = 0; i < 4; ++i)
        #pragma unroll
        for (int j = 0; j < 4; ++j) { acc[i][j][0]=0.f; acc[i][j][1]=0.f; acc[i][j][2]=0.f; acc[i][j][3]=0.f; }

    GEMM_MAINLOOP(gAh, gAl, gBh, gBl, acc);

    __syncthreads();   // all warps done reading stage buffers before tile reuse
    // stash C tile [pm][cc] in smem
    float* tile = (float*)smc;
    #pragma unroll
    for (int i = 0; i < 4; ++i) {
        int pm = wm + i * 16 + grp;
        #pragma unroll
        for (int j = 0; j < 4; ++j) {
            int cc = wn + j * 8 + tig * 2;
            *(float2*)&tile[pm * 130 + cc] = make_float2(acc[i][j][0], acc[i][j][1]);
            *(float2*)&tile[(pm + 8) * 130 + cc] = make_float2(acc[i][j][2], acc[i][j][3]);
        }
    }
    __syncthreads();
    #pragma unroll
    for (int it = 0; it < 16; ++it) {
        int idx = it * 256 + t;
        int cc = idx >> 5;
        int q = idx & 31, half = q >> 4, n4 = (q & 15) << 2;
        int ch = nt * 128 + cc;
        float bi = bp[ch];
        int pm0 = half * 64 + n4;
        float4 v;
        v.x = tile[(pm0 + 0) * 130 + cc] + bi;
        v.y = tile[(pm0 + 1) * 130 + cc] + bi;
        v.z = tile[(pm0 + 2) * 130 + cc] + bi;
        v.w = tile[(pm0 + 3) * 130 + cc] + bi;
        int b = mg * 2 + half;
        *(float4*)(g_proj + (size_t)b * 65536 + (size_t)ch * 64 + n4) = v;
    }
}

// ---------------------------------------------------------------------------
// Attention: per (b, head). Reads g_qkv fp32 [pixel][ch]; writes hi/lo bf16.
// ---------------------------------------------------------------------------
__global__ void __launch_bounds__(256) attn_kernel(const float* __restrict__ temp_p)
{
    extern __shared__ float sm[];
    float* qs  = sm;                 // [d][n]
    float* ks  = sm + 64 * PAD;
    float* vsT = sm + 2 * 64 * PAD;  // [n][d]
    float* At  = sm + 3 * 64 * PAD;  // [m][n]
    float* cd  = sm + 4 * 64 * PAD;
    float* knv = cd + 64;

    const int t  = threadIdx.x;
    const int tx = t & 15, ty = t >> 4;
    const int b  = blockIdx.x >> 4;
    const int h  = blockIdx.x & 15;

    const size_t base = (size_t)b * 65536 + h * 64;
    const float* qg = g_qkv + base;
    const float* kg = g_qkv + QKVSZ + base;
    const float* vg = g_qkv + 2 * QKVSZ + base;

    #pragma unroll
    for (int i = 0; i < 4; ++i) {
        int idx = i * 256 + t;
        int n = idx >> 4, d4 = (idx & 15) << 2;
        size_t off = (size_t)n * 1024 + d4;
        float4 qv = *(const float4*)(qg + off);
        qs[(d4 + 0) * PAD + n] = qv.x; qs[(d4 + 1) * PAD + n] = qv.y;
        qs[(d4 + 2) * PAD + n] = qv.z; qs[(d4 + 3) * PAD + n] = qv.w;
        float4 kv = *(const float4*)(kg + off);
        ks[(d4 + 0) * PAD + n] = kv.x; ks[(d4 + 1) * PAD + n] = kv.y;
        ks[(d4 + 2) * PAD + n] = kv.z; ks[(d4 + 3) * PAD + n] = kv.w;
        float4 vv = *(const float4*)(vg + off);
        *(float4*)(vsT + n * PAD + d4) = vv;
    }
    __syncthreads();

    float tinv = 1.0f / (temp_p[0] + 1e-6f);
    if (t < 64) {
        float s = 0.f;
        #pragma unroll 8
        for (int n = 0; n < 64; ++n) { float v = qs[t * PAD + n]; s += v * v; }
        cd[t] = 1.0f / fmaxf(sqrtf(s), 1e-12f);
    } else if (t < 128) {
        int r = t - 64;
        float s = 0.f;
        #pragma unroll 8
        for (int n = 0; n < 64; ++n) { float v = ks[r * PAD + n]; s += v * v; }
        knv[r] = 1.0f / fmaxf(sqrtf(s), 1e-12f);
    }
    __syncthreads();
    for (int i = t; i < 64 * 64; i += 256) {
        int d = i >> 6, n = i & 63;
        qs[d * PAD + n] *= cd[d] * knv[d] * tinv;
    }
    __syncthreads();

    u64t sa[4][2];
    #pragma unroll
    for (int i = 0; i < 4; ++i) { sa[i][0] = 0ull; sa[i][1] = 0ull; }
    #pragma unroll 4
    for (int d = 0; d < 64; ++d) {
        float4 av = *(const float4*)(qs + d * PAD + (ty << 2));
        ulonglong2 bv2 = *(const ulonglong2*)(ks + d * PAD + (tx << 2));
        u64t a0 = pk2(av.x, av.x), a1 = pk2(av.y, av.y);
        u64t a2 = pk2(av.z, av.z), a3 = pk2(av.w, av.w);
        sa[0][0] = ffma2(a0, bv2.x, sa[0][0]); sa[0][1] = ffma2(a0, bv2.y, sa[0][1]);
        sa[1][0] = ffma2(a1, bv2.x, sa[1][0]); sa[1][1] = ffma2(a1, bv2.y, sa[1][1]);
        sa[2][0] = ffma2(a2, bv2.x, sa[2][0]); sa[2][1] = ffma2(a2, bv2.y, sa[2][1]);
        sa[3][0] = ffma2(a3, bv2.x, sa[3][0]); sa[3][1] = ffma2(a3, bv2.y, sa[3][1]);
    }

    #pragma unroll
    for (int i = 0; i < 4; ++i) {
        float2 s01 = upk2(sa[i][0]);
        float2 s23 = upk2(sa[i][1]);
        float s0 = s01.x, s1 = s01.y, s2 = s23.x, s3 = s23.y;
        float mx = fmaxf(fmaxf(s0, s1), fmaxf(s2, s3));
        #pragma unroll
        for (int o = 8; o; o >>= 1) mx = fmaxf(mx, __shfl_xor_sync(0xffffffffu, mx, o));
        float e0 = __expf(s0 - mx), e1 = __expf(s1 - mx);
        float e2 = __expf(s2 - mx), e3 = __expf(s3 - mx);
        float sum = e0 + e1 + e2 + e3;
        #pragma unroll
        for (int o = 8; o; o >>= 1) sum += __shfl_xor_sync(0xffffffffu, sum, o);
        float rinv = 1.0f / sum;
        int n = (ty << 2) + i, m0 = tx << 2;
        At[(m0 + 0) * PAD + n] = e0 * rinv;
        At[(m0 + 1) * PAD + n] = e1 * rinv;
        At[(m0 + 2) * PAD + n] = e2 * rinv;
        At[(m0 + 3) * PAD + n] = e3 * rinv;
    }
    __syncthreads();

    u64t oa[4][2];
    #pragma unroll
    for (int i = 0; i < 4; ++i) { oa[i][0] = 0ull; oa[i][1] = 0ull; }
    #pragma unroll 4
    for (int m = 0; m < 64; ++m) {
        float4 av = *(const float4*)(At + m * PAD + (ty << 2));
        ulonglong2 bv2 = *(const ulonglong2*)(vsT + m * PAD + (tx << 2));
        u64t a0 = pk2(av.x, av.x), a1 = pk2(av.y, av.y);
        u64t a2 = pk2(av.z, av.z), a3 = pk2(av.w, av.w);
        oa[0][0] = ffma2(a0, bv2.x, oa[0][0]); oa[0][1] = ffma2(a0, bv2.y, oa[0][1]);
        oa[1][0] = ffma2(a1, bv2.x, oa[1][0]); oa[1][1] = ffma2(a1, bv2.y, oa[1][1]);
        oa[2][0] = ffma2(a2, bv2.x, oa[2][0]); oa[2][1] = ffma2(a2, bv2.y, oa[2][1]);
        oa[3][0] = ffma2(a3, bv2.x, oa[3][0]); oa[3][1] = ffma2(a3, bv2.y, oa[3][1]);
    }
    #pragma unroll
    for (int i = 0; i < 4; ++i) {
        float2 v01 = upk2(oa[i][0]);
        float2 v23 = upk2(oa[i][1]);
        int n = (ty << 2) + i;
        size_t o = (size_t)(b * 64 + n) * 1024 + h * 64 + (tx << 2);
        ushort4 hh, ll;
        hh.x = bf16hi_bits(v01.x); hh.y = bf16hi_bits(v01.y);
        hh.z = bf16hi_bits(v23.x); hh.w = bf16hi_bits(v23.y);
        ll.x = bf16lo_bits(v01.x); ll.y = bf16lo_bits(v01.y);
        ll.z = bf16lo_bits(v23.x); ll.w = bf16lo_bits(v23.y);
        *(ushort4*)(g_ohi + o) = hh;
        *(ushort4*)(g_olo + o) = ll;
    }
}

// ---------------------------------------------------------------------------
// Stats + final LN
// ---------------------------------------------------------------------------
__global__ void __launch_bounds__(256) stats_kernel(
    const float* __restrict__ x, const float* __restrict__ gamma_p)
{
    __shared__ float r1[8], r2[8];
    const int b = blockIdx.x, t = threadIdx.x;
    const float g = gamma_p[0], og = 1.0f - g;
    const float* pb = g_proj + (size_t)b * 65536;
    const float* xb = x + (size_t)b * 65536;
    float s1 = 0.f, s2 = 0.f;
    for (int i = t * 4; i < 65536; i += 1024) {
        float4 p  = *(const float4*)(pb + i);
        float4 xx = *(const float4*)(xb + i);
        float a;
        a = g * p.x + og * xx.x; s1 += a; s2 += a * a;
        a = g * p.y + og * xx.y; s1 += a; s2 += a * a;
        a = g * p.z + og * xx.z; s1 += a; s2 += a * a;
        a = g * p.w + og * xx.w; s1 += a; s2 += a * a;
    }
    #pragma unroll
    for (int o = 16; o; o >>= 1) {
        s1 += __shfl_xor_sync(0xffffffffu, s1, o);
        s2 += __shfl_xor_sync(0xffffffffu, s2, o);
    }
    if ((t & 31) == 0) { r1[t >> 5] = s1; r2[t >> 5] = s2; }
    __syncthreads();
    if (t < 8) {
        s1 = r1[t]; s2 = r2[t];
        #pragma unroll
        for (int o = 4; o; o >>= 1) {
            s1 += __shfl_xor_sync(0x000000ffu, s1, o);
            s2 += __shfl_xor_sync(0x000000ffu, s2, o);
        }
        if (t == 0) {
            float mu  = s1 * (1.0f / 65536.0f);
            float var = s2 * (1.0f / 65536.0f) - mu * mu;
            g_stats[2 * b]     = mu;
            g_stats[2 * b + 1] = rsqrtf(var + 1e-5f);
        }
    }
}

__global__ void __launch_bounds__(256) final_kernel(
    const float* __restrict__ x, const float* __restrict__ gamma_p,
    const float* __restrict__ lnw, const float* __restrict__ lnb,
    float* __restrict__ y)
{
    size_t i4 = (size_t)blockIdx.x * 256 + threadIdx.x;
    int b   = (int)(i4 >> 14);
    int rem = (int)(i4 & 16383);
    size_t base = ((size_t)b << 16) + ((size_t)rem << 2);
    float4 p  = *(const float4*)(g_proj + base);
    float4 xx = *(const float4*)(x + base);
    float4 w  = *(const float4*)(lnw + ((size_t)rem << 2));
    float4 lb = *(const float4*)(lnb + ((size_t)rem << 2));
    float g = gamma_p[0], og = 1.0f - g;
    float mu = g_stats[2 * b], rs = g_stats[2 * b + 1];
    float4 o;
    o.x = (g * p.x + og * xx.x - mu) * rs * w.x + lb.x;
    o.y = (g * p.y + og * xx.y - mu) * rs * w.y + lb.y;
    o.z = (g * p.z + og * xx.z - mu) * rs * w.z + lb.z;
    o.w = (g * p.w + og * xx.w - mu) * rs * w.w + lb.w;
    *(float4*)(y + base) = o;
}

// ---------------------------------------------------------------------------
extern "C" void kernel_launch(void* const* d_in, const int* in_sizes, int n_in,
                              void* d_out, int out_size)
{
    const float* x     = (const float*)d_in[0];
    const float* Wq    = (const float*)d_in[1];
    const float* bq    = (const float*)d_in[2];
    const float* Wk    = (const float*)d_in[3];
    const float* bk    = (const float*)d_in[4];
    const float* Wv    = (const float*)d_in[5];
    const float* bv    = (const float*)d_in[6];
    const float* Wp    = (const float*)d_in[7];
    const float* bp    = (const float*)d_in[8];
    const float* gamma = (const float*)d_in[9];
    const float* temp  = (const float*)d_in[10];
    const float* lnw   = (const float*)d_in[11];
    const float* lnb   = (const float*)d_in[12];
    float* y = (float*)d_out;

    const int sm_att = (4 * 64 * PAD + 128) * (int)sizeof(float);
    cudaFuncSetAttribute(qkv_gemm_kernel, cudaFuncAttributeMaxDynamicSharedMemorySize, SM_GEMM);
    cudaFuncSetAttribute(proj_gemm_kernel, cudaFuncAttributeMaxDynamicSharedMemorySize, SM_GEMM);
    cudaFuncSetAttribute(attn_kernel, cudaFuncAttributeMaxDynamicSharedMemorySize, sm_att);

    prep_w_kernel<<<4096, 256>>>(Wq, Wk, Wv, Wp);
    prep_x_kernel<<<BB, 256>>>(x);
    qkv_gemm_kernel<<<dim3(24, 512), 256, SM_GEMM>>>(bq, bk, bv);
    attn_kernel<<<BB * NH, 256, sm_att>>>(temp);
    proj_gemm_kernel<<<dim3(8, 512), 256, SM_GEMM>>>(bp);
    stats_kernel<<<BB, 256>>>(x, gamma);
    final_kernel<<<65536, 256>>>(x, gamma, lnw, lnb, y);
}

// round 5
// speedup vs baseline: 1.4706x; 1.4706x over previous
#include <cuda_runtime.h>
#include <cuda_bf16.h>

#define NH   16
#define NN   64
#define CC   1024
#define BB   1024
#define PAD  68

typedef unsigned int u32;
typedef unsigned long long u64;
typedef unsigned short u16;

#define QKVSZ 67108864ull          // 1024*64*1024 elems

// Scratch (allocation-free rule: device globals)
__device__ u16   g_xhi [(size_t)BB * NN * CC];    // x transposed, bf16 hi [pixel][ch]
__device__ u16   g_xlo [(size_t)BB * NN * CC];
__device__ u16   g_whi [(size_t)4096 * CC];       // Wq,Wk,Wv,Wp fused rows
__device__ u16   g_wlo [(size_t)4096 * CC];
__device__ float g_qkv [3ull * QKVSZ];            // q,k,v fp32 [pixel][ch]
__device__ u16   g_ohi [(size_t)BB * NN * CC];    // attn out bf16 hi [pixel][ch]
__device__ u16   g_olo [(size_t)BB * NN * CC];
__device__ float g_proj[(size_t)BB * CC * NN];    // proj out [b][c][n]
__device__ float g_stats[2 * BB];

// ---------------------------------------------------------------------------
// helpers
// ---------------------------------------------------------------------------
__device__ __forceinline__ u32 smem_u32(const void* p) {
    u32 a;
    asm("{ .reg .u64 t; cvta.to.shared.u64 t, %1; cvt.u32.u64 %0, t; }" : "=r"(a) : "l"(p));
    return a;
}
__device__ __forceinline__ void cpa16(u32 dst, const void* src) {
    asm volatile("cp.async.cg.shared.global [%0], [%1], 16;" :: "r"(dst), "l"(src));
}
#define CP_COMMIT() asm volatile("cp.async.commit_group;" ::: "memory")
#define CP_WAIT2()  asm volatile("cp.async.wait_group 2;" ::: "memory")

__device__ __forceinline__ void ldsm_x4(u32* r, u32 addr) {
    asm volatile("ldmatrix.sync.aligned.m8n8.x4.shared.b16 {%0,%1,%2,%3}, [%4];"
        : "=r"(r[0]), "=r"(r[1]), "=r"(r[2]), "=r"(r[3]) : "r"(addr));
}
__device__ __forceinline__ void mma16816(float* c, const u32* a, const u32* b) {
    asm volatile("mma.sync.aligned.m16n8k16.row.col.f32.bf16.bf16.f32 "
        "{%0,%1,%2,%3}, {%4,%5,%6,%7}, {%8,%9}, {%0,%1,%2,%3};"
        : "+f"(c[0]), "+f"(c[1]), "+f"(c[2]), "+f"(c[3])
        : "r"(a[0]), "r"(a[1]), "r"(a[2]), "r"(a[3]), "r"(b[0]), "r"(b[1]));
}
// swizzled smem byte address: rows of 64B (4 chunks), chunk ^= (row>>1)&3
__device__ __forceinline__ u32 sw_addr(u32 base, int row, int kbyte) {
    int chunk = kbyte >> 4, in = kbyte & 15;
    return base + row * 64 + ((chunk ^ ((row >> 1) & 3)) << 4) + in;
}
__device__ __forceinline__ u16 bf16hi_bits(float f) {
    return (u16)(__float_as_uint(f) >> 16);
}
__device__ __forceinline__ u16 bf16lo_bits(float f) {
    float hi = __uint_as_float(__float_as_uint(f) & 0xFFFF0000u);
    __nv_bfloat16 h = __float2bfloat16(f - hi);
    return *reinterpret_cast<u16*>(&h);
}

// FFMA2 helpers (attention)
typedef unsigned long long u64t;
__device__ __forceinline__ u64t pk2(float a, float b) {
    u64t r; asm("mov.b64 %0, {%1,%2};" : "=l"(r) : "f"(a), "f"(b)); return r;
}
__device__ __forceinline__ u64t ffma2(u64t a, u64t b, u64t c) {
    u64t d; asm("fma.rn.f32x2 %0, %1, %2, %3;" : "=l"(d) : "l"(a), "l"(b), "l"(c)); return d;
}
__device__ __forceinline__ float2 upk2(u64t v) {
    float lo, hi; asm("mov.b64 {%0,%1}, %2;" : "=f"(lo), "=f"(hi) : "l"(v));
    float2 f; f.x = lo; f.y = hi; return f;
}

// GEMM smem: 4 stages x 32KB (Ah 8K | Al 8K | Bh 8K | Bl 8K per stage)
#define STAGE_BYTES 32768
#define SM_GEMM     (4 * STAGE_BYTES)

// ---------------------------------------------------------------------------
// prep_w: 4 weight matrices -> fused hi/lo bf16 [4096][1024]
// ---------------------------------------------------------------------------
__global__ void __launch_bounds__(256) prep_w_kernel(
    const float* __restrict__ Wq, const float* __restrict__ Wk,
    const float* __restrict__ Wv, const float* __restrict__ Wp)
{
    int blk = blockIdx.x;
    int mat = blk >> 10;
    const float* src = (mat == 0) ? Wq : (mat == 1) ? Wk : (mat == 2) ? Wv : Wp;
    size_t idx = ((size_t)(blk & 1023) * 256 + threadIdx.x) * 4;
    float4 v = *(const float4*)(src + idx);
    size_t o = (size_t)mat * 1048576 + idx;
    ushort4 h, l;
    h.x = bf16hi_bits(v.x); h.y = bf16hi_bits(v.y);
    h.z = bf16hi_bits(v.z); h.w = bf16hi_bits(v.w);
    l.x = bf16lo_bits(v.x); l.y = bf16lo_bits(v.y);
    l.z = bf16lo_bits(v.z); l.w = bf16lo_bits(v.w);
    *(ushort4*)(g_whi + o) = h;
    *(ushort4*)(g_wlo + o) = l;
}

// ---------------------------------------------------------------------------
// prep_x: x[b][c][n] -> transposed hi/lo bf16 [pixel=b*64+n][c]
// ---------------------------------------------------------------------------
__global__ void __launch_bounds__(256) prep_x_kernel(const float* __restrict__ x) {
    __shared__ u16 hT[64][72];
    __shared__ u16 lT[64][72];
    const int b = blockIdx.x, t = threadIdx.x;
    const float* xb = x + (size_t)b * 65536;
    for (int ct = 0; ct < 16; ++ct) {
        #pragma unroll
        for (int i = 0; i < 16; ++i) {
            int idx = i * 256 + t, c = idx >> 6, n = idx & 63;
            float v = xb[(ct * 64 + c) * 64 + n];
            hT[n][c] = bf16hi_bits(v);
            lT[n][c] = bf16lo_bits(v);
        }
        __syncthreads();
        #pragma unroll
        for (int i = 0; i < 2; ++i) {
            int idx = i * 256 + t;
            int n = idx >> 3, c8 = (idx & 7) << 3;
            size_t o = (size_t)(b * 64 + n) * 1024 + ct * 64 + c8;
            *(uint4*)(g_xhi + o) = *(const uint4*)&hT[n][c8];
            *(uint4*)(g_xlo + o) = *(const uint4*)&lT[n][c8];
        }
        __syncthreads();
    }
}

// ---------------------------------------------------------------------------
// GEMM core: C[128 pix][128 ch] = A(hi+lo) x B(hi+lo)^T over K=1024.
// A,B bf16 [row][k] k-major, row stride 2048B. 8 warps, warp tile 64x32.
// 4-stage cp.async pipeline, ldmatrix fragment loads.
// ---------------------------------------------------------------------------
__device__ __forceinline__ void gemm_issue_stage(
    u32 sb, int s, int c,
    const char* gAh, const char* gAl, const char* gBh, const char* gBl)
{
    const int t = threadIdx.x;
    const char* gsrc[4] = {gAh, gAl, gBh, gBl};
    u32 stb = sb + s * STAGE_BYTES;
    #pragma unroll
    for (int arr = 0; arr < 4; ++arr) {
        #pragma unroll
        for (int r2 = 0; r2 < 2; ++r2) {
            int ch = t + r2 * 256;
            int row = ch >> 2, part = ch & 3;
            u32 dst = stb + arr * 8192 + row * 64 + ((part ^ ((row >> 1) & 3)) << 4);
            const char* src = gsrc[arr] + (size_t)row * 2048 + c * 64 + part * 16;
            cpa16(dst, src);
        }
    }
    CP_COMMIT();
}

__device__ __forceinline__ void gemm_compute_stage(u32 sb, int s, float acc[4][4][4],
                                                   int wm, int wn, int lane)
{
    u32 stb = sb + s * STAGE_BYTES;
    u32 pAh = stb, pAl = stb + 8192, pBh = stb + 16384, pBl = stb + 24576;
    // ldmatrix lane->row/kchunk mapping (plain, non-trans; layout is [row][k])
    const int arow = lane & 15;              // A: lanes 0-15 rows m0..15 @kb, 16-31 same rows @kb+16
    const int akb  = (lane >> 4) << 4;
    const int brow = (lane & 7) + ((lane & 16) >> 1);  // B: +8 rows for lanes>=16
    const int bkb  = (lane & 8) << 1;                  // kb+16 for lanes 8-15,24-31
    #pragma unroll
    for (int ks = 0; ks < 2; ++ks) {
        int kb = ks * 32;
        u32 A[4][4], Bh[4][2], Bl[4][2];
        #pragma unroll
        for (int i = 0; i < 4; ++i)
            ldsm_x4(A[i], sw_addr(pAh, wm + i * 16 + arow, kb + akb));
        #pragma unroll
        for (int jp = 0; jp < 2; ++jp) {
            u32 r[4];
            ldsm_x4(r, sw_addr(pBh, wn + jp * 16 + brow, kb + bkb));
            Bh[jp*2][0] = r[0]; Bh[jp*2][1] = r[1];
            Bh[jp*2+1][0] = r[2]; Bh[jp*2+1][1] = r[3];
            ldsm_x4(r, sw_addr(pBl, wn + jp * 16 + brow, kb + bkb));
            Bl[jp*2][0] = r[0]; Bl[jp*2][1] = r[1];
            Bl[jp*2+1][0] = r[2]; Bl[jp*2+1][1] = r[3];
        }
        // pass 1: Ah x Bh
        #pragma unroll
        for (int i = 0; i < 4; ++i)
            #pragma unroll
            for (int j = 0; j < 4; ++j) mma16816(acc[i][j], A[i], Bh[j]);
        // pass 2: Ah x Bl
        #pragma unroll
        for (int i = 0; i < 4; ++i)
            #pragma unroll
            for (int j = 0; j < 4; ++j) mma16816(acc[i][j], A[i], Bl[j]);
        // pass 3: Al x Bh (A regs overwritten)
        #pragma unroll
        for (int i = 0; i < 4; ++i)
            ldsm_x4(A[i], sw_addr(pAl, wm + i * 16 + arow, kb + akb));
        #pragma unroll
        for (int i = 0; i < 4; ++i)
            #pragma unroll
            for (int j = 0; j < 4; ++j) mma16816(acc[i][j], A[i], Bh[j]);
    }
}

#define GEMM_MAINLOOP(gAh, gAl, gBh, gBl, acc)                                  \
    do {                                                                        \
        gemm_issue_stage(sb, 0, 0, gAh, gAl, gBh, gBl);                         \
        gemm_issue_stage(sb, 1, 1, gAh, gAl, gBh, gBl);                         \
        gemm_issue_stage(sb, 2, 2, gAh, gAl, gBh, gBl);                         \
        for (int c = 0; c < 32; ++c) {                                          \
            CP_WAIT2();                                                         \
            __syncthreads();                                                    \
            gemm_compute_stage(sb, c & 3, acc, wm, wn, lane);                   \
            if (c + 3 < 32) gemm_issue_stage(sb, (c + 3) & 3, c + 3, gAh, gAl, gBh, gBl); \
            else CP_COMMIT();                                                   \
        }                                                                       \
    } while (0)

// ---------------------------------------------------------------------------
// QKV GEMM: grid (24 ntiles, 512 pixel-groups). out fp32 q/k/v [pixel][ch]+bias
// ---------------------------------------------------------------------------
__global__ void __launch_bounds__(256) qkv_gemm_kernel(
    const float* __restrict__ bq, const float* __restrict__ bk,
    const float* __restrict__ bv)
{
    extern __shared__ char smc[];
    const u32 sb = smem_u32(smc);
    const int t = threadIdx.x, wid = t >> 5, lane = t & 31;
    const int grp = lane >> 2, tig = lane & 3;
    const int wm = (wid & 1) << 6, wn = (wid >> 1) << 5;
    const int nt = blockIdx.x, mg = blockIdx.y;

    const char* gAh = (const char*)g_xhi + (size_t)mg * 128 * 2048;
    const char* gAl = (const char*)g_xlo + (size_t)mg * 128 * 2048;
    const char* gBh = (const char*)g_whi + (size_t)nt * 128 * 2048;
    const char* gBl = (const char*)g_wlo + (size_t)nt * 128 * 2048;

    float acc[4][4][4];
    #pragma unroll
    for (int i = 0; i < 4; ++i)
        #pragma unroll
        for (int j = 0; j < 4; ++j) { acc[i][j][0]=0.f; acc[i][j][1]=0.f; acc[i][j][2]=0.f; acc[i][j][3]=0.f; }

    GEMM_MAINLOOP(gAh, gAl, gBh, gBl, acc);

    const int sel = nt >> 3;
    const int cbase = (nt & 7) * 128;
    const float* bias = (sel == 0) ? bq : (sel == 1) ? bk : bv;
    float* out = g_qkv + (size_t)sel * QKVSZ;
    #pragma unroll
    for (int i = 0; i < 4; ++i) {
        int prow = mg * 128 + wm + i * 16 + grp;
        #pragma unroll
        for (int j = 0; j < 4; ++j) {
            int col = cbase + wn + j * 8 + tig * 2;
            float b0 = bias[col], b1 = bias[col + 1];
            float* o = out + (size_t)prow * 1024 + col;
            *(float2*)o = make_float2(acc[i][j][0] + b0, acc[i][j][1] + b1);
            *(float2*)(o + 8 * 1024) = make_float2(acc[i][j][2] + b0, acc[i][j][3] + b1);
        }
    }
}

// ---------------------------------------------------------------------------
// Proj GEMM: grid (8 ntiles, 512 pixel-groups). A = attn out (hi/lo).
// Epilogue: smem transpose -> g_proj [b][c][n] + bias.
// ---------------------------------------------------------------------------
__global__ void __launch_bounds__(256) proj_gemm_kernel(const float* __restrict__ bp)
{
    extern __shared__ char smc[];
    const u32 sb = smem_u32(smc);
    const int t = threadIdx.x, wid = t >> 5, lane = t & 31;
    const int grp = lane >> 2, tig = lane & 3;
    const int wm = (wid & 1) << 6, wn = (wid >> 1) << 5;
    const int nt = blockIdx.x, mg = blockIdx.y;

    const char* gAh = (const char*)g_ohi + (size_t)mg * 128 * 2048;
    const char* gAl = (const char*)g_olo + (size_t)mg * 128 * 2048;
    const char* gBh = (const char*)g_whi + (size_t)(3072 + nt * 128) * 2048;
    const char* gBl = (const char*)g_wlo + (size_t)(3072 + nt * 128) * 2048;

    float acc[4][4][4];
    #pragma unroll
    for (int i = 0; i < 4; ++i)
        #pragma unroll
        for (int j = 0; j < 4; ++j) { acc[i][j][0]=0.f; acc[i][j][1]=0.f; acc[i][j][2]=0.f; acc[i][j][3]=0.f; }

    GEMM_MAINLOOP(gAh, gAl, gBh, gBl, acc);

    __syncthreads();   // all warps done with stage buffers before tile reuse
    // stash C tile [pm][cc] in smem
    float* tile = (float*)smc;
    #pragma unroll
    for (int i = 0; i < 4; ++i) {
        int pm = wm + i * 16 + grp;
        #pragma unroll
        for (int j = 0; j < 4; ++j) {
            int cc = wn + j * 8 + tig * 2;
            *(float2*)&tile[pm * 130 + cc] = make_float2(acc[i][j][0], acc[i][j][1]);
            *(float2*)&tile[(pm + 8) * 130 + cc] = make_float2(acc[i][j][2], acc[i][j][3]);
        }
    }
    __syncthreads();
    #pragma unroll
    for (int it = 0; it < 16; ++it) {
        int idx = it * 256 + t;
        int cc = idx >> 5;
        int q = idx & 31, half = q >> 4, n4 = (q & 15) << 2;
        int ch = nt * 128 + cc;
        float bi = bp[ch];
        int pm0 = half * 64 + n4;
        float4 v;
        v.x = tile[(pm0 + 0) * 130 + cc] + bi;
        v.y = tile[(pm0 + 1) * 130 + cc] + bi;
        v.z = tile[(pm0 + 2) * 130 + cc] + bi;
        v.w = tile[(pm0 + 3) * 130 + cc] + bi;
        int b = mg * 2 + half;
        *(float4*)(g_proj + (size_t)b * 65536 + (size_t)ch * 64 + n4) = v;
    }
}

// ---------------------------------------------------------------------------
// Attention: per (b, head). Reads g_qkv fp32 [pixel][ch]; writes hi/lo bf16.
// ---------------------------------------------------------------------------
__global__ void __launch_bounds__(256) attn_kernel(const float* __restrict__ temp_p)
{
    extern __shared__ float sm[];
    float* qs  = sm;                 // [d][n]
    float* ks  = sm + 64 * PAD;
    float* vsT = sm + 2 * 64 * PAD;  // [n][d]
    float* At  = sm + 3 * 64 * PAD;  // [m][n]
    float* cd  = sm + 4 * 64 * PAD;
    float* knv = cd + 64;

    const int t  = threadIdx.x;
    const int tx = t & 15, ty = t >> 4;
    const int b  = blockIdx.x >> 4;
    const int h  = blockIdx.x & 15;

    const size_t base = (size_t)b * 65536 + h * 64;
    const float* qg = g_qkv + base;
    const float* kg = g_qkv + QKVSZ + base;
    const float* vg = g_qkv + 2 * QKVSZ + base;

    #pragma unroll
    for (int i = 0; i < 4; ++i) {
        int idx = i * 256 + t;
        int n = idx >> 4, d4 = (idx & 15) << 2;
        size_t off = (size_t)n * 1024 + d4;
        float4 qv = *(const float4*)(qg + off);
        qs[(d4 + 0) * PAD + n] = qv.x; qs[(d4 + 1) * PAD + n] = qv.y;
        qs[(d4 + 2) * PAD + n] = qv.z; qs[(d4 + 3) * PAD + n] = qv.w;
        float4 kv = *(const float4*)(kg + off);
        ks[(d4 + 0) * PAD + n] = kv.x; ks[(d4 + 1) * PAD + n] = kv.y;
        ks[(d4 + 2) * PAD + n] = kv.z; ks[(d4 + 3) * PAD + n] = kv.w;
        float4 vv = *(const float4*)(vg + off);
        *(float4*)(vsT + n * PAD + d4) = vv;
    }
    __syncthreads();

    float tinv = 1.0f / (temp_p[0] + 1e-6f);
    if (t < 64) {
        float s = 0.f;
        #pragma unroll 8
        for (int n = 0; n < 64; ++n) { float v = qs[t * PAD + n]; s += v * v; }
        cd[t] = 1.0f / fmaxf(sqrtf(s), 1e-12f);
    } else if (t < 128) {
        int r = t - 64;
        float s = 0.f;
        #pragma unroll 8
        for (int n = 0; n < 64; ++n) { float v = ks[r * PAD + n]; s += v * v; }
        knv[r] = 1.0f / fmaxf(sqrtf(s), 1e-12f);
    }
    __syncthreads();
    for (int i = t; i < 64 * 64; i += 256) {
        int d = i >> 6, n = i & 63;
        qs[d * PAD + n] *= cd[d] * knv[d] * tinv;
    }
    __syncthreads();

    u64t sa[4][2];
    #pragma unroll
    for (int i = 0; i < 4; ++i) { sa[i][0] = 0ull; sa[i][1] = 0ull; }
    #pragma unroll 4
    for (int d = 0; d < 64; ++d) {
        float4 av = *(const float4*)(qs + d * PAD + (ty << 2));
        ulonglong2 bv2 = *(const ulonglong2*)(ks + d * PAD + (tx << 2));
        u64t a0 = pk2(av.x, av.x), a1 = pk2(av.y, av.y);
        u64t a2 = pk2(av.z, av.z), a3 = pk2(av.w, av.w);
        sa[0][0] = ffma2(a0, bv2.x, sa[0][0]); sa[0][1] = ffma2(a0, bv2.y, sa[0][1]);
        sa[1][0] = ffma2(a1, bv2.x, sa[1][0]); sa[1][1] = ffma2(a1, bv2.y, sa[1][1]);
        sa[2][0] = ffma2(a2, bv2.x, sa[2][0]); sa[2][1] = ffma2(a2, bv2.y, sa[2][1]);
        sa[3][0] = ffma2(a3, bv2.x, sa[3][0]); sa[3][1] = ffma2(a3, bv2.y, sa[3][1]);
    }

    #pragma unroll
    for (int i = 0; i < 4; ++i) {
        float2 s01 = upk2(sa[i][0]);
        float2 s23 = upk2(sa[i][1]);
        float s0 = s01.x, s1 = s01.y, s2 = s23.x, s3 = s23.y;
        float mx = fmaxf(fmaxf(s0, s1), fmaxf(s2, s3));
        #pragma unroll
        for (int o = 8; o; o >>= 1) mx = fmaxf(mx, __shfl_xor_sync(0xffffffffu, mx, o));
        float e0 = __expf(s0 - mx), e1 = __expf(s1 - mx);
        float e2 = __expf(s2 - mx), e3 = __expf(s3 - mx);
        float sum = e0 + e1 + e2 + e3;
        #pragma unroll
        for (int o = 8; o; o >>= 1) sum += __shfl_xor_sync(0xffffffffu, sum, o);
        float rinv = 1.0f / sum;
        int n = (ty << 2) + i, m0 = tx << 2;
        At[(m0 + 0) * PAD + n] = e0 * rinv;
        At[(m0 + 1) * PAD + n] = e1 * rinv;
        At[(m0 + 2) * PAD + n] = e2 * rinv;
        At[(m0 + 3) * PAD + n] = e3 * rinv;
    }
    __syncthreads();

    u64t oa[4][2];
    #pragma unroll
    for (int i = 0; i < 4; ++i) { oa[i][0] = 0ull; oa[i][1] = 0ull; }
    #pragma unroll 4
    for (int m = 0; m < 64; ++m) {
        float4 av = *(const float4*)(At + m * PAD + (ty << 2));
        ulonglong2 bv2 = *(const ulonglong2*)(vsT + m * PAD + (tx << 2));
        u64t a0 = pk2(av.x, av.x), a1 = pk2(av.y, av.y);
        u64t a2 = pk2(av.z, av.z), a3 = pk2(av.w, av.w);
        oa[0][0] = ffma2(a0, bv2.x, oa[0][0]); oa[0][1] = ffma2(a0, bv2.y, oa[0][1]);
        oa[1][0] = ffma2(a1, bv2.x, oa[1][0]); oa[1][1] = ffma2(a1, bv2.y, oa[1][1]);
        oa[2][0] = ffma2(a2, bv2.x, oa[2][0]); oa[2][1] = ffma2(a2, bv2.y, oa[2][1]);
        oa[3][0] = ffma2(a3, bv2.x, oa[3][0]); oa[3][1] = ffma2(a3, bv2.y, oa[3][1]);
    }
    #pragma unroll
    for (int i = 0; i < 4; ++i) {
        float2 v01 = upk2(oa[i][0]);
        float2 v23 = upk2(oa[i][1]);
        int n = (ty << 2) + i;
        size_t o = (size_t)(b * 64 + n) * 1024 + h * 64 + (tx << 2);
        ushort4 hh, ll;
        hh.x = bf16hi_bits(v01.x); hh.y = bf16hi_bits(v01.y);
        hh.z = bf16hi_bits(v23.x); hh.w = bf16hi_bits(v23.y);
        ll.x = bf16lo_bits(v01.x); ll.y = bf16lo_bits(v01.y);
        ll.z = bf16lo_bits(v23.x); ll.w = bf16lo_bits(v23.y);
        *(ushort4*)(g_ohi + o) = hh;
        *(ushort4*)(g_olo + o) = ll;
    }
}

// ---------------------------------------------------------------------------
// Stats + final LN
// ---------------------------------------------------------------------------
__global__ void __launch_bounds__(256) stats_kernel(
    const float* __restrict__ x, const float* __restrict__ gamma_p)
{
    __shared__ float r1[8], r2[8];
    const int b = blockIdx.x, t = threadIdx.x;
    const float g = gamma_p[0], og = 1.0f - g;
    const float* pb = g_proj + (size_t)b * 65536;
    const float* xb = x + (size_t)b * 65536;
    float s1 = 0.f, s2 = 0.f;
    for (int i = t * 4; i < 65536; i += 1024) {
        float4 p  = *(const float4*)(pb + i);
        float4 xx = *(const float4*)(xb + i);
        float a;
        a = g * p.x + og * xx.x; s1 += a; s2 += a * a;
        a = g * p.y + og * xx.y; s1 += a; s2 += a * a;
        a = g * p.z + og * xx.z; s1 += a; s2 += a * a;
        a = g * p.w + og * xx.w; s1 += a; s2 += a * a;
    }
    #pragma unroll
    for (int o = 16; o; o >>= 1) {
        s1 += __shfl_xor_sync(0xffffffffu, s1, o);
        s2 += __shfl_xor_sync(0xffffffffu, s2, o);
    }
    if ((t & 31) == 0) { r1[t >> 5] = s1; r2[t >> 5] = s2; }
    __syncthreads();
    if (t < 8) {
        s1 = r1[t]; s2 = r2[t];
        #pragma unroll
        for (int o = 4; o; o >>= 1) {
            s1 += __shfl_xor_sync(0x000000ffu, s1, o);
            s2 += __shfl_xor_sync(0x000000ffu, s2, o);
        }
        if (t == 0) {
            float mu  = s1 * (1.0f / 65536.0f);
            float var = s2 * (1.0f / 65536.0f) - mu * mu;
            g_stats[2 * b]     = mu;
            g_stats[2 * b + 1] = rsqrtf(var + 1e-5f);
        }
    }
}

__global__ void __launch_bounds__(256) final_kernel(
    const float* __restrict__ x, const float* __restrict__ gamma_p,
    const float* __restrict__ lnw, const float* __restrict__ lnb,
    float* __restrict__ y)
{
    size_t i4 = (size_t)blockIdx.x * 256 + threadIdx.x;
    int b   = (int)(i4 >> 14);
    int rem = (int)(i4 & 16383);
    size_t base = ((size_t)b << 16) + ((size_t)rem << 2);
    float4 p  = *(const float4*)(g_proj + base);
    float4 xx = *(const float4*)(x + base);
    float4 w  = *(const float4*)(lnw + ((size_t)rem << 2));
    float4 lb = *(const float4*)(lnb + ((size_t)rem << 2));
    float g = gamma_p[0], og = 1.0f - g;
    float mu = g_stats[2 * b], rs = g_stats[2 * b + 1];
    float4 o;
    o.x = (g * p.x + og * xx.x - mu) * rs * w.x + lb.x;
    o.y = (g * p.y + og * xx.y - mu) * rs * w.y + lb.y;
    o.z = (g * p.z + og * xx.z - mu) * rs * w.z + lb.z;
    o.w = (g * p.w + og * xx.w - mu) * rs * w.w + lb.w;
    *(float4*)(y + base) = o;
}

// ---------------------------------------------------------------------------
extern "C" void kernel_launch(void* const* d_in, const int* in_sizes, int n_in,
                              void* d_out, int out_size)
{
    const float* x     = (const float*)d_in[0];
    const float* Wq    = (const float*)d_in[1];
    const float* bq    = (const float*)d_in[2];
    const float* Wk    = (const float*)d_in[3];
    const float* bk    = (const float*)d_in[4];
    const float* Wv    = (const float*)d_in[5];
    const float* bv    = (const float*)d_in[6];
    const float* Wp    = (const float*)d_in[7];
    const float* bp    = (const float*)d_in[8];
    const float* gamma = (const float*)d_in[9];
    const float* temp  = (const float*)d_in[10];
    const float* lnw   = (const float*)d_in[11];
    const float* lnb   = (const float*)d_in[12];
    float* y = (float*)d_out;

    const int sm_att = (4 * 64 * PAD + 128) * (int)sizeof(float);
    cudaFuncSetAttribute(qkv_gemm_kernel, cudaFuncAttributeMaxDynamicSharedMemorySize, SM_GEMM);
    cudaFuncSetAttribute(proj_gemm_kernel, cudaFuncAttributeMaxDynamicSharedMemorySize, SM_GEMM);
    cudaFuncSetAttribute(attn_kernel, cudaFuncAttributeMaxDynamicSharedMemorySize, sm_att);

    prep_w_kernel<<<4096, 256>>>(Wq, Wk, Wv, Wp);
    prep_x_kernel<<<BB, 256>>>(x);
    qkv_gemm_kernel<<<dim3(24, 512), 256, SM_GEMM>>>(bq, bk, bv);
    attn_kernel<<<BB * NH, 256, sm_att>>>(temp);
    proj_gemm_kernel<<<dim3(8, 512), 256, SM_GEMM>>>(bp);
    stats_kernel<<<BB, 256>>>(x, gamma);
    final_kernel<<<65536, 256>>>(x, gamma, lnw, lnb, y);
}

// round 6
// speedup vs baseline: 2.1461x; 1.4593x over previous
#include <cuda_runtime.h>
#include <cuda_fp16.h>

#define NH   16
#define NN   64
#define CC   1024
#define BB   1024
#define PAD  68

typedef unsigned int u32;
typedef unsigned long long u64;
typedef unsigned short u16;

#define QKVSZ 67108864ull          // 1024*64*1024 elems

// Scratch (allocation-free rule: device globals)
__device__ u16   g_xhi [(size_t)BB * NN * CC];    // x transposed, fp16 hi [pixel][ch]
__device__ u16   g_xlo [(size_t)BB * NN * CC];    // fp16 residual
__device__ u16   g_wf16[(size_t)4096 * CC];       // Wq,Wk,Wv,Wp fused rows, fp16 RN
__device__ float g_qkv [3ull * QKVSZ];            // q,k,v fp32 [pixel][ch]
__device__ u16   g_ohi [(size_t)BB * NN * CC];    // attn out fp16 hi [pixel][ch]
__device__ u16   g_olo [(size_t)BB * NN * CC];
__device__ float g_proj[(size_t)BB * CC * NN];    // proj out [b][c][n]
__device__ float g_stats[2 * BB];

// ---------------------------------------------------------------------------
// helpers
// ---------------------------------------------------------------------------
__device__ __forceinline__ u32 smem_u32(const void* p) {
    u32 a;
    asm("{ .reg .u64 t; cvta.to.shared.u64 t, %1; cvt.u32.u64 %0, t; }" : "=r"(a) : "l"(p));
    return a;
}
__device__ __forceinline__ void cpa16(u32 dst, const void* src) {
    asm volatile("cp.async.cg.shared.global [%0], [%1], 16;" :: "r"(dst), "l"(src));
}
#define CP_COMMIT() asm volatile("cp.async.commit_group;" ::: "memory")
#define CP_WAIT2()  asm volatile("cp.async.wait_group 2;" ::: "memory")

__device__ __forceinline__ void ldsm_x4(u32* r, u32 addr) {
    asm volatile("ldmatrix.sync.aligned.m8n8.x4.shared.b16 {%0,%1,%2,%3}, [%4];"
        : "=r"(r[0]), "=r"(r[1]), "=r"(r[2]), "=r"(r[3]) : "r"(addr));
}
__device__ __forceinline__ void mma16816(float* c, const u32* a, const u32* b) {
    asm volatile("mma.sync.aligned.m16n8k16.row.col.f32.f16.f16.f32 "
        "{%0,%1,%2,%3}, {%4,%5,%6,%7}, {%8,%9}, {%0,%1,%2,%3};"
        : "+f"(c[0]), "+f"(c[1]), "+f"(c[2]), "+f"(c[3])
        : "r"(a[0]), "r"(a[1]), "r"(a[2]), "r"(a[3]), "r"(b[0]), "r"(b[1]));
}
// swizzled smem byte address: rows of 64B (4 chunks), chunk ^= (row>>1)&3
__device__ __forceinline__ u32 sw_addr(u32 base, int row, int kbyte) {
    int chunk = kbyte >> 4, in = kbyte & 15;
    return base + row * 64 + ((chunk ^ ((row >> 1) & 3)) << 4) + in;
}
__device__ __forceinline__ u16 f16r(float f) {
    __half h = __float2half_rn(f);
    return *reinterpret_cast<u16*>(&h);
}
__device__ __forceinline__ float f16f(u16 b) {
    __half h; *reinterpret_cast<u16*>(&h) = b;
    return __half2float(h);
}
__device__ __forceinline__ void split16(float f, u16& hi, u16& lo) {
    hi = f16r(f);
    lo = f16r(f - f16f(hi));
}

// FFMA2 helpers (attention)
typedef unsigned long long u64t;
__device__ __forceinline__ u64t pk2(float a, float b) {
    u64t r; asm("mov.b64 %0, {%1,%2};" : "=l"(r) : "f"(a), "f"(b)); return r;
}
__device__ __forceinline__ u64t ffma2(u64t a, u64t b, u64t c) {
    u64t d; asm("fma.rn.f32x2 %0, %1, %2, %3;" : "=l"(d) : "l"(a), "l"(b), "l"(c)); return d;
}
__device__ __forceinline__ float2 upk2(u64t v) {
    float lo, hi; asm("mov.b64 {%0,%1}, %2;" : "=f"(lo), "=f"(hi) : "l"(v));
    float2 f; f.x = lo; f.y = hi; return f;
}

// GEMM smem: 4 stages x 24KB (Ah 8K | Al 8K | B 8K per stage)
#define STAGE_BYTES 24576
#define SM_GEMM     (4 * STAGE_BYTES)

// ---------------------------------------------------------------------------
// prep_w: 4 weight matrices -> fused fp16 [4096][1024]
// ---------------------------------------------------------------------------
__global__ void __launch_bounds__(256) prep_w_kernel(
    const float* __restrict__ Wq, const float* __restrict__ Wk,
    const float* __restrict__ Wv, const float* __restrict__ Wp)
{
    int blk = blockIdx.x;
    int mat = blk >> 10;
    const float* src = (mat == 0) ? Wq : (mat == 1) ? Wk : (mat == 2) ? Wv : Wp;
    size_t idx = ((size_t)(blk & 1023) * 256 + threadIdx.x) * 4;
    float4 v = *(const float4*)(src + idx);
    size_t o = (size_t)mat * 1048576 + idx;
    ushort4 h;
    h.x = f16r(v.x); h.y = f16r(v.y); h.z = f16r(v.z); h.w = f16r(v.w);
    *(ushort4*)(g_wf16 + o) = h;
}

// ---------------------------------------------------------------------------
// prep_x: x[b][c][n] -> transposed fp16 hi/lo [pixel=b*64+n][c]
// ---------------------------------------------------------------------------
__global__ void __launch_bounds__(256) prep_x_kernel(const float* __restrict__ x) {
    __shared__ u16 hT[64][72];
    __shared__ u16 lT[64][72];
    const int b = blockIdx.x, t = threadIdx.x;
    const float* xb = x + (size_t)b * 65536;
    for (int ct = 0; ct < 16; ++ct) {
        #pragma unroll
        for (int i = 0; i < 16; ++i) {
            int idx = i * 256 + t, c = idx >> 6, n = idx & 63;
            float v = xb[(ct * 64 + c) * 64 + n];
            split16(v, hT[n][c], lT[n][c]);
        }
        __syncthreads();
        #pragma unroll
        for (int i = 0; i < 2; ++i) {
            int idx = i * 256 + t;
            int n = idx >> 3, c8 = (idx & 7) << 3;
            size_t o = (size_t)(b * 64 + n) * 1024 + ct * 64 + c8;
            *(uint4*)(g_xhi + o) = *(const uint4*)&hT[n][c8];
            *(uint4*)(g_xlo + o) = *(const uint4*)&lT[n][c8];
        }
        __syncthreads();
    }
}

// ---------------------------------------------------------------------------
// GEMM core: C[128 pix][128 ch] = (Ah+Al) x B^T over K=1024, fp16 2-pass.
// A,B fp16 [row][k] k-major, row stride 2048B. 8 warps, warp tile 64x32.
// 4-stage cp.async pipeline, ldmatrix fragment loads.
// ---------------------------------------------------------------------------
__device__ __forceinline__ void gemm_issue_stage(
    u32 sb, int s, int c,
    const char* gAh, const char* gAl, const char* gB)
{
    const int t = threadIdx.x;
    const char* gsrc[3] = {gAh, gAl, gB};
    u32 stb = sb + s * STAGE_BYTES;
    #pragma unroll
    for (int arr = 0; arr < 3; ++arr) {
        #pragma unroll
        for (int r2 = 0; r2 < 2; ++r2) {
            int ch = t + r2 * 256;
            int row = ch >> 2, part = ch & 3;
            u32 dst = stb + arr * 8192 + row * 64 + ((part ^ ((row >> 1) & 3)) << 4);
            const char* src = gsrc[arr] + (size_t)row * 2048 + c * 64 + part * 16;
            cpa16(dst, src);
        }
    }
    CP_COMMIT();
}

__device__ __forceinline__ void gemm_compute_stage(u32 sb, int s, float acc[4][4][4],
                                                   int wm, int wn, int lane)
{
    u32 stb = sb + s * STAGE_BYTES;
    u32 pAh = stb, pAl = stb + 8192, pB = stb + 16384;
    // ldmatrix lane->row/kchunk mapping (plain, non-trans; layout is [row][k])
    const int arow = lane & 15;
    const int akb  = (lane >> 4) << 4;
    const int brow = (lane & 7) + ((lane & 16) >> 1);
    const int bkb  = (lane & 8) << 1;
    #pragma unroll
    for (int ks = 0; ks < 2; ++ks) {
        int kb = ks * 32;
        u32 A[4][4], B[4][2];
        #pragma unroll
        for (int i = 0; i < 4; ++i)
            ldsm_x4(A[i], sw_addr(pAh, wm + i * 16 + arow, kb + akb));
        #pragma unroll
        for (int jp = 0; jp < 2; ++jp) {
            u32 r[4];
            ldsm_x4(r, sw_addr(pB, wn + jp * 16 + brow, kb + bkb));
            B[jp*2][0] = r[0]; B[jp*2][1] = r[1];
            B[jp*2+1][0] = r[2]; B[jp*2+1][1] = r[3];
        }
        // pass 1: Ah x B
        #pragma unroll
        for (int i = 0; i < 4; ++i)
            #pragma unroll
            for (int j = 0; j < 4; ++j) mma16816(acc[i][j], A[i], B[j]);
        // pass 2: Al x B (A regs overwritten)
        #pragma unroll
        for (int i = 0; i < 4; ++i)
            ldsm_x4(A[i], sw_addr(pAl, wm + i * 16 + arow, kb + akb));
        #pragma unroll
        for (int i = 0; i < 4; ++i)
            #pragma unroll
            for (int j = 0; j < 4; ++j) mma16816(acc[i][j], A[i], B[j]);
    }
}

#define GEMM_MAINLOOP(gAh, gAl, gB, acc)                                        \
    do {                                                                        \
        gemm_issue_stage(sb, 0, 0, gAh, gAl, gB);                               \
        gemm_issue_stage(sb, 1, 1, gAh, gAl, gB);                               \
        gemm_issue_stage(sb, 2, 2, gAh, gAl, gB);                               \
        for (int c = 0; c < 32; ++c) {                                          \
            CP_WAIT2();                                                         \
            __syncthreads();                                                    \
            gemm_compute_stage(sb, c & 3, acc, wm, wn, lane);                   \
            if (c + 3 < 32) gemm_issue_stage(sb, (c + 3) & 3, c + 3, gAh, gAl, gB); \
            else CP_COMMIT();                                                   \
        }                                                                       \
    } while (0)

// ---------------------------------------------------------------------------
// QKV GEMM: grid (24 ntiles, 512 pixel-groups). out fp32 q/k/v [pixel][ch]+bias
// ---------------------------------------------------------------------------
__global__ void __launch_bounds__(256) qkv_gemm_kernel(
    const float* __restrict__ bq, const float* __restrict__ bk,
    const float* __restrict__ bv)
{
    extern __shared__ char smc[];
    const u32 sb = smem_u32(smc);
    const int t = threadIdx.x, wid = t >> 5, lane = t & 31;
    const int grp = lane >> 2, tig = lane & 3;
    const int wm = (wid & 1) << 6, wn = (wid >> 1) << 5;
    const int nt = blockIdx.x, mg = blockIdx.y;

    const char* gAh = (const char*)g_xhi + (size_t)mg * 128 * 2048;
    const char* gAl = (const char*)g_xlo + (size_t)mg * 128 * 2048;
    const char* gB  = (const char*)g_wf16 + (size_t)nt * 128 * 2048;

    float acc[4][4][4];
    #pragma unroll
    for (int i = 0; i < 4; ++i)
        #pragma unroll
        for (int j = 0; j < 4; ++j) { acc[i][j][0]=0.f; acc[i][j][1]=0.f; acc[i][j][2]=0.f; acc[i][j][3]=0.f; }

    GEMM_MAINLOOP(gAh, gAl, gB, acc);

    const int sel = nt >> 3;
    const int cbase = (nt & 7) * 128;
    const float* bias = (sel == 0) ? bq : (sel == 1) ? bk : bv;
    float* out = g_qkv + (size_t)sel * QKVSZ;
    #pragma unroll
    for (int i = 0; i < 4; ++i) {
        int prow = mg * 128 + wm + i * 16 + grp;
        #pragma unroll
        for (int j = 0; j < 4; ++j) {
            int col = cbase + wn + j * 8 + tig * 2;
            float b0 = bias[col], b1 = bias[col + 1];
            float* o = out + (size_t)prow * 1024 + col;
            *(float2*)o = make_float2(acc[i][j][0] + b0, acc[i][j][1] + b1);
            *(float2*)(o + 8 * 1024) = make_float2(acc[i][j][2] + b0, acc[i][j][3] + b1);
        }
    }
}

// ---------------------------------------------------------------------------
// Proj GEMM: grid (8 ntiles, 512 pixel-groups). A = attn out (hi/lo fp16).
// Epilogue: smem transpose -> g_proj [b][c][n] + bias.
// ---------------------------------------------------------------------------
__global__ void __launch_bounds__(256) proj_gemm_kernel(const float* __restrict__ bp)
{
    extern __shared__ char smc[];
    const u32 sb = smem_u32(smc);
    const int t = threadIdx.x, wid = t >> 5, lane = t & 31;
    const int grp = lane >> 2, tig = lane & 3;
    const int wm = (wid & 1) << 6, wn = (wid >> 1) << 5;
    const int nt = blockIdx.x, mg = blockIdx.y;

    const char* gAh = (const char*)g_ohi + (size_t)mg * 128 * 2048;
    const char* gAl = (const char*)g_olo + (size_t)mg * 128 * 2048;
    const char* gB  = (const char*)g_wf16 + (size_t)(3072 + nt * 128) * 2048;

    float acc[4][4][4];
    #pragma unroll
    for (int i = 0; i < 4; ++i)
        #pragma unroll
        for (int j = 0; j < 4; ++j) { acc[i][j][0]=0.f; acc[i][j][1]=0.f; acc[i][j][2]=0.f; acc[i][j][3]=0.f; }

    GEMM_MAINLOOP(gAh, gAl, gB, acc);

    __syncthreads();   // all warps done with stage buffers before tile reuse
    // stash C tile [pm][cc] in smem
    float* tile = (float*)smc;
    #pragma unroll
    for (int i = 0; i < 4; ++i) {
        int pm = wm + i * 16 + grp;
        #pragma unroll
        for (int j = 0; j < 4; ++j) {
            int cc = wn + j * 8 + tig * 2;
            *(float2*)&tile[pm * 130 + cc] = make_float2(acc[i][j][0], acc[i][j][1]);
            *(float2*)&tile[(pm + 8) * 130 + cc] = make_float2(acc[i][j][2], acc[i][j][3]);
        }
    }
    __syncthreads();
    #pragma unroll
    for (int it = 0; it < 16; ++it) {
        int idx = it * 256 + t;
        int cc = idx >> 5;
        int q = idx & 31, half = q >> 4, n4 = (q & 15) << 2;
        int ch = nt * 128 + cc;
        float bi = bp[ch];
        int pm0 = half * 64 + n4;
        float4 v;
        v.x = tile[(pm0 + 0) * 130 + cc] + bi;
        v.y = tile[(pm0 + 1) * 130 + cc] + bi;
        v.z = tile[(pm0 + 2) * 130 + cc] + bi;
        v.w = tile[(pm0 + 3) * 130 + cc] + bi;
        int b = mg * 2 + half;
        *(float4*)(g_proj + (size_t)b * 65536 + (size_t)ch * 64 + n4) = v;
    }
}

// ---------------------------------------------------------------------------
// Attention: per (b, head). Reads g_qkv fp32 [pixel][ch]; writes hi/lo fp16.
// ---------------------------------------------------------------------------
__global__ void __launch_bounds__(256) attn_kernel(const float* __restrict__ temp_p)
{
    extern __shared__ float sm[];
    float* qs  = sm;                 // [d][n]
    float* ks  = sm + 64 * PAD;
    float* vsT = sm + 2 * 64 * PAD;  // [n][d]
    float* At  = sm + 3 * 64 * PAD;  // [m][n]
    float* cd  = sm + 4 * 64 * PAD;
    float* knv = cd + 64;

    const int t  = threadIdx.x;
    const int tx = t & 15, ty = t >> 4;
    const int b  = blockIdx.x >> 4;
    const int h  = blockIdx.x & 15;

    const size_t base = (size_t)b * 65536 + h * 64;
    const float* qg = g_qkv + base;
    const float* kg = g_qkv + QKVSZ + base;
    const float* vg = g_qkv + 2 * QKVSZ + base;

    #pragma unroll
    for (int i = 0; i < 4; ++i) {
        int idx = i * 256 + t;
        int n = idx >> 4, d4 = (idx & 15) << 2;
        size_t off = (size_t)n * 1024 + d4;
        float4 qv = *(const float4*)(qg + off);
        qs[(d4 + 0) * PAD + n] = qv.x; qs[(d4 + 1) * PAD + n] = qv.y;
        qs[(d4 + 2) * PAD + n] = qv.z; qs[(d4 + 3) * PAD + n] = qv.w;
        float4 kv = *(const float4*)(kg + off);
        ks[(d4 + 0) * PAD + n] = kv.x; ks[(d4 + 1) * PAD + n] = kv.y;
        ks[(d4 + 2) * PAD + n] = kv.z; ks[(d4 + 3) * PAD + n] = kv.w;
        float4 vv = *(const float4*)(vg + off);
        *(float4*)(vsT + n * PAD + d4) = vv;
    }
    __syncthreads();

    float tinv = 1.0f / (temp_p[0] + 1e-6f);
    if (t < 64) {
        float s = 0.f;
        #pragma unroll 8
        for (int n = 0; n < 64; ++n) { float v = qs[t * PAD + n]; s += v * v; }
        cd[t] = 1.0f / fmaxf(sqrtf(s), 1e-12f);
    } else if (t < 128) {
        int r = t - 64;
        float s = 0.f;
        #pragma unroll 8
        for (int n = 0; n < 64; ++n) { float v = ks[r * PAD + n]; s += v * v; }
        knv[r] = 1.0f / fmaxf(sqrtf(s), 1e-12f);
    }
    __syncthreads();
    for (int i = t; i < 64 * 64; i += 256) {
        int d = i >> 6, n = i & 63;
        qs[d * PAD + n] *= cd[d] * knv[d] * tinv;
    }
    __syncthreads();

    u64t sa[4][2];
    #pragma unroll
    for (int i = 0; i < 4; ++i) { sa[i][0] = 0ull; sa[i][1] = 0ull; }
    #pragma unroll 4
    for (int d = 0; d < 64; ++d) {
        float4 av = *(const float4*)(qs + d * PAD + (ty << 2));
        ulonglong2 bv2 = *(const ulonglong2*)(ks + d * PAD + (tx << 2));
        u64t a0 = pk2(av.x, av.x), a1 = pk2(av.y, av.y);
        u64t a2 = pk2(av.z, av.z), a3 = pk2(av.w, av.w);
        sa[0][0] = ffma2(a0, bv2.x, sa[0][0]); sa[0][1] = ffma2(a0, bv2.y, sa[0][1]);
        sa[1][0] = ffma2(a1, bv2.x, sa[1][0]); sa[1][1] = ffma2(a1, bv2.y, sa[1][1]);
        sa[2][0] = ffma2(a2, bv2.x, sa[2][0]); sa[2][1] = ffma2(a2, bv2.y, sa[2][1]);
        sa[3][0] = ffma2(a3, bv2.x, sa[3][0]); sa[3][1] = ffma2(a3, bv2.y, sa[3][1]);
    }

    #pragma unroll
    for (int i = 0; i < 4; ++i) {
        float2 s01 = upk2(sa[i][0]);
        float2 s23 = upk2(sa[i][1]);
        float s0 = s01.x, s1 = s01.y, s2 = s23.x, s3 = s23.y;
        float mx = fmaxf(fmaxf(s0, s1), fmaxf(s2, s3));
        #pragma unroll
        for (int o = 8; o; o >>= 1) mx = fmaxf(mx, __shfl_xor_sync(0xffffffffu, mx, o));
        float e0 = __expf(s0 - mx), e1 = __expf(s1 - mx);
        float e2 = __expf(s2 - mx), e3 = __expf(s3 - mx);
        float sum = e0 + e1 + e2 + e3;
        #pragma unroll
        for (int o = 8; o; o >>= 1) sum += __shfl_xor_sync(0xffffffffu, sum, o);
        float rinv = 1.0f / sum;
        int n = (ty << 2) + i, m0 = tx << 2;
        At[(m0 + 0) * PAD + n] = e0 * rinv;
        At[(m0 + 1) * PAD + n] = e1 * rinv;
        At[(m0 + 2) * PAD + n] = e2 * rinv;
        At[(m0 + 3) * PAD + n] = e3 * rinv;
    }
    __syncthreads();

    u64t oa[4][2];
    #pragma unroll
    for (int i = 0; i < 4; ++i) { oa[i][0] = 0ull; oa[i][1] = 0ull; }
    #pragma unroll 4
    for (int m = 0; m < 64; ++m) {
        float4 av = *(const float4*)(At + m * PAD + (ty << 2));
        ulonglong2 bv2 = *(const ulonglong2*)(vsT + m * PAD + (tx << 2));
        u64t a0 = pk2(av.x, av.x), a1 = pk2(av.y, av.y);
        u64t a2 = pk2(av.z, av.z), a3 = pk2(av.w, av.w);
        oa[0][0] = ffma2(a0, bv2.x, oa[0][0]); oa[0][1] = ffma2(a0, bv2.y, oa[0][1]);
        oa[1][0] = ffma2(a1, bv2.x, oa[1][0]); oa[1][1] = ffma2(a1, bv2.y, oa[1][1]);
        oa[2][0] = ffma2(a2, bv2.x, oa[2][0]); oa[2][1] = ffma2(a2, bv2.y, oa[2][1]);
        oa[3][0] = ffma2(a3, bv2.x, oa[3][0]); oa[3][1] = ffma2(a3, bv2.y, oa[3][1]);
    }
    #pragma unroll
    for (int i = 0; i < 4; ++i) {
        float2 v01 = upk2(oa[i][0]);
        float2 v23 = upk2(oa[i][1]);
        int n = (ty << 2) + i;
        size_t o = (size_t)(b * 64 + n) * 1024 + h * 64 + (tx << 2);
        ushort4 hh, ll;
        split16(v01.x, hh.x, ll.x);
        split16(v01.y, hh.y, ll.y);
        split16(v23.x, hh.z, ll.z);
        split16(v23.y, hh.w, ll.w);
        *(ushort4*)(g_ohi + o) = hh;
        *(ushort4*)(g_olo + o) = ll;
    }
}

// ---------------------------------------------------------------------------
// Stats + final LN
// ---------------------------------------------------------------------------
__global__ void __launch_bounds__(256) stats_kernel(
    const float* __restrict__ x, const float* __restrict__ gamma_p)
{
    __shared__ float r1[8], r2[8];
    const int b = blockIdx.x, t = threadIdx.x;
    const float g = gamma_p[0], og = 1.0f - g;
    const float* pb = g_proj + (size_t)b * 65536;
    const float* xb = x + (size_t)b * 65536;
    float s1 = 0.f, s2 = 0.f;
    for (int i = t * 4; i < 65536; i += 1024) {
        float4 p  = *(const float4*)(pb + i);
        float4 xx = *(const float4*)(xb + i);
        float a;
        a = g * p.x + og * xx.x; s1 += a; s2 += a * a;
        a = g * p.y + og * xx.y; s1 += a; s2 += a * a;
        a = g * p.z + og * xx.z; s1 += a; s2 += a * a;
        a = g * p.w + og * xx.w; s1 += a; s2 += a * a;
    }
    #pragma unroll
    for (int o = 16; o; o >>= 1) {
        s1 += __shfl_xor_sync(0xffffffffu, s1, o);
        s2 += __shfl_xor_sync(0xffffffffu, s2, o);
    }
    if ((t & 31) == 0) { r1[t >> 5] = s1; r2[t >> 5] = s2; }
    __syncthreads();
    if (t < 8) {
        s1 = r1[t]; s2 = r2[t];
        #pragma unroll
        for (int o = 4; o; o >>= 1) {
            s1 += __shfl_xor_sync(0x000000ffu, s1, o);
            s2 += __shfl_xor_sync(0x000000ffu, s2, o);
        }
        if (t == 0) {
            float mu  = s1 * (1.0f / 65536.0f);
            float var = s2 * (1.0f / 65536.0f) - mu * mu;
            g_stats[2 * b]     = mu;
            g_stats[2 * b + 1] = rsqrtf(var + 1e-5f);
        }
    }
}

__global__ void __launch_bounds__(256) final_kernel(
    const float* __restrict__ x, const float* __restrict__ gamma_p,
    const float* __restrict__ lnw, const float* __restrict__ lnb,
    float* __restrict__ y)
{
    size_t i4 = (size_t)blockIdx.x * 256 + threadIdx.x;
    int b   = (int)(i4 >> 14);
    int rem = (int)(i4 & 16383);
    size_t base = ((size_t)b << 16) + ((size_t)rem << 2);
    float4 p  = *(const float4*)(g_proj + base);
    float4 xx = *(const float4*)(x + base);
    float4 w  = *(const float4*)(lnw + ((size_t)rem << 2));
    float4 lb = *(const float4*)(lnb + ((size_t)rem << 2));
    float g = gamma_p[0], og = 1.0f - g;
    float mu = g_stats[2 * b], rs = g_stats[2 * b + 1];
    float4 o;
    o.x = (g * p.x + og * xx.x - mu) * rs * w.x + lb.x;
    o.y = (g * p.y + og * xx.y - mu) * rs * w.y + lb.y;
    o.z = (g * p.z + og * xx.z - mu) * rs * w.z + lb.z;
    o.w = (g * p.w + og * xx.w - mu) * rs * w.w + lb.w;
    *(float4*)(y + base) = o;
}

// ---------------------------------------------------------------------------
extern "C" void kernel_launch(void* const* d_in, const int* in_sizes, int n_in,
                              void* d_out, int out_size)
{
    const float* x     = (const float*)d_in[0];
    const float* Wq    = (const float*)d_in[1];
    const float* bq    = (const float*)d_in[2];
    const float* Wk    = (const float*)d_in[3];
    const float* bk    = (const float*)d_in[4];
    const float* Wv    = (const float*)d_in[5];
    const float* bv    = (const float*)d_in[6];
    const float* Wp    = (const float*)d_in[7];
    const float* bp    = (const float*)d_in[8];
    const float* gamma = (const float*)d_in[9];
    const float* temp  = (const float*)d_in[10];
    const float* lnw   = (const float*)d_in[11];
    const float* lnb   = (const float*)d_in[12];
    float* y = (float*)d_out;

    const int sm_att = (4 * 64 * PAD + 128) * (int)sizeof(float);
    cudaFuncSetAttribute(qkv_gemm_kernel, cudaFuncAttributeMaxDynamicSharedMemorySize, SM_GEMM);
    cudaFuncSetAttribute(proj_gemm_kernel, cudaFuncAttributeMaxDynamicSharedMemorySize, SM_GEMM);
    cudaFuncSetAttribute(attn_kernel, cudaFuncAttributeMaxDynamicSharedMemorySize, sm_att);

    prep_w_kernel<<<4096, 256>>>(Wq, Wk, Wv, Wp);
    prep_x_kernel<<<BB, 256>>>(x);
    qkv_gemm_kernel<<<dim3(24, 512), 256, SM_GEMM>>>(bq, bk, bv);
    attn_kernel<<<BB * NH, 256, sm_att>>>(temp);
    proj_gemm_kernel<<<dim3(8, 512), 256, SM_GEMM>>>(bp);
    stats_kernel<<<BB, 256>>>(x, gamma);
    final_kernel<<<65536, 256>>>(x, gamma, lnw, lnb, y);
}

// round 7
// speedup vs baseline: 3.0293x; 1.4115x over previous
#include <cuda_runtime.h>
#include <cuda_fp16.h>

#define NH   16
#define NN   64
#define CC   1024
#define BB   1024
#define PAD  68

typedef unsigned int u32;
typedef unsigned long long u64;
typedef unsigned short u16;

#define QKVSZ 67108864ull          // 1024*64*1024 elems

// Scratch (allocation-free rule: device globals)
__device__ u16   g_xf16[(size_t)BB * NN * CC];    // x transposed, fp16 [pixel][ch]
__device__ u16   g_wf16[(size_t)4096 * CC];       // Wq,Wk,Wv,Wp fused rows, fp16 RN
__device__ float g_qkv [3ull * QKVSZ];            // q,k,v fp32 [pixel][ch]
__device__ u16   g_of16[(size_t)BB * NN * CC];    // attn out fp16 [pixel][ch]
__device__ float g_proj[(size_t)BB * CC * NN];    // proj out [b][c][n]
__device__ float g_stats[2 * BB];

// ---------------------------------------------------------------------------
// helpers
// ---------------------------------------------------------------------------
__device__ __forceinline__ u32 smem_u32(const void* p) {
    u32 a;
    asm("{ .reg .u64 t; cvta.to.shared.u64 t, %1; cvt.u32.u64 %0, t; }" : "=r"(a) : "l"(p));
    return a;
}
__device__ __forceinline__ void cpa16(u32 dst, const void* src) {
    asm volatile("cp.async.cg.shared.global [%0], [%1], 16;" :: "r"(dst), "l"(src));
}
#define CP_COMMIT() asm volatile("cp.async.commit_group;" ::: "memory")
#define CP_WAIT2()  asm volatile("cp.async.wait_group 2;" ::: "memory")

__device__ __forceinline__ void ldsm_x4(u32* r, u32 addr) {
    asm volatile("ldmatrix.sync.aligned.m8n8.x4.shared.b16 {%0,%1,%2,%3}, [%4];"
        : "=r"(r[0]), "=r"(r[1]), "=r"(r[2]), "=r"(r[3]) : "r"(addr));
}
__device__ __forceinline__ void mma16816(float* c, const u32* a, const u32* b) {
    asm volatile("mma.sync.aligned.m16n8k16.row.col.f32.f16.f16.f32 "
        "{%0,%1,%2,%3}, {%4,%5,%6,%7}, {%8,%9}, {%0,%1,%2,%3};"
        : "+f"(c[0]), "+f"(c[1]), "+f"(c[2]), "+f"(c[3])
        : "r"(a[0]), "r"(a[1]), "r"(a[2]), "r"(a[3]), "r"(b[0]), "r"(b[1]));
}
// swizzled smem byte address: rows of 64B (4 chunks), chunk ^= (row>>1)&3
__device__ __forceinline__ u32 sw_addr(u32 base, int row, int kbyte) {
    int chunk = kbyte >> 4, in = kbyte & 15;
    return base + row * 64 + ((chunk ^ ((row >> 1) & 3)) << 4) + in;
}
__device__ __forceinline__ u16 f16r(float f) {
    __half h = __float2half_rn(f);
    return *reinterpret_cast<u16*>(&h);
}

// FFMA2 helpers (attention)
typedef unsigned long long u64t;
__device__ __forceinline__ u64t pk2(float a, float b) {
    u64t r; asm("mov.b64 %0, {%1,%2};" : "=l"(r) : "f"(a), "f"(b)); return r;
}
__device__ __forceinline__ u64t ffma2(u64t a, u64t b, u64t c) {
    u64t d; asm("fma.rn.f32x2 %0, %1, %2, %3;" : "=l"(d) : "l"(a), "l"(b), "l"(c)); return d;
}
__device__ __forceinline__ float2 upk2(u64t v) {
    float lo, hi; asm("mov.b64 {%0,%1}, %2;" : "=f"(lo), "=f"(hi) : "l"(v));
    float2 f; f.x = lo; f.y = hi; return f;
}

// GEMM smem: 4 stages x 16KB (A 8K | B 8K per stage)
#define STAGE_BYTES 16384
#define SM_GEMM     (4 * STAGE_BYTES)

// ---------------------------------------------------------------------------
// prep_w: 4 weight matrices -> fused fp16 [4096][1024]
// ---------------------------------------------------------------------------
__global__ void __launch_bounds__(256) prep_w_kernel(
    const float* __restrict__ Wq, const float* __restrict__ Wk,
    const float* __restrict__ Wv, const float* __restrict__ Wp)
{
    int blk = blockIdx.x;
    int mat = blk >> 10;
    const float* src = (mat == 0) ? Wq : (mat == 1) ? Wk : (mat == 2) ? Wv : Wp;
    size_t idx = ((size_t)(blk & 1023) * 256 + threadIdx.x) * 4;
    float4 v = *(const float4*)(src + idx);
    size_t o = (size_t)mat * 1048576 + idx;
    ushort4 h;
    h.x = f16r(v.x); h.y = f16r(v.y); h.z = f16r(v.z); h.w = f16r(v.w);
    *(ushort4*)(g_wf16 + o) = h;
}

// ---------------------------------------------------------------------------
// prep_x: x[b][c][n] -> transposed fp16 [pixel=b*64+n][c]
// ---------------------------------------------------------------------------
__global__ void __launch_bounds__(256) prep_x_kernel(const float* __restrict__ x) {
    __shared__ u16 hT[64][72];
    const int b = blockIdx.x, t = threadIdx.x;
    const float* xb = x + (size_t)b * 65536;
    for (int ct = 0; ct < 16; ++ct) {
        #pragma unroll
        for (int i = 0; i < 16; ++i) {
            int idx = i * 256 + t, c = idx >> 6, n = idx & 63;
            hT[n][c] = f16r(xb[(ct * 64 + c) * 64 + n]);
        }
        __syncthreads();
        #pragma unroll
        for (int i = 0; i < 2; ++i) {
            int idx = i * 256 + t;
            int n = idx >> 3, c8 = (idx & 7) << 3;
            size_t o = (size_t)(b * 64 + n) * 1024 + ct * 64 + c8;
            *(uint4*)(g_xf16 + o) = *(const uint4*)&hT[n][c8];
        }
        __syncthreads();
    }
}

// ---------------------------------------------------------------------------
// GEMM core: C[128 pix][128 ch] = A x B^T over K=1024, fp16 single-pass.
// A,B fp16 [row][k] k-major, row stride 2048B. 8 warps, warp tile 64x32.
// 4-stage cp.async pipeline, ldmatrix fragment loads.
// ---------------------------------------------------------------------------
__device__ __forceinline__ void gemm_issue_stage(
    u32 sb, int s, int c, const char* gA, const char* gB)
{
    const int t = threadIdx.x;
    const char* gsrc[2] = {gA, gB};
    u32 stb = sb + s * STAGE_BYTES;
    #pragma unroll
    for (int arr = 0; arr < 2; ++arr) {
        #pragma unroll
        for (int r2 = 0; r2 < 2; ++r2) {
            int ch = t + r2 * 256;
            int row = ch >> 2, part = ch & 3;
            u32 dst = stb + arr * 8192 + row * 64 + ((part ^ ((row >> 1) & 3)) << 4);
            const char* src = gsrc[arr] + (size_t)row * 2048 + c * 64 + part * 16;
            cpa16(dst, src);
        }
    }
    CP_COMMIT();
}

__device__ __forceinline__ void gemm_compute_stage(u32 sb, int s, float acc[4][4][4],
                                                   int wm, int wn, int lane)
{
    u32 stb = sb + s * STAGE_BYTES;
    u32 pA = stb, pB = stb + 8192;
    // ldmatrix lane->row/kchunk mapping (plain, non-trans; layout is [row][k])
    const int arow = lane & 15;
    const int akb  = (lane >> 4) << 4;
    const int brow = (lane & 7) + ((lane & 16) >> 1);
    const int bkb  = (lane & 8) << 1;
    #pragma unroll
    for (int ks = 0; ks < 2; ++ks) {
        int kb = ks * 32;
        u32 A[4][4], B[4][2];
        #pragma unroll
        for (int i = 0; i < 4; ++i)
            ldsm_x4(A[i], sw_addr(pA, wm + i * 16 + arow, kb + akb));
        #pragma unroll
        for (int jp = 0; jp < 2; ++jp) {
            u32 r[4];
            ldsm_x4(r, sw_addr(pB, wn + jp * 16 + brow, kb + bkb));
            B[jp*2][0] = r[0]; B[jp*2][1] = r[1];
            B[jp*2+1][0] = r[2]; B[jp*2+1][1] = r[3];
        }
        #pragma unroll
        for (int i = 0; i < 4; ++i)
            #pragma unroll
            for (int j = 0; j < 4; ++j) mma16816(acc[i][j], A[i], B[j]);
    }
}

#define GEMM_MAINLOOP(gA, gB, acc)                                              \
    do {                                                                        \
        gemm_issue_stage(sb, 0, 0, gA, gB);                                     \
        gemm_issue_stage(sb, 1, 1, gA, gB);                                     \
        gemm_issue_stage(sb, 2, 2, gA, gB);                                     \
        for (int c = 0; c < 32; ++c) {                                          \
            CP_WAIT2();                                                         \
            __syncthreads();                                                    \
            gemm_compute_stage(sb, c & 3, acc, wm, wn, lane);                   \
            if (c + 3 < 32) gemm_issue_stage(sb, (c + 3) & 3, c + 3, gA, gB);   \
            else CP_COMMIT();                                                   \
        }                                                                       \
    } while (0)

// ---------------------------------------------------------------------------
// QKV GEMM: grid (24 ntiles, 512 pixel-groups). out fp32 q/k/v [pixel][ch]+bias
// ---------------------------------------------------------------------------
__global__ void __launch_bounds__(256) qkv_gemm_kernel(
    const float* __restrict__ bq, const float* __restrict__ bk,
    const float* __restrict__ bv)
{
    extern __shared__ char smc[];
    const u32 sb = smem_u32(smc);
    const int t = threadIdx.x, wid = t >> 5, lane = t & 31;
    const int grp = lane >> 2, tig = lane & 3;
    const int wm = (wid & 1) << 6, wn = (wid >> 1) << 5;
    const int nt = blockIdx.x, mg = blockIdx.y;

    const char* gA = (const char*)g_xf16 + (size_t)mg * 128 * 2048;
    const char* gB = (const char*)g_wf16 + (size_t)nt * 128 * 2048;

    float acc[4][4][4];
    #pragma unroll
    for (int i = 0; i < 4; ++i)
        #pragma unroll
        for (int j = 0; j < 4; ++j) { acc[i][j][0]=0.f; acc[i][j][1]=0.f; acc[i][j][2]=0.f; acc[i][j][3]=0.f; }

    GEMM_MAINLOOP(gA, gB, acc);

    const int sel = nt >> 3;
    const int cbase = (nt & 7) * 128;
    const float* bias = (sel == 0) ? bq : (sel == 1) ? bk : bv;
    float* out = g_qkv + (size_t)sel * QKVSZ;
    #pragma unroll
    for (int i = 0; i < 4; ++i) {
        int prow = mg * 128 + wm + i * 16 + grp;
        #pragma unroll
        for (int j = 0; j < 4; ++j) {
            int col = cbase + wn + j * 8 + tig * 2;
            float b0 = bias[col], b1 = bias[col + 1];
            float* o = out + (size_t)prow * 1024 + col;
            *(float2*)o = make_float2(acc[i][j][0] + b0, acc[i][j][1] + b1);
            *(float2*)(o + 8 * 1024) = make_float2(acc[i][j][2] + b0, acc[i][j][3] + b1);
        }
    }
}

// ---------------------------------------------------------------------------
// Proj GEMM: grid (8 ntiles, 512 pixel-groups). A = attn out fp16.
// Epilogue: smem transpose -> g_proj [b][c][n] + bias.
// ---------------------------------------------------------------------------
__global__ void __launch_bounds__(256) proj_gemm_kernel(const float* __restrict__ bp)
{
    extern __shared__ char smc[];
    const u32 sb = smem_u32(smc);
    const int t = threadIdx.x, wid = t >> 5, lane = t & 31;
    const int grp = lane >> 2, tig = lane & 3;
    const int wm = (wid & 1) << 6, wn = (wid >> 1) << 5;
    const int nt = blockIdx.x, mg = blockIdx.y;

    const char* gA = (const char*)g_of16 + (size_t)mg * 128 * 2048;
    const char* gB = (const char*)g_wf16 + (size_t)(3072 + nt * 128) * 2048;

    float acc[4][4][4];
    #pragma unroll
    for (int i = 0; i < 4; ++i)
        #pragma unroll
        for (int j = 0; j < 4; ++j) { acc[i][j][0]=0.f; acc[i][j][1]=0.f; acc[i][j][2]=0.f; acc[i][j][3]=0.f; }

    GEMM_MAINLOOP(gA, gB, acc);

    __syncthreads();   // all warps done with stage buffers before tile reuse
    // stash C tile [pm][cc] in smem (128*130*4 = 66.6KB > 64KB? NO: 66560 bytes > 65536!)
    // use stride 129 instead: 128*129*4 = 66048 > 65536 too. Use u16-safe plan:
    // stride 128 + separate pad region not needed — write through registers in
    // two half-tiles of 64 rows: 64*130*4 = 33280 bytes, well within 64KB.
    float* tile = (float*)smc;
    #pragma unroll
    for (int half = 0; half < 2; ++half) {
        // rows [half*64, half*64+64): warps with wm matching contribute
        if ((wm >> 6) == half) {
            #pragma unroll
            for (int i = 0; i < 4; ++i) {
                int pm = i * 16 + grp;   // 0..63 local
                #pragma unroll
                for (int j = 0; j < 4; ++j) {
                    int cc = wn + j * 8 + tig * 2;
                    *(float2*)&tile[pm * 130 + cc] = make_float2(acc[i][j][0], acc[i][j][1]);
                    *(float2*)&tile[(pm + 8) * 130 + cc] = make_float2(acc[i][j][2], acc[i][j][3]);
                }
            }
        }
        __syncthreads();
        // write 64 pixel-rows (= 1 batch) x 128 ch, transposed to [ch][n]
        int b = mg * 2 + half;
        #pragma unroll
        for (int it = 0; it < 8; ++it) {
            int idx = it * 256 + t;          // 2048 float4 groups: 128ch x 16 n4
            int cc = idx >> 4, n4 = (idx & 15) << 2;
            int ch = nt * 128 + cc;
            float bi = bp[ch];
            float4 v;
            v.x = tile[(n4 + 0) * 130 + cc] + bi;
            v.y = tile[(n4 + 1) * 130 + cc] + bi;
            v.z = tile[(n4 + 2) * 130 + cc] + bi;
            v.w = tile[(n4 + 3) * 130 + cc] + bi;
            *(float4*)(g_proj + (size_t)b * 65536 + (size_t)ch * 64 + n4) = v;
        }
        __syncthreads();
    }
}

// ---------------------------------------------------------------------------
// Attention: per (b, head). Reads g_qkv fp32 [pixel][ch]; writes fp16 out.
// ---------------------------------------------------------------------------
__global__ void __launch_bounds__(256) attn_kernel(const float* __restrict__ temp_p)
{
    extern __shared__ float sm[];
    float* qs  = sm;                 // [d][n]
    float* ks  = sm + 64 * PAD;
    float* vsT = sm + 2 * 64 * PAD;  // [n][d]
    float* At  = sm + 3 * 64 * PAD;  // [m][n]
    float* cd  = sm + 4 * 64 * PAD;
    float* knv = cd + 64;

    const int t  = threadIdx.x;
    const int tx = t & 15, ty = t >> 4;
    const int b  = blockIdx.x >> 4;
    const int h  = blockIdx.x & 15;

    const size_t base = (size_t)b * 65536 + h * 64;
    const float* qg = g_qkv + base;
    const float* kg = g_qkv + QKVSZ + base;
    const float* vg = g_qkv + 2 * QKVSZ + base;

    #pragma unroll
    for (int i = 0; i < 4; ++i) {
        int idx = i * 256 + t;
        int n = idx >> 4, d4 = (idx & 15) << 2;
        size_t off = (size_t)n * 1024 + d4;
        float4 qv = *(const float4*)(qg + off);
        qs[(d4 + 0) * PAD + n] = qv.x; qs[(d4 + 1) * PAD + n] = qv.y;
        qs[(d4 + 2) * PAD + n] = qv.z; qs[(d4 + 3) * PAD + n] = qv.w;
        float4 kv = *(const float4*)(kg + off);
        ks[(d4 + 0) * PAD + n] = kv.x; ks[(d4 + 1) * PAD + n] = kv.y;
        ks[(d4 + 2) * PAD + n] = kv.z; ks[(d4 + 3) * PAD + n] = kv.w;
        float4 vv = *(const float4*)(vg + off);
        *(float4*)(vsT + n * PAD + d4) = vv;
    }
    __syncthreads();

    float tinv = 1.0f / (temp_p[0] + 1e-6f);
    if (t < 64) {
        float s = 0.f;
        #pragma unroll 8
        for (int n = 0; n < 64; ++n) { float v = qs[t * PAD + n]; s += v * v; }
        cd[t] = 1.0f / fmaxf(sqrtf(s), 1e-12f);
    } else if (t < 128) {
        int r = t - 64;
        float s = 0.f;
        #pragma unroll 8
        for (int n = 0; n < 64; ++n) { float v = ks[r * PAD + n]; s += v * v; }
        knv[r] = 1.0f / fmaxf(sqrtf(s), 1e-12f);
    }
    __syncthreads();
    for (int i = t; i < 64 * 64; i += 256) {
        int d = i >> 6, n = i & 63;
        qs[d * PAD + n] *= cd[d] * knv[d] * tinv;
    }
    __syncthreads();

    u64t sa[4][2];
    #pragma unroll
    for (int i = 0; i < 4; ++i) { sa[i][0] = 0ull; sa[i][1] = 0ull; }
    #pragma unroll 4
    for (int d = 0; d < 64; ++d) {
        float4 av = *(const float4*)(qs + d * PAD + (ty << 2));
        ulonglong2 bv2 = *(const ulonglong2*)(ks + d * PAD + (tx << 2));
        u64t a0 = pk2(av.x, av.x), a1 = pk2(av.y, av.y);
        u64t a2 = pk2(av.z, av.z), a3 = pk2(av.w, av.w);
        sa[0][0] = ffma2(a0, bv2.x, sa[0][0]); sa[0][1] = ffma2(a0, bv2.y, sa[0][1]);
        sa[1][0] = ffma2(a1, bv2.x, sa[1][0]); sa[1][1] = ffma2(a1, bv2.y, sa[1][1]);
        sa[2][0] = ffma2(a2, bv2.x, sa[2][0]); sa[2][1] = ffma2(a2, bv2.y, sa[2][1]);
        sa[3][0] = ffma2(a3, bv2.x, sa[3][0]); sa[3][1] = ffma2(a3, bv2.y, sa[3][1]);
    }

    #pragma unroll
    for (int i = 0; i < 4; ++i) {
        float2 s01 = upk2(sa[i][0]);
        float2 s23 = upk2(sa[i][1]);
        float s0 = s01.x, s1 = s01.y, s2 = s23.x, s3 = s23.y;
        float mx = fmaxf(fmaxf(s0, s1), fmaxf(s2, s3));
        #pragma unroll
        for (int o = 8; o; o >>= 1) mx = fmaxf(mx, __shfl_xor_sync(0xffffffffu, mx, o));
        float e0 = __expf(s0 - mx), e1 = __expf(s1 - mx);
        float e2 = __expf(s2 - mx), e3 = __expf(s3 - mx);
        float sum = e0 + e1 + e2 + e3;
        #pragma unroll
        for (int o = 8; o; o >>= 1) sum += __shfl_xor_sync(0xffffffffu, sum, o);
        float rinv = 1.0f / sum;
        int n = (ty << 2) + i, m0 = tx << 2;
        At[(m0 + 0) * PAD + n] = e0 * rinv;
        At[(m0 + 1) * PAD + n] = e1 * rinv;
        At[(m0 + 2) * PAD + n] = e2 * rinv;
        At[(m0 + 3) * PAD + n] = e3 * rinv;
    }
    __syncthreads();

    u64t oa[4][2];
    #pragma unroll
    for (int i = 0; i < 4; ++i) { oa[i][0] = 0ull; oa[i][1] = 0ull; }
    #pragma unroll 4
    for (int m = 0; m < 64; ++m) {
        float4 av = *(const float4*)(At + m * PAD + (ty << 2));
        ulonglong2 bv2 = *(const ulonglong2*)(vsT + m * PAD + (tx << 2));
        u64t a0 = pk2(av.x, av.x), a1 = pk2(av.y, av.y);
        u64t a2 = pk2(av.z, av.z), a3 = pk2(av.w, av.w);
        oa[0][0] = ffma2(a0, bv2.x, oa[0][0]); oa[0][1] = ffma2(a0, bv2.y, oa[0][1]);
        oa[1][0] = ffma2(a1, bv2.x, oa[1][0]); oa[1][1] = ffma2(a1, bv2.y, oa[1][1]);
        oa[2][0] = ffma2(a2, bv2.x, oa[2][0]); oa[2][1] = ffma2(a2, bv2.y, oa[2][1]);
        oa[3][0] = ffma2(a3, bv2.x, oa[3][0]); oa[3][1] = ffma2(a3, bv2.y, oa[3][1]);
    }
    #pragma unroll
    for (int i = 0; i < 4; ++i) {
        float2 v01 = upk2(oa[i][0]);
        float2 v23 = upk2(oa[i][1]);
        int n = (ty << 2) + i;
        size_t o = (size_t)(b * 64 + n) * 1024 + h * 64 + (tx << 2);
        ushort4 hh;
        hh.x = f16r(v01.x); hh.y = f16r(v01.y);
        hh.z = f16r(v23.x); hh.w = f16r(v23.y);
        *(ushort4*)(g_of16 + o) = hh;
    }
}

// ---------------------------------------------------------------------------
// Stats + final LN
// ---------------------------------------------------------------------------
__global__ void __launch_bounds__(256) stats_kernel(
    const float* __restrict__ x, const float* __restrict__ gamma_p)
{
    __shared__ float r1[8], r2[8];
    const int b = blockIdx.x, t = threadIdx.x;
    const float g = gamma_p[0], og = 1.0f - g;
    const float* pb = g_proj + (size_t)b * 65536;
    const float* xb = x + (size_t)b * 65536;
    float s1 = 0.f, s2 = 0.f;
    for (int i = t * 4; i < 65536; i += 1024) {
        float4 p  = *(const float4*)(pb + i);
        float4 xx = *(const float4*)(xb + i);
        float a;
        a = g * p.x + og * xx.x; s1 += a; s2 += a * a;
        a = g * p.y + og * xx.y; s1 += a; s2 += a * a;
        a = g * p.z + og * xx.z; s1 += a; s2 += a * a;
        a = g * p.w + og * xx.w; s1 += a; s2 += a * a;
    }
    #pragma unroll
    for (int o = 16; o; o >>= 1) {
        s1 += __shfl_xor_sync(0xffffffffu, s1, o);
        s2 += __shfl_xor_sync(0xffffffffu, s2, o);
    }
    if ((t & 31) == 0) { r1[t >> 5] = s1; r2[t >> 5] = s2; }
    __syncthreads();
    if (t < 8) {
        s1 = r1[t]; s2 = r2[t];
        #pragma unroll
        for (int o = 4; o; o >>= 1) {
            s1 += __shfl_xor_sync(0x000000ffu, s1, o);
            s2 += __shfl_xor_sync(0x000000ffu, s2, o);
        }
        if (t == 0) {
            float mu  = s1 * (1.0f / 65536.0f);
            float var = s2 * (1.0f / 65536.0f) - mu * mu;
            g_stats[2 * b]     = mu;
            g_stats[2 * b + 1] = rsqrtf(var + 1e-5f);
        }
    }
}

__global__ void __launch_bounds__(256) final_kernel(
    const float* __restrict__ x, const float* __restrict__ gamma_p,
    const float* __restrict__ lnw, const float* __restrict__ lnb,
    float* __restrict__ y)
{
    size_t i4 = (size_t)blockIdx.x * 256 + threadIdx.x;
    int b   = (int)(i4 >> 14);
    int rem = (int)(i4 & 16383);
    size_t base = ((size_t)b << 16) + ((size_t)rem << 2);
    float4 p  = *(const float4*)(g_proj + base);
    float4 xx = *(const float4*)(x + base);
    float4 w  = *(const float4*)(lnw + ((size_t)rem << 2));
    float4 lb = *(const float4*)(lnb + ((size_t)rem << 2));
    float g = gamma_p[0], og = 1.0f - g;
    float mu = g_stats[2 * b], rs = g_stats[2 * b + 1];
    float4 o;
    o.x = (g * p.x + og * xx.x - mu) * rs * w.x + lb.x;
    o.y = (g * p.y + og * xx.y - mu) * rs * w.y + lb.y;
    o.z = (g * p.z + og * xx.z - mu) * rs * w.z + lb.z;
    o.w = (g * p.w + og * xx.w - mu) * rs * w.w + lb.w;
    *(float4*)(y + base) = o;
}

// ---------------------------------------------------------------------------
extern "C" void kernel_launch(void* const* d_in, const int* in_sizes, int n_in,
                              void* d_out, int out_size)
{
    const float* x     = (const float*)d_in[0];
    const float* Wq    = (const float*)d_in[1];
    const float* bq    = (const float*)d_in[2];
    const float* Wk    = (const float*)d_in[3];
    const float* bk    = (const float*)d_in[4];
    const float* Wv    = (const float*)d_in[5];
    const float* bv    = (const float*)d_in[6];
    const float* Wp    = (const float*)d_in[7];
    const float* bp    = (const float*)d_in[8];
    const float* gamma = (const float*)d_in[9];
    const float* temp  = (const float*)d_in[10];
    const float* lnw   = (const float*)d_in[11];
    const float* lnb   = (const float*)d_in[12];
    float* y = (float*)d_out;

    const int sm_att = (4 * 64 * PAD + 128) * (int)sizeof(float);
    cudaFuncSetAttribute(qkv_gemm_kernel, cudaFuncAttributeMaxDynamicSharedMemorySize, SM_GEMM);
    cudaFuncSetAttribute(proj_gemm_kernel, cudaFuncAttributeMaxDynamicSharedMemorySize, SM_GEMM);
    cudaFuncSetAttribute(attn_kernel, cudaFuncAttributeMaxDynamicSharedMemorySize, sm_att);

    prep_w_kernel<<<4096, 256>>>(Wq, Wk, Wv, Wp);
    prep_x_kernel<<<BB, 256>>>(x);
    qkv_gemm_kernel<<<dim3(24, 512), 256, SM_GEMM>>>(bq, bk, bv);
    attn_kernel<<<BB * NH, 256, sm_att>>>(temp);
    proj_gemm_kernel<<<dim3(8, 512), 256, SM_GEMM>>>(bp);
    stats_kernel<<<BB, 256>>>(x, gamma);
    final_kernel<<<65536, 256>>>(x, gamma, lnw, lnb, y);
}

// round 8
// speedup vs baseline: 3.8584x; 1.2737x over previous
#include <cuda_runtime.h>
#include <cuda_fp16.h>

#define NH   16
#define NN   64
#define CC   1024
#define BB   1024

typedef unsigned int u32;
typedef unsigned long long u64;
typedef unsigned short u16;

#define QKVSZ 67108864ull          // 1024*64*1024 elems

// Scratch (allocation-free rule: device globals)
__device__ u16   g_xf16[(size_t)BB * NN * CC];    // x transposed, fp16 [pixel][ch]
__device__ u16   g_wf16[(size_t)4096 * CC];       // Wq,Wk,Wv,Wp fused rows, fp16 RN
__device__ u16   g_qkv16[3ull * QKVSZ];           // q,k,v fp16 [pixel][ch]
__device__ u16   g_of16[(size_t)BB * NN * CC];    // attn out fp16 [pixel][ch]
__device__ float g_proj[(size_t)BB * CC * NN];    // proj out [b][c][n]
__device__ float g_stats[2 * BB];

// ---------------------------------------------------------------------------
// helpers
// ---------------------------------------------------------------------------
__device__ __forceinline__ u32 smem_u32(const void* p) {
    u32 a;
    asm("{ .reg .u64 t; cvta.to.shared.u64 t, %1; cvt.u32.u64 %0, t; }" : "=r"(a) : "l"(p));
    return a;
}
__device__ __forceinline__ void cpa16(u32 dst, const void* src) {
    asm volatile("cp.async.cg.shared.global [%0], [%1], 16;" :: "r"(dst), "l"(src));
}
#define CP_COMMIT() asm volatile("cp.async.commit_group;" ::: "memory")
#define CP_WAIT2()  asm volatile("cp.async.wait_group 2;" ::: "memory")
#define CP_WAIT0()  asm volatile("cp.async.wait_group 0;" ::: "memory")

__device__ __forceinline__ void ldsm_x4(u32* r, u32 addr) {
    asm volatile("ldmatrix.sync.aligned.m8n8.x4.shared.b16 {%0,%1,%2,%3}, [%4];"
        : "=r"(r[0]), "=r"(r[1]), "=r"(r[2]), "=r"(r[3]) : "r"(addr));
}
__device__ __forceinline__ void ldsm_x4t(u32* r, u32 addr) {
    asm volatile("ldmatrix.sync.aligned.m8n8.x4.trans.shared.b16 {%0,%1,%2,%3}, [%4];"
        : "=r"(r[0]), "=r"(r[1]), "=r"(r[2]), "=r"(r[3]) : "r"(addr));
}
__device__ __forceinline__ void mma16816(float* c, const u32* a, const u32* b) {
    asm volatile("mma.sync.aligned.m16n8k16.row.col.f32.f16.f16.f32 "
        "{%0,%1,%2,%3}, {%4,%5,%6,%7}, {%8,%9}, {%0,%1,%2,%3};"
        : "+f"(c[0]), "+f"(c[1]), "+f"(c[2]), "+f"(c[3])
        : "r"(a[0]), "r"(a[1]), "r"(a[2]), "r"(a[3]), "r"(b[0]), "r"(b[1]));
}
// GEMM smem swizzle: rows of 64B (4 chunks), chunk ^= (row>>1)&3
__device__ __forceinline__ u32 sw_addr(u32 base, int row, int kbyte) {
    int chunk = kbyte >> 4, in = kbyte & 15;
    return base + row * 64 + ((chunk ^ ((row >> 1) & 3)) << 4) + in;
}
// attn smem swizzle: rows of 128B (8 chunks), chunk ^= row&7
__device__ __forceinline__ u32 sw128(u32 base, int row, int kbyte) {
    int chunk = kbyte >> 4, in = kbyte & 15;
    return base + row * 128 + ((chunk ^ (row & 7)) << 4) + in;
}
__device__ __forceinline__ u16 f16r(float f) {
    __half h = __float2half_rn(f);
    return *reinterpret_cast<u16*>(&h);
}
__device__ __forceinline__ u32 packh2(float lo, float hi) {
    u32 r;
    asm("cvt.rn.f16x2.f32 %0, %1, %2;" : "=r"(r) : "f"(hi), "f"(lo));
    return r;
}

// GEMM smem: 4 stages x 16KB (A 8K | B 8K per stage)
#define STAGE_BYTES 16384
#define SM_GEMM     (4 * STAGE_BYTES)

// ---------------------------------------------------------------------------
// prep_w: 4 weight matrices -> fused fp16 [4096][1024]
// ---------------------------------------------------------------------------
__global__ void __launch_bounds__(256) prep_w_kernel(
    const float* __restrict__ Wq, const float* __restrict__ Wk,
    const float* __restrict__ Wv, const float* __restrict__ Wp)
{
    int blk = blockIdx.x;
    int mat = blk >> 10;
    const float* src = (mat == 0) ? Wq : (mat == 1) ? Wk : (mat == 2) ? Wv : Wp;
    size_t idx = ((size_t)(blk & 1023) * 256 + threadIdx.x) * 4;
    float4 v = *(const float4*)(src + idx);
    size_t o = (size_t)mat * 1048576 + idx;
    ushort4 h;
    h.x = f16r(v.x); h.y = f16r(v.y); h.z = f16r(v.z); h.w = f16r(v.w);
    *(ushort4*)(g_wf16 + o) = h;
}

// ---------------------------------------------------------------------------
// prep_x: x[b][c][n] -> transposed fp16 [pixel=b*64+n][c]
// ---------------------------------------------------------------------------
__global__ void __launch_bounds__(256) prep_x_kernel(const float* __restrict__ x) {
    __shared__ u16 hT[64][72];
    const int b = blockIdx.x, t = threadIdx.x;
    const float* xb = x + (size_t)b * 65536;
    for (int ct = 0; ct < 16; ++ct) {
        #pragma unroll
        for (int i = 0; i < 16; ++i) {
            int idx = i * 256 + t, c = idx >> 6, n = idx & 63;
            hT[n][c] = f16r(xb[(ct * 64 + c) * 64 + n]);
        }
        __syncthreads();
        #pragma unroll
        for (int i = 0; i < 2; ++i) {
            int idx = i * 256 + t;
            int n = idx >> 3, c8 = (idx & 7) << 3;
            size_t o = (size_t)(b * 64 + n) * 1024 + ct * 64 + c8;
            *(uint4*)(g_xf16 + o) = *(const uint4*)&hT[n][c8];
        }
        __syncthreads();
    }
}

// ---------------------------------------------------------------------------
// GEMM core: C[128 pix][128 ch] = A x B^T over K=1024, fp16 single-pass.
// ---------------------------------------------------------------------------
__device__ __forceinline__ void gemm_issue_stage(
    u32 sb, int s, int c, const char* gA, const char* gB)
{
    const int t = threadIdx.x;
    const char* gsrc[2] = {gA, gB};
    u32 stb = sb + s * STAGE_BYTES;
    #pragma unroll
    for (int arr = 0; arr < 2; ++arr) {
        #pragma unroll
        for (int r2 = 0; r2 < 2; ++r2) {
            int ch = t + r2 * 256;
            int row = ch >> 2, part = ch & 3;
            u32 dst = stb + arr * 8192 + row * 64 + ((part ^ ((row >> 1) & 3)) << 4);
            const char* src = gsrc[arr] + (size_t)row * 2048 + c * 64 + part * 16;
            cpa16(dst, src);
        }
    }
    CP_COMMIT();
}

__device__ __forceinline__ void gemm_compute_stage(u32 sb, int s, float acc[4][4][4],
                                                   int wm, int wn, int lane)
{
    u32 stb = sb + s * STAGE_BYTES;
    u32 pA = stb, pB = stb + 8192;
    const int arow = lane & 15;
    const int akb  = (lane >> 4) << 4;
    const int brow = (lane & 7) + ((lane & 16) >> 1);
    const int bkb  = (lane & 8) << 1;
    #pragma unroll
    for (int ks = 0; ks < 2; ++ks) {
        int kb = ks * 32;
        u32 A[4][4], B[4][2];
        #pragma unroll
        for (int i = 0; i < 4; ++i)
            ldsm_x4(A[i], sw_addr(pA, wm + i * 16 + arow, kb + akb));
        #pragma unroll
        for (int jp = 0; jp < 2; ++jp) {
            u32 r[4];
            ldsm_x4(r, sw_addr(pB, wn + jp * 16 + brow, kb + bkb));
            B[jp*2][0] = r[0]; B[jp*2][1] = r[1];
            B[jp*2+1][0] = r[2]; B[jp*2+1][1] = r[3];
        }
        #pragma unroll
        for (int i = 0; i < 4; ++i)
            #pragma unroll
            for (int j = 0; j < 4; ++j) mma16816(acc[i][j], A[i], B[j]);
    }
}

#define GEMM_MAINLOOP(gA, gB, acc)                                              \
    do {                                                                        \
        gemm_issue_stage(sb, 0, 0, gA, gB);                                     \
        gemm_issue_stage(sb, 1, 1, gA, gB);                                     \
        gemm_issue_stage(sb, 2, 2, gA, gB);                                     \
        for (int c = 0; c < 32; ++c) {                                          \
            CP_WAIT2();                                                         \
            __syncthreads();                                                    \
            gemm_compute_stage(sb, c & 3, acc, wm, wn, lane);                   \
            if (c + 3 < 32) gemm_issue_stage(sb, (c + 3) & 3, c + 3, gA, gB);   \
            else CP_COMMIT();                                                   \
        }                                                                       \
    } while (0)

// ---------------------------------------------------------------------------
// QKV GEMM: grid (24 ntiles, 512 pixel-groups). out fp16 q/k/v [pixel][ch]+bias
// ---------------------------------------------------------------------------
__global__ void __launch_bounds__(256) qkv_gemm_kernel(
    const float* __restrict__ bq, const float* __restrict__ bk,
    const float* __restrict__ bv)
{
    extern __shared__ char smc[];
    const u32 sb = smem_u32(smc);
    const int t = threadIdx.x, wid = t >> 5, lane = t & 31;
    const int grp = lane >> 2, tig = lane & 3;
    const int wm = (wid & 1) << 6, wn = (wid >> 1) << 5;
    const int nt = blockIdx.x, mg = blockIdx.y;

    const char* gA = (const char*)g_xf16 + (size_t)mg * 128 * 2048;
    const char* gB = (const char*)g_wf16 + (size_t)nt * 128 * 2048;

    float acc[4][4][4];
    #pragma unroll
    for (int i = 0; i < 4; ++i)
        #pragma unroll
        for (int j = 0; j < 4; ++j) { acc[i][j][0]=0.f; acc[i][j][1]=0.f; acc[i][j][2]=0.f; acc[i][j][3]=0.f; }

    GEMM_MAINLOOP(gA, gB, acc);

    const int sel = nt >> 3;
    const int cbase = (nt & 7) * 128;
    const float* bias = (sel == 0) ? bq : (sel == 1) ? bk : bv;
    u16* out = g_qkv16 + (size_t)sel * QKVSZ;
    #pragma unroll
    for (int i = 0; i < 4; ++i) {
        int prow = mg * 128 + wm + i * 16 + grp;
        #pragma unroll
        for (int j = 0; j < 4; ++j) {
            int col = cbase + wn + j * 8 + tig * 2;
            float b0 = bias[col], b1 = bias[col + 1];
            *(u32*)(out + (size_t)prow * 1024 + col) = packh2(acc[i][j][0] + b0, acc[i][j][1] + b1);
            *(u32*)(out + (size_t)(prow + 8) * 1024 + col) = packh2(acc[i][j][2] + b0, acc[i][j][3] + b1);
        }
    }
}

// ---------------------------------------------------------------------------
// Proj GEMM: grid (8 ntiles, 512 pixel-groups). A = attn out fp16.
// Epilogue: smem transpose -> g_proj [b][c][n] + bias.
// ---------------------------------------------------------------------------
__global__ void __launch_bounds__(256) proj_gemm_kernel(const float* __restrict__ bp)
{
    extern __shared__ char smc[];
    const u32 sb = smem_u32(smc);
    const int t = threadIdx.x, wid = t >> 5, lane = t & 31;
    const int grp = lane >> 2, tig = lane & 3;
    const int wm = (wid & 1) << 6, wn = (wid >> 1) << 5;
    const int nt = blockIdx.x, mg = blockIdx.y;

    const char* gA = (const char*)g_of16 + (size_t)mg * 128 * 2048;
    const char* gB = (const char*)g_wf16 + (size_t)(3072 + nt * 128) * 2048;

    float acc[4][4][4];
    #pragma unroll
    for (int i = 0; i < 4; ++i)
        #pragma unroll
        for (int j = 0; j < 4; ++j) { acc[i][j][0]=0.f; acc[i][j][1]=0.f; acc[i][j][2]=0.f; acc[i][j][3]=0.f; }

    GEMM_MAINLOOP(gA, gB, acc);

    __syncthreads();
    float* tile = (float*)smc;
    #pragma unroll
    for (int half = 0; half < 2; ++half) {
        if ((wm >> 6) == half) {
            #pragma unroll
            for (int i = 0; i < 4; ++i) {
                int pm = i * 16 + grp;
                #pragma unroll
                for (int j = 0; j < 4; ++j) {
                    int cc = wn + j * 8 + tig * 2;
                    *(float2*)&tile[pm * 130 + cc] = make_float2(acc[i][j][0], acc[i][j][1]);
                    *(float2*)&tile[(pm + 8) * 130 + cc] = make_float2(acc[i][j][2], acc[i][j][3]);
                }
            }
        }
        __syncthreads();
        int b = mg * 2 + half;
        #pragma unroll
        for (int it = 0; it < 8; ++it) {
            int idx = it * 256 + t;
            int cc = idx >> 4, n4 = (idx & 15) << 2;
            int ch = nt * 128 + cc;
            float bi = bp[ch];
            float4 v;
            v.x = tile[(n4 + 0) * 130 + cc] + bi;
            v.y = tile[(n4 + 1) * 130 + cc] + bi;
            v.z = tile[(n4 + 2) * 130 + cc] + bi;
            v.w = tile[(n4 + 3) * 130 + cc] + bi;
            *(float4*)(g_proj + (size_t)b * 65536 + (size_t)ch * 64 + n4) = v;
        }
        __syncthreads();
    }
}

// ---------------------------------------------------------------------------
// Attention (tensor-core): one CTA per (b,h), 128 threads / 4 warps.
// S = (q*s)^T k via mma, softmax in registers, O = P V via mma (P repacked
// in registers, V loaded with ldmatrix.trans). Output fp16 [pixel][ch].
// ---------------------------------------------------------------------------
__global__ void __launch_bounds__(128) attn_kernel(const float* __restrict__ temp_p)
{
    __shared__ __align__(128) u16 qs[4096];   // [n][d] fp16, sw128
    __shared__ __align__(128) u16 kk[4096];   // [m][d]
    __shared__ __align__(128) u16 vv[4096];   // [m][d]
    __shared__ float scq[64], sck[64];

    const int t = threadIdx.x, lane = t & 31, wid = t >> 5;
    const int b = blockIdx.x >> 4, h = blockIdx.x & 15;
    const u32 q0 = smem_u32(qs), k0 = smem_u32(kk), v0 = smem_u32(vv);

    // ---- load q/k/v tiles (64 x 64 fp16 each) via cp.async ----
    {
        u32 bases[3] = {q0, k0, v0};
        #pragma unroll
        for (int i = 0; i < 12; ++i) {
            int idx = t + i * 128;           // 0..1535
            int arr = idx >> 9, rem = idx & 511;
            int row = rem >> 3, ch = rem & 7;
            u32 dst = bases[arr] + row * 128 + ((ch ^ (row & 7)) << 4);
            const char* src = (const char*)(g_qkv16 + (size_t)arr * QKVSZ)
                            + ((size_t)(b * 64 + row) * 1024 + h * 64) * 2 + ch * 16;
            cpa16(dst, src);
        }
        CP_COMMIT();
        CP_WAIT0();
        __syncthreads();
    }

    // ---- per-d column norms over the spatial axis (fp32) ----
    {
        float tinv = 1.0f / (temp_p[0] + 1e-6f);
        int d = t & 63;
        const __half* base = (const __half*)((t < 64) ? qs : kk);
        int cb = d >> 3, io = (d * 2) & 15;
        float s = 0.f;
        #pragma unroll 8
        for (int n = 0; n < 64; ++n) {
            int bi = (n * 128 + ((cb ^ (n & 7)) << 4) + io) >> 1;
            float v = __half2float(base[bi]);
            s += v * v;
        }
        float inv = 1.0f / fmaxf(sqrtf(s), 1e-12f);
        if (t < 64) scq[d] = inv; else sck[d] = inv;
        __syncthreads();
        if (t < 64) scq[d] = scq[d] * sck[d] * tinv;
        __syncthreads();
    }

    // ---- fold combined scale into q (fp16, in place) ----
    {
        u32* qw = (u32*)qs;
        #pragma unroll
        for (int i = 0; i < 16; ++i) {
            int idx = t + i * 128;
            int row = idx >> 5, pos = idx & 31;
            int ui = (row * 128 + (((pos >> 2) ^ (row & 7)) << 4) + (pos & 3) * 4) >> 2;
            float2 f = __half22float2(*(__half2*)&qw[ui]);
            f.x *= scq[pos * 2];
            f.y *= scq[pos * 2 + 1];
            qw[ui] = packh2(f.x, f.y);
        }
        __syncthreads();
    }

    // ---- S = qhat^T khat : warp rows wm..wm+15, cols 0..63 ----
    const int wm = wid << 4;
    float sa[8][4];
    #pragma unroll
    for (int j = 0; j < 8; ++j) { sa[j][0]=0.f; sa[j][1]=0.f; sa[j][2]=0.f; sa[j][3]=0.f; }
    {
        const int arow = lane & 15, akb = (lane >> 4) << 4;
        const int br = (lane & 7) + ((lane & 16) >> 1), bkb = (lane & 8) << 1;
        #pragma unroll
        for (int ks = 0; ks < 4; ++ks) {
            int kb = ks * 32;
            u32 A[4];
            ldsm_x4(A, sw128(q0, wm + arow, kb + akb));
            #pragma unroll
            for (int jp = 0; jp < 4; ++jp) {
                u32 r[4];
                ldsm_x4(r, sw128(k0, jp * 16 + br, kb + bkb));
                mma16816(sa[jp * 2], A, r);
                mma16816(sa[jp * 2 + 1], A, r + 2);
            }
        }
    }

    // ---- softmax over m (rows r=grp and r+8 of this warp's tile) ----
    u32 pa[4][4];
    {
        float mx0 = -1e30f, mx1 = -1e30f;
        #pragma unroll
        for (int j = 0; j < 8; ++j) {
            mx0 = fmaxf(mx0, fmaxf(sa[j][0], sa[j][1]));
            mx1 = fmaxf(mx1, fmaxf(sa[j][2], sa[j][3]));
        }
        #pragma unroll
        for (int o = 1; o <= 2; o <<= 1) {
            mx0 = fmaxf(mx0, __shfl_xor_sync(0xffffffffu, mx0, o));
            mx1 = fmaxf(mx1, __shfl_xor_sync(0xffffffffu, mx1, o));
        }
        float sum0 = 0.f, sum1 = 0.f;
        #pragma unroll
        for (int j = 0; j < 8; ++j) {
            sa[j][0] = __expf(sa[j][0] - mx0); sum0 += sa[j][0];
            sa[j][1] = __expf(sa[j][1] - mx0); sum0 += sa[j][1];
            sa[j][2] = __expf(sa[j][2] - mx1); sum1 += sa[j][2];
            sa[j][3] = __expf(sa[j][3] - mx1); sum1 += sa[j][3];
        }
        #pragma unroll
        for (int o = 1; o <= 2; o <<= 1) {
            sum0 += __shfl_xor_sync(0xffffffffu, sum0, o);
            sum1 += __shfl_xor_sync(0xffffffffu, sum1, o);
        }
        float r0 = 1.0f / sum0, r1 = 1.0f / sum1;
        // repack P into A-fragments for the AV mma (k = m)
        #pragma unroll
        for (int ks = 0; ks < 4; ++ks) {
            pa[ks][0] = packh2(sa[2*ks][0] * r0, sa[2*ks][1] * r0);
            pa[ks][1] = packh2(sa[2*ks][2] * r1, sa[2*ks][3] * r1);
            pa[ks][2] = packh2(sa[2*ks+1][0] * r0, sa[2*ks+1][1] * r0);
            pa[ks][3] = packh2(sa[2*ks+1][2] * r1, sa[2*ks+1][3] * r1);
        }
    }

    // ---- O = P V : ldmatrix.trans on v ([m][d] -> [d][m] fragments) ----
    float oa[8][4];
    #pragma unroll
    for (int j = 0; j < 8; ++j) { oa[j][0]=0.f; oa[j][1]=0.f; oa[j][2]=0.f; oa[j][3]=0.f; }
    {
        const int vrow = lane & 15, vdb = (lane >> 4) << 4;
        #pragma unroll
        for (int ks = 0; ks < 4; ++ks) {
            #pragma unroll
            for (int Dp = 0; Dp < 4; ++Dp) {
                u32 r[4];
                ldsm_x4t(r, sw128(v0, ks * 16 + vrow, Dp * 32 + vdb));
                mma16816(oa[Dp * 2], pa[ks], r);
                mma16816(oa[Dp * 2 + 1], pa[ks], r + 2);
            }
        }
    }
    __syncthreads();   // all warps past the S phase before bounce reuses qs/kk

    // ---- bounce O through smem (pad-33 u32 rows), then coalesced writes ----
    {
        u32* bn = (u32*)qs;                     // 64*33*4 = 8448B (spills into kk)
        int grp = lane >> 2, tg = lane & 3;
        #pragma unroll
        for (int jd = 0; jd < 8; ++jd) {
            int c = jd * 4 + tg;
            bn[(wm + grp) * 33 + c]     = packh2(oa[jd][0], oa[jd][1]);
            bn[(wm + grp + 8) * 33 + c] = packh2(oa[jd][2], oa[jd][3]);
        }
        __syncthreads();
        u16* outg = g_of16 + (size_t)(b * 64) * 1024 + h * 64;
        #pragma unroll
        for (int i = 0; i < 16; ++i) {
            int idx = t + i * 128;
            int row = idx >> 5, c = idx & 31;
            *(u32*)(outg + (size_t)row * 1024 + c * 2) = bn[row * 33 + c];
        }
    }
}

// ---------------------------------------------------------------------------
// Stats + final LN
// ---------------------------------------------------------------------------
__global__ void __launch_bounds__(256) stats_kernel(
    const float* __restrict__ x, const float* __restrict__ gamma_p)
{
    __shared__ float r1[8], r2[8];
    const int b = blockIdx.x, t = threadIdx.x;
    const float g = gamma_p[0], og = 1.0f - g;
    const float* pb = g_proj + (size_t)b * 65536;
    const float* xb = x + (size_t)b * 65536;
    float s1 = 0.f, s2 = 0.f;
    for (int i = t * 4; i < 65536; i += 1024) {
        float4 p  = *(const float4*)(pb + i);
        float4 xx = *(const float4*)(xb + i);
        float a;
        a = g * p.x + og * xx.x; s1 += a; s2 += a * a;
        a = g * p.y + og * xx.y; s1 += a; s2 += a * a;
        a = g * p.z + og * xx.z; s1 += a; s2 += a * a;
        a = g * p.w + og * xx.w; s1 += a; s2 += a * a;
    }
    #pragma unroll
    for (int o = 16; o; o >>= 1) {
        s1 += __shfl_xor_sync(0xffffffffu, s1, o);
        s2 += __shfl_xor_sync(0xffffffffu, s2, o);
    }
    if ((t & 31) == 0) { r1[t >> 5] = s1; r2[t >> 5] = s2; }
    __syncthreads();
    if (t < 8) {
        s1 = r1[t]; s2 = r2[t];
        #pragma unroll
        for (int o = 4; o; o >>= 1) {
            s1 += __shfl_xor_sync(0x000000ffu, s1, o);
            s2 += __shfl_xor_sync(0x000000ffu, s2, o);
        }
        if (t == 0) {
            float mu  = s1 * (1.0f / 65536.0f);
            float var = s2 * (1.0f / 65536.0f) - mu * mu;
            g_stats[2 * b]     = mu;
            g_stats[2 * b + 1] = rsqrtf(var + 1e-5f);
        }
    }
}

__global__ void __launch_bounds__(256) final_kernel(
    const float* __restrict__ x, const float* __restrict__ gamma_p,
    const float* __restrict__ lnw, const float* __restrict__ lnb,
    float* __restrict__ y)
{
    size_t i4 = (size_t)blockIdx.x * 256 + threadIdx.x;
    int b   = (int)(i4 >> 14);
    int rem = (int)(i4 & 16383);
    size_t base = ((size_t)b << 16) + ((size_t)rem << 2);
    float4 p  = *(const float4*)(g_proj + base);
    float4 xx = *(const float4*)(x + base);
    float4 w  = *(const float4*)(lnw + ((size_t)rem << 2));
    float4 lb = *(const float4*)(lnb + ((size_t)rem << 2));
    float g = gamma_p[0], og = 1.0f - g;
    float mu = g_stats[2 * b], rs = g_stats[2 * b + 1];
    float4 o;
    o.x = (g * p.x + og * xx.x - mu) * rs * w.x + lb.x;
    o.y = (g * p.y + og * xx.y - mu) * rs * w.y + lb.y;
    o.z = (g * p.z + og * xx.z - mu) * rs * w.z + lb.z;
    o.w = (g * p.w + og * xx.w - mu) * rs * w.w + lb.w;
    *(float4*)(y + base) = o;
}

// ---------------------------------------------------------------------------
extern "C" void kernel_launch(void* const* d_in, const int* in_sizes, int n_in,
                              void* d_out, int out_size)
{
    const float* x     = (const float*)d_in[0];
    const float* Wq    = (const float*)d_in[1];
    const float* bq    = (const float*)d_in[2];
    const float* Wk    = (const float*)d_in[3];
    const float* bk    = (const float*)d_in[4];
    const float* Wv    = (const float*)d_in[5];
    const float* bv    = (const float*)d_in[6];
    const float* Wp    = (const float*)d_in[7];
    const float* bp    = (const float*)d_in[8];
    const float* gamma = (const float*)d_in[9];
    const float* temp  = (const float*)d_in[10];
    const float* lnw   = (const float*)d_in[11];
    const float* lnb   = (const float*)d_in[12];
    float* y = (float*)d_out;

    cudaFuncSetAttribute(qkv_gemm_kernel, cudaFuncAttributeMaxDynamicSharedMemorySize, SM_GEMM);
    cudaFuncSetAttribute(proj_gemm_kernel, cudaFuncAttributeMaxDynamicSharedMemorySize, SM_GEMM);

    prep_w_kernel<<<4096, 256>>>(Wq, Wk, Wv, Wp);
    prep_x_kernel<<<BB, 256>>>(x);
    qkv_gemm_kernel<<<dim3(24, 512), 256, SM_GEMM>>>(bq, bk, bv);
    attn_kernel<<<BB * NH, 128>>>(temp);
    proj_gemm_kernel<<<dim3(8, 512), 256, SM_GEMM>>>(bp);
    stats_kernel<<<BB, 256>>>(x, gamma);
    final_kernel<<<65536, 256>>>(x, gamma, lnw, lnb, y);
}

// round 9
// speedup vs baseline: 4.0007x; 1.0369x over previous
#include <cuda_runtime.h>
#include <cuda_fp16.h>

#define NH   16
#define NN   64
#define CC   1024
#define BB   1024

typedef unsigned int u32;
typedef unsigned long long u64;
typedef unsigned short u16;

#define QKVSZ 67108864ull          // 1024*64*1024 elems

// Scratch (allocation-free rule: device globals)
__device__ u16   g_xf16[(size_t)BB * NN * CC];    // x transposed, fp16 [pixel][ch]
__device__ u16   g_wf16[(size_t)4096 * CC];       // Wq,Wk,Wv,Wp fused rows, fp16 RN
__device__ u16   g_qkv16[3ull * QKVSZ];           // q,k,v fp16 [pixel][ch]
__device__ u16   g_of16[(size_t)BB * NN * CC];    // attn out fp16 [pixel][ch]
__device__ float g_res [(size_t)BB * CC * NN];    // residual r [b][c][n]
__device__ float g_stats[2 * BB];

// ---------------------------------------------------------------------------
// helpers
// ---------------------------------------------------------------------------
__device__ __forceinline__ u32 smem_u32(const void* p) {
    u32 a;
    asm("{ .reg .u64 t; cvta.to.shared.u64 t, %1; cvt.u32.u64 %0, t; }" : "=r"(a) : "l"(p));
    return a;
}
__device__ __forceinline__ void cpa16(u32 dst, const void* src) {
    asm volatile("cp.async.cg.shared.global [%0], [%1], 16;" :: "r"(dst), "l"(src));
}
#define CP_COMMIT() asm volatile("cp.async.commit_group;" ::: "memory")
#define CP_WAIT2()  asm volatile("cp.async.wait_group 2;" ::: "memory")
#define CP_WAIT0()  asm volatile("cp.async.wait_group 0;" ::: "memory")

__device__ __forceinline__ void ldsm_x4(u32* r, u32 addr) {
    asm volatile("ldmatrix.sync.aligned.m8n8.x4.shared.b16 {%0,%1,%2,%3}, [%4];"
        : "=r"(r[0]), "=r"(r[1]), "=r"(r[2]), "=r"(r[3]) : "r"(addr));
}
__device__ __forceinline__ void ldsm_x4t(u32* r, u32 addr) {
    asm volatile("ldmatrix.sync.aligned.m8n8.x4.trans.shared.b16 {%0,%1,%2,%3}, [%4];"
        : "=r"(r[0]), "=r"(r[1]), "=r"(r[2]), "=r"(r[3]) : "r"(addr));
}
__device__ __forceinline__ void mma16816(float* c, const u32* a, const u32* b) {
    asm volatile("mma.sync.aligned.m16n8k16.row.col.f32.f16.f16.f32 "
        "{%0,%1,%2,%3}, {%4,%5,%6,%7}, {%8,%9}, {%0,%1,%2,%3};"
        : "+f"(c[0]), "+f"(c[1]), "+f"(c[2]), "+f"(c[3])
        : "r"(a[0]), "r"(a[1]), "r"(a[2]), "r"(a[3]), "r"(b[0]), "r"(b[1]));
}
// GEMM smem swizzle: rows of 64B (4 chunks), chunk ^= (row>>1)&3
__device__ __forceinline__ u32 sw_addr(u32 base, int row, int kbyte) {
    int chunk = kbyte >> 4, in = kbyte & 15;
    return base + row * 64 + ((chunk ^ ((row >> 1) & 3)) << 4) + in;
}
// attn smem swizzle: rows of 128B (8 chunks), chunk ^= row&7
__device__ __forceinline__ u32 sw128(u32 base, int row, int kbyte) {
    int chunk = kbyte >> 4, in = kbyte & 15;
    return base + row * 128 + ((chunk ^ (row & 7)) << 4) + in;
}
__device__ __forceinline__ u16 f16r(float f) {
    __half h = __float2half_rn(f);
    return *reinterpret_cast<u16*>(&h);
}
__device__ __forceinline__ u32 packh2(float lo, float hi) {
    u32 r;
    asm("cvt.rn.f16x2.f32 %0, %1, %2;" : "=r"(r) : "f"(hi), "f"(lo));
    return r;
}

// GEMM smem: 4 stages x 16KB (A 8K | B 8K per stage)
#define STAGE_BYTES 16384
#define SM_GEMM     (4 * STAGE_BYTES)

// ---------------------------------------------------------------------------
// prep_w: 4 weight matrices -> fused fp16 [4096][1024]
// ---------------------------------------------------------------------------
__global__ void __launch_bounds__(256) prep_w_kernel(
    const float* __restrict__ Wq, const float* __restrict__ Wk,
    const float* __restrict__ Wv, const float* __restrict__ Wp)
{
    int blk = blockIdx.x;
    int mat = blk >> 10;
    const float* src = (mat == 0) ? Wq : (mat == 1) ? Wk : (mat == 2) ? Wv : Wp;
    size_t idx = ((size_t)(blk & 1023) * 256 + threadIdx.x) * 4;
    float4 v = *(const float4*)(src + idx);
    size_t o = (size_t)mat * 1048576 + idx;
    ushort4 h;
    h.x = f16r(v.x); h.y = f16r(v.y); h.z = f16r(v.z); h.w = f16r(v.w);
    *(ushort4*)(g_wf16 + o) = h;
}

// ---------------------------------------------------------------------------
// prep_x: x[b][c][n] -> transposed fp16 [pixel=b*64+n][c]
// ---------------------------------------------------------------------------
__global__ void __launch_bounds__(256) prep_x_kernel(const float* __restrict__ x) {
    __shared__ u16 hT[64][72];
    const int b = blockIdx.x, t = threadIdx.x;
    const float* xb = x + (size_t)b * 65536;
    for (int ct = 0; ct < 16; ++ct) {
        #pragma unroll
        for (int i = 0; i < 16; ++i) {
            int idx = i * 256 + t, c = idx >> 6, n = idx & 63;
            hT[n][c] = f16r(xb[(ct * 64 + c) * 64 + n]);
        }
        __syncthreads();
        #pragma unroll
        for (int i = 0; i < 2; ++i) {
            int idx = i * 256 + t;
            int n = idx >> 3, c8 = (idx & 7) << 3;
            size_t o = (size_t)(b * 64 + n) * 1024 + ct * 64 + c8;
            *(uint4*)(g_xf16 + o) = *(const uint4*)&hT[n][c8];
        }
        __syncthreads();
    }
}

// ---------------------------------------------------------------------------
// GEMM core: C[128 pix][128 ch] = A x B^T over K=1024, fp16 single-pass.
// ---------------------------------------------------------------------------
__device__ __forceinline__ void gemm_issue_stage(
    u32 sb, int s, int c, const char* gA, const char* gB)
{
    const int t = threadIdx.x;
    const char* gsrc[2] = {gA, gB};
    u32 stb = sb + s * STAGE_BYTES;
    #pragma unroll
    for (int arr = 0; arr < 2; ++arr) {
        #pragma unroll
        for (int r2 = 0; r2 < 2; ++r2) {
            int ch = t + r2 * 256;
            int row = ch >> 2, part = ch & 3;
            u32 dst = stb + arr * 8192 + row * 64 + ((part ^ ((row >> 1) & 3)) << 4);
            const char* src = gsrc[arr] + (size_t)row * 2048 + c * 64 + part * 16;
            cpa16(dst, src);
        }
    }
    CP_COMMIT();
}

__device__ __forceinline__ void gemm_compute_stage(u32 sb, int s, float acc[4][4][4],
                                                   int wm, int wn, int lane)
{
    u32 stb = sb + s * STAGE_BYTES;
    u32 pA = stb, pB = stb + 8192;
    const int arow = lane & 15;
    const int akb  = (lane >> 4) << 4;
    const int brow = (lane & 7) + ((lane & 16) >> 1);
    const int bkb  = (lane & 8) << 1;
    #pragma unroll
    for (int ks = 0; ks < 2; ++ks) {
        int kb = ks * 32;
        u32 A[4][4], B[4][2];
        #pragma unroll
        for (int i = 0; i < 4; ++i)
            ldsm_x4(A[i], sw_addr(pA, wm + i * 16 + arow, kb + akb));
        #pragma unroll
        for (int jp = 0; jp < 2; ++jp) {
            u32 r[4];
            ldsm_x4(r, sw_addr(pB, wn + jp * 16 + brow, kb + bkb));
            B[jp*2][0] = r[0]; B[jp*2][1] = r[1];
            B[jp*2+1][0] = r[2]; B[jp*2+1][1] = r[3];
        }
        #pragma unroll
        for (int i = 0; i < 4; ++i)
            #pragma unroll
            for (int j = 0; j < 4; ++j) mma16816(acc[i][j], A[i], B[j]);
    }
}

#define GEMM_MAINLOOP(gA, gB, acc)                                              \
    do {                                                                        \
        gemm_issue_stage(sb, 0, 0, gA, gB);                                     \
        gemm_issue_stage(sb, 1, 1, gA, gB);                                     \
        gemm_issue_stage(sb, 2, 2, gA, gB);                                     \
        for (int c = 0; c < 32; ++c) {                                          \
            CP_WAIT2();                                                         \
            __syncthreads();                                                    \
            gemm_compute_stage(sb, c & 3, acc, wm, wn, lane);                   \
            if (c + 3 < 32) gemm_issue_stage(sb, (c + 3) & 3, c + 3, gA, gB);   \
            else CP_COMMIT();                                                   \
        }                                                                       \
    } while (0)

// ---------------------------------------------------------------------------
// QKV GEMM: grid (24 ntiles, 512 pixel-groups). out fp16 q/k/v [pixel][ch]+bias
// ---------------------------------------------------------------------------
__global__ void __launch_bounds__(256) qkv_gemm_kernel(
    const float* __restrict__ bq, const float* __restrict__ bk,
    const float* __restrict__ bv)
{
    extern __shared__ char smc[];
    const u32 sb = smem_u32(smc);
    const int t = threadIdx.x, wid = t >> 5, lane = t & 31;
    const int grp = lane >> 2, tig = lane & 3;
    const int wm = (wid & 1) << 6, wn = (wid >> 1) << 5;
    const int nt = blockIdx.x, mg = blockIdx.y;

    const char* gA = (const char*)g_xf16 + (size_t)mg * 128 * 2048;
    const char* gB = (const char*)g_wf16 + (size_t)nt * 128 * 2048;

    float acc[4][4][4];
    #pragma unroll
    for (int i = 0; i < 4; ++i)
        #pragma unroll
        for (int j = 0; j < 4; ++j) { acc[i][j][0]=0.f; acc[i][j][1]=0.f; acc[i][j][2]=0.f; acc[i][j][3]=0.f; }

    GEMM_MAINLOOP(gA, gB, acc);

    const int sel = nt >> 3;
    const int cbase = (nt & 7) * 128;
    const float* bias = (sel == 0) ? bq : (sel == 1) ? bk : bv;
    u16* out = g_qkv16 + (size_t)sel * QKVSZ;
    #pragma unroll
    for (int i = 0; i < 4; ++i) {
        int prow = mg * 128 + wm + i * 16 + grp;
        #pragma unroll
        for (int j = 0; j < 4; ++j) {
            int col = cbase + wn + j * 8 + tig * 2;
            float b0 = bias[col], b1 = bias[col + 1];
            *(u32*)(out + (size_t)prow * 1024 + col) = packh2(acc[i][j][0] + b0, acc[i][j][1] + b1);
            *(u32*)(out + (size_t)(prow + 8) * 1024 + col) = packh2(acc[i][j][2] + b0, acc[i][j][3] + b1);
        }
    }
}

// ---------------------------------------------------------------------------
// Proj GEMM: grid (8 ntiles, 512 pixel-groups). A = attn out fp16.
// Epilogue: smem transpose -> residual r = g*(out+bias) + (1-g)*x  [b][c][n].
// ---------------------------------------------------------------------------
__global__ void __launch_bounds__(256) proj_gemm_kernel(
    const float* __restrict__ bp, const float* __restrict__ x,
    const float* __restrict__ gamma_p)
{
    extern __shared__ char smc[];
    const u32 sb = smem_u32(smc);
    const int t = threadIdx.x, wid = t >> 5, lane = t & 31;
    const int grp = lane >> 2, tig = lane & 3;
    const int wm = (wid & 1) << 6, wn = (wid >> 1) << 5;
    const int nt = blockIdx.x, mg = blockIdx.y;

    const char* gA = (const char*)g_of16 + (size_t)mg * 128 * 2048;
    const char* gB = (const char*)g_wf16 + (size_t)(3072 + nt * 128) * 2048;

    float acc[4][4][4];
    #pragma unroll
    for (int i = 0; i < 4; ++i)
        #pragma unroll
        for (int j = 0; j < 4; ++j) { acc[i][j][0]=0.f; acc[i][j][1]=0.f; acc[i][j][2]=0.f; acc[i][j][3]=0.f; }

    GEMM_MAINLOOP(gA, gB, acc);

    const float g = gamma_p[0], og = 1.0f - g;
    __syncthreads();
    float* tile = (float*)smc;
    #pragma unroll
    for (int half = 0; half < 2; ++half) {
        if ((wm >> 6) == half) {
            #pragma unroll
            for (int i = 0; i < 4; ++i) {
                int pm = i * 16 + grp;
                #pragma unroll
                for (int j = 0; j < 4; ++j) {
                    int cc = wn + j * 8 + tig * 2;
                    *(float2*)&tile[pm * 130 + cc] = make_float2(acc[i][j][0], acc[i][j][1]);
                    *(float2*)&tile[(pm + 8) * 130 + cc] = make_float2(acc[i][j][2], acc[i][j][3]);
                }
            }
        }
        __syncthreads();
        int b = mg * 2 + half;
        #pragma unroll
        for (int it = 0; it < 8; ++it) {
            int idx = it * 256 + t;
            int cc = idx >> 4, n4 = (idx & 15) << 2;
            int ch = nt * 128 + cc;
            float bi = bp[ch];
            size_t off = (size_t)b * 65536 + (size_t)ch * 64 + n4;
            float4 xv = *(const float4*)(x + off);
            float4 v;
            v.x = g * (tile[(n4 + 0) * 130 + cc] + bi) + og * xv.x;
            v.y = g * (tile[(n4 + 1) * 130 + cc] + bi) + og * xv.y;
            v.z = g * (tile[(n4 + 2) * 130 + cc] + bi) + og * xv.z;
            v.w = g * (tile[(n4 + 3) * 130 + cc] + bi) + og * xv.w;
            *(float4*)(g_res + off) = v;
        }
        __syncthreads();
    }
}

// ---------------------------------------------------------------------------
// Attention (tensor-core): one CTA per (b,h), 128 threads / 4 warps.
// ---------------------------------------------------------------------------
__global__ void __launch_bounds__(128) attn_kernel(const float* __restrict__ temp_p)
{
    __shared__ __align__(128) u16 qs[4096];   // [n][d] fp16, sw128
    __shared__ __align__(128) u16 kk[4096];   // [m][d]
    __shared__ __align__(128) u16 vv[4096];   // [m][d]
    __shared__ float scq[64], sck[64];

    const int t = threadIdx.x, lane = t & 31, wid = t >> 5;
    const int b = blockIdx.x >> 4, h = blockIdx.x & 15;
    const u32 q0 = smem_u32(qs), k0 = smem_u32(kk), v0 = smem_u32(vv);

    // ---- load q/k/v tiles (64 x 64 fp16 each) via cp.async ----
    {
        u32 bases[3] = {q0, k0, v0};
        #pragma unroll
        for (int i = 0; i < 12; ++i) {
            int idx = t + i * 128;           // 0..1535
            int arr = idx >> 9, rem = idx & 511;
            int row = rem >> 3, ch = rem & 7;
            u32 dst = bases[arr] + row * 128 + ((ch ^ (row & 7)) << 4);
            const char* src = (const char*)(g_qkv16 + (size_t)arr * QKVSZ)
                            + ((size_t)(b * 64 + row) * 1024 + h * 64) * 2 + ch * 16;
            cpa16(dst, src);
        }
        CP_COMMIT();
        CP_WAIT0();
        __syncthreads();
    }

    // ---- per-d column norms over the spatial axis (fp32) ----
    {
        float tinv = 1.0f / (temp_p[0] + 1e-6f);
        int d = t & 63;
        const __half* base = (const __half*)((t < 64) ? qs : kk);
        int cb = d >> 3, io = (d * 2) & 15;
        float s = 0.f;
        #pragma unroll 8
        for (int n = 0; n < 64; ++n) {
            int bi = (n * 128 + ((cb ^ (n & 7)) << 4) + io) >> 1;
            float v = __half2float(base[bi]);
            s += v * v;
        }
        float inv = 1.0f / fmaxf(sqrtf(s), 1e-12f);
        if (t < 64) scq[d] = inv; else sck[d] = inv;
        __syncthreads();
        if (t < 64) scq[d] = scq[d] * sck[d] * tinv;
        __syncthreads();
    }

    // ---- fold combined scale into q (fp16, in place) ----
    {
        u32* qw = (u32*)qs;
        #pragma unroll
        for (int i = 0; i < 16; ++i) {
            int idx = t + i * 128;
            int row = idx >> 5, pos = idx & 31;
            int ui = (row * 128 + (((pos >> 2) ^ (row & 7)) << 4) + (pos & 3) * 4) >> 2;
            float2 f = __half22float2(*(__half2*)&qw[ui]);
            f.x *= scq[pos * 2];
            f.y *= scq[pos * 2 + 1];
            qw[ui] = packh2(f.x, f.y);
        }
        __syncthreads();
    }

    // ---- S = qhat^T khat ----
    const int wm = wid << 4;
    float sa[8][4];
    #pragma unroll
    for (int j = 0; j < 8; ++j) { sa[j][0]=0.f; sa[j][1]=0.f; sa[j][2]=0.f; sa[j][3]=0.f; }
    {
        const int arow = lane & 15, akb = (lane >> 4) << 4;
        const int br = (lane & 7) + ((lane & 16) >> 1), bkb = (lane & 8) << 1;
        #pragma unroll
        for (int ks = 0; ks < 4; ++ks) {
            int kb = ks * 32;
            u32 A[4];
            ldsm_x4(A, sw128(q0, wm + arow, kb + akb));
            #pragma unroll
            for (int jp = 0; jp < 4; ++jp) {
                u32 r[4];
                ldsm_x4(r, sw128(k0, jp * 16 + br, kb + bkb));
                mma16816(sa[jp * 2], A, r);
                mma16816(sa[jp * 2 + 1], A, r + 2);
            }
        }
    }

    // ---- softmax + repack P into A-fragments ----
    u32 pa[4][4];
    {
        float mx0 = -1e30f, mx1 = -1e30f;
        #pragma unroll
        for (int j = 0; j < 8; ++j) {
            mx0 = fmaxf(mx0, fmaxf(sa[j][0], sa[j][1]));
            mx1 = fmaxf(mx1, fmaxf(sa[j][2], sa[j][3]));
        }
        #pragma unroll
        for (int o = 1; o <= 2; o <<= 1) {
            mx0 = fmaxf(mx0, __shfl_xor_sync(0xffffffffu, mx0, o));
            mx1 = fmaxf(mx1, __shfl_xor_sync(0xffffffffu, mx1, o));
        }
        float sum0 = 0.f, sum1 = 0.f;
        #pragma unroll
        for (int j = 0; j < 8; ++j) {
            sa[j][0] = __expf(sa[j][0] - mx0); sum0 += sa[j][0];
            sa[j][1] = __expf(sa[j][1] - mx0); sum0 += sa[j][1];
            sa[j][2] = __expf(sa[j][2] - mx1); sum1 += sa[j][2];
            sa[j][3] = __expf(sa[j][3] - mx1); sum1 += sa[j][3];
        }
        #pragma unroll
        for (int o = 1; o <= 2; o <<= 1) {
            sum0 += __shfl_xor_sync(0xffffffffu, sum0, o);
            sum1 += __shfl_xor_sync(0xffffffffu, sum1, o);
        }
        float r0 = 1.0f / sum0, r1 = 1.0f / sum1;
        #pragma unroll
        for (int ks = 0; ks < 4; ++ks) {
            pa[ks][0] = packh2(sa[2*ks][0] * r0, sa[2*ks][1] * r0);
            pa[ks][1] = packh2(sa[2*ks][2] * r1, sa[2*ks][3] * r1);
            pa[ks][2] = packh2(sa[2*ks+1][0] * r0, sa[2*ks+1][1] * r0);
            pa[ks][3] = packh2(sa[2*ks+1][2] * r1, sa[2*ks+1][3] * r1);
        }
    }

    // ---- O = P V ----
    float oa[8][4];
    #pragma unroll
    for (int j = 0; j < 8; ++j) { oa[j][0]=0.f; oa[j][1]=0.f; oa[j][2]=0.f; oa[j][3]=0.f; }
    {
        const int vrow = lane & 15, vdb = (lane >> 4) << 4;
        #pragma unroll
        for (int ks = 0; ks < 4; ++ks) {
            #pragma unroll
            for (int Dp = 0; Dp < 4; ++Dp) {
                u32 r[4];
                ldsm_x4t(r, sw128(v0, ks * 16 + vrow, Dp * 32 + vdb));
                mma16816(oa[Dp * 2], pa[ks], r);
                mma16816(oa[Dp * 2 + 1], pa[ks], r + 2);
            }
        }
    }
    __syncthreads();

    // ---- bounce O through smem, coalesced fp16 writes ----
    {
        u32* bn = (u32*)qs;
        int grp = lane >> 2, tg = lane & 3;
        #pragma unroll
        for (int jd = 0; jd < 8; ++jd) {
            int c = jd * 4 + tg;
            bn[(wm + grp) * 33 + c]     = packh2(oa[jd][0], oa[jd][1]);
            bn[(wm + grp + 8) * 33 + c] = packh2(oa[jd][2], oa[jd][3]);
        }
        __syncthreads();
        u16* outg = g_of16 + (size_t)(b * 64) * 1024 + h * 64;
        #pragma unroll
        for (int i = 0; i < 16; ++i) {
            int idx = t + i * 128;
            int row = idx >> 5, c = idx & 31;
            *(u32*)(outg + (size_t)row * 1024 + c * 2) = bn[row * 33 + c];
        }
    }
}

// ---------------------------------------------------------------------------
// Fused LayerNorm: one CTA per batch, 512 threads, two passes over g_res.
// y = (r - mu) * rstd * ln_w + ln_b
// ---------------------------------------------------------------------------
__global__ void __launch_bounds__(512) ln_kernel(
    const float* __restrict__ lnw, const float* __restrict__ lnb,
    float* __restrict__ y)
{
    __shared__ float r1[16], r2[16];
    const int b = blockIdx.x, t = threadIdx.x;
    const float* rb = g_res + (size_t)b * 65536;
    float s1 = 0.f, s2 = 0.f;
    #pragma unroll 4
    for (int i = t * 4; i < 65536; i += 2048) {
        float4 p = *(const float4*)(rb + i);
        s1 += p.x + p.y + p.z + p.w;
        s2 += p.x * p.x + p.y * p.y + p.z * p.z + p.w * p.w;
    }
    #pragma unroll
    for (int o = 16; o; o >>= 1) {
        s1 += __shfl_xor_sync(0xffffffffu, s1, o);
        s2 += __shfl_xor_sync(0xffffffffu, s2, o);
    }
    if ((t & 31) == 0) { r1[t >> 5] = s1; r2[t >> 5] = s2; }
    __syncthreads();
    if (t < 16) {
        s1 = r1[t]; s2 = r2[t];
        #pragma unroll
        for (int o = 8; o; o >>= 1) {
            s1 += __shfl_xor_sync(0x0000ffffu, s1, o);
            s2 += __shfl_xor_sync(0x0000ffffu, s2, o);
        }
        if (t == 0) {
            float mu  = s1 * (1.0f / 65536.0f);
            float var = s2 * (1.0f / 65536.0f) - mu * mu;
            r1[0] = mu;
            r2[0] = rsqrtf(var + 1e-5f);
        }
    }
    __syncthreads();
    const float mu = r1[0], rs = r2[0];
    float* yb = y + (size_t)b * 65536;
    #pragma unroll 4
    for (int i = t * 4; i < 65536; i += 2048) {
        float4 p = *(const float4*)(rb + i);
        float4 w = *(const float4*)(lnw + i);
        float4 lb = *(const float4*)(lnb + i);
        float4 o;
        o.x = (p.x - mu) * rs * w.x + lb.x;
        o.y = (p.y - mu) * rs * w.y + lb.y;
        o.z = (p.z - mu) * rs * w.z + lb.z;
        o.w = (p.w - mu) * rs * w.w + lb.w;
        *(float4*)(yb + i) = o;
    }
}

// ---------------------------------------------------------------------------
extern "C" void kernel_launch(void* const* d_in, const int* in_sizes, int n_in,
                              void* d_out, int out_size)
{
    const float* x     = (const float*)d_in[0];
    const float* Wq    = (const float*)d_in[1];
    const float* bq    = (const float*)d_in[2];
    const float* Wk    = (const float*)d_in[3];
    const float* bk    = (const float*)d_in[4];
    const float* Wv    = (const float*)d_in[5];
    const float* bv    = (const float*)d_in[6];
    const float* Wp    = (const float*)d_in[7];
    const float* bp    = (const float*)d_in[8];
    const float* gamma = (const float*)d_in[9];
    const float* temp  = (const float*)d_in[10];
    const float* lnw   = (const float*)d_in[11];
    const float* lnb   = (const float*)d_in[12];
    float* y = (float*)d_out;

    cudaFuncSetAttribute(qkv_gemm_kernel, cudaFuncAttributeMaxDynamicSharedMemorySize, SM_GEMM);
    cudaFuncSetAttribute(proj_gemm_kernel, cudaFuncAttributeMaxDynamicSharedMemorySize, SM_GEMM);

    prep_w_kernel<<<4096, 256>>>(Wq, Wk, Wv, Wp);
    prep_x_kernel<<<BB, 256>>>(x);
    qkv_gemm_kernel<<<dim3(24, 512), 256, SM_GEMM>>>(bq, bk, bv);
    attn_kernel<<<BB * NH, 128>>>(temp);
    proj_gemm_kernel<<<dim3(8, 512), 256, SM_GEMM>>>(bp, x, gamma);
    ln_kernel<<<BB, 512>>>(lnw, lnb, y);
}

// round 10
// speedup vs baseline: 4.1004x; 1.0249x over previous
#include <cuda_runtime.h>
#include <cuda_fp16.h>

#define NH   16
#define NN   64
#define CC   1024
#define BB   1024

typedef unsigned int u32;
typedef unsigned long long u64;
typedef unsigned short u16;

#define QKVSZ 67108864ull          // 1024*64*1024 elems

// Scratch (allocation-free rule: device globals)
__device__ u16   g_xf16[(size_t)BB * NN * CC];    // x transposed, fp16 [pixel][ch]
__device__ u16   g_wf16[(size_t)4096 * CC];       // Wq,Wk,Wv,Wp fused rows, fp16 RN
__device__ u16   g_qkv16[3ull * QKVSZ];           // q,k,v fp16 [pixel][ch]
__device__ u16   g_of16[(size_t)BB * NN * CC];    // attn out fp16 [pixel][ch]
__device__ float g_res [(size_t)BB * CC * NN];    // residual r [b][c][n]
__device__ float g_stats[2 * BB];

// ---------------------------------------------------------------------------
// helpers
// ---------------------------------------------------------------------------
__device__ __forceinline__ u32 smem_u32(const void* p) {
    u32 a;
    asm("{ .reg .u64 t; cvta.to.shared.u64 t, %1; cvt.u32.u64 %0, t; }" : "=r"(a) : "l"(p));
    return a;
}
__device__ __forceinline__ void cpa16(u32 dst, const void* src) {
    asm volatile("cp.async.cg.shared.global [%0], [%1], 16;" :: "r"(dst), "l"(src));
}
#define CP_COMMIT() asm volatile("cp.async.commit_group;" ::: "memory")
#define CP_WAIT2()  asm volatile("cp.async.wait_group 2;" ::: "memory")
#define CP_WAIT0()  asm volatile("cp.async.wait_group 0;" ::: "memory")

__device__ __forceinline__ void ldsm_x4(u32* r, u32 addr) {
    asm volatile("ldmatrix.sync.aligned.m8n8.x4.shared.b16 {%0,%1,%2,%3}, [%4];"
        : "=r"(r[0]), "=r"(r[1]), "=r"(r[2]), "=r"(r[3]) : "r"(addr));
}
__device__ __forceinline__ void ldsm_x4t(u32* r, u32 addr) {
    asm volatile("ldmatrix.sync.aligned.m8n8.x4.trans.shared.b16 {%0,%1,%2,%3}, [%4];"
        : "=r"(r[0]), "=r"(r[1]), "=r"(r[2]), "=r"(r[3]) : "r"(addr));
}
__device__ __forceinline__ void mma16816(float* c, const u32* a, const u32* b) {
    asm volatile("mma.sync.aligned.m16n8k16.row.col.f32.f16.f16.f32 "
        "{%0,%1,%2,%3}, {%4,%5,%6,%7}, {%8,%9}, {%0,%1,%2,%3};"
        : "+f"(c[0]), "+f"(c[1]), "+f"(c[2]), "+f"(c[3])
        : "r"(a[0]), "r"(a[1]), "r"(a[2]), "r"(a[3]), "r"(b[0]), "r"(b[1]));
}
// GEMM smem swizzle: rows of 64B (4 chunks), chunk ^= (row>>1)&3
__device__ __forceinline__ u32 sw_addr(u32 base, int row, int kbyte) {
    int chunk = kbyte >> 4, in = kbyte & 15;
    return base + row * 64 + ((chunk ^ ((row >> 1) & 3)) << 4) + in;
}
// attn smem swizzle: rows of 128B (8 chunks), chunk ^= row&7
__device__ __forceinline__ u32 sw128(u32 base, int row, int kbyte) {
    int chunk = kbyte >> 4, in = kbyte & 15;
    return base + row * 128 + ((chunk ^ (row & 7)) << 4) + in;
}
__device__ __forceinline__ u16 f16r(float f) {
    __half h = __float2half_rn(f);
    return *reinterpret_cast<u16*>(&h);
}
__device__ __forceinline__ u32 packh2(float lo, float hi) {
    u32 r;
    asm("cvt.rn.f16x2.f32 %0, %1, %2;" : "=r"(r) : "f"(hi), "f"(lo));
    return r;
}

// GEMM smem: 4 stages x 16KB (A 8K | B 8K per stage)
#define STAGE_BYTES 16384
#define SM_GEMM     (4 * STAGE_BYTES)

// ---------------------------------------------------------------------------
// prep_w: 4 weight matrices -> fused fp16 [4096][1024]
// ---------------------------------------------------------------------------
__global__ void __launch_bounds__(256) prep_w_kernel(
    const float* __restrict__ Wq, const float* __restrict__ Wk,
    const float* __restrict__ Wv, const float* __restrict__ Wp)
{
    int blk = blockIdx.x;
    int mat = blk >> 10;
    const float* src = (mat == 0) ? Wq : (mat == 1) ? Wk : (mat == 2) ? Wv : Wp;
    size_t idx = ((size_t)(blk & 1023) * 256 + threadIdx.x) * 4;
    float4 v = *(const float4*)(src + idx);
    size_t o = (size_t)mat * 1048576 + idx;
    ushort4 h;
    h.x = f16r(v.x); h.y = f16r(v.y); h.z = f16r(v.z); h.w = f16r(v.w);
    *(ushort4*)(g_wf16 + o) = h;
}

// ---------------------------------------------------------------------------
// prep_x: x[b][c][n] -> transposed fp16 [pixel=b*64+n][c]
// ---------------------------------------------------------------------------
__global__ void __launch_bounds__(256) prep_x_kernel(const float* __restrict__ x) {
    __shared__ u16 hT[64][72];
    const int b = blockIdx.x, t = threadIdx.x;
    const float* xb = x + (size_t)b * 65536;
    for (int ct = 0; ct < 16; ++ct) {
        #pragma unroll
        for (int i = 0; i < 16; ++i) {
            int idx = i * 256 + t, c = idx >> 6, n = idx & 63;
            hT[n][c] = f16r(xb[(ct * 64 + c) * 64 + n]);
        }
        __syncthreads();
        #pragma unroll
        for (int i = 0; i < 2; ++i) {
            int idx = i * 256 + t;
            int n = idx >> 3, c8 = (idx & 7) << 3;
            size_t o = (size_t)(b * 64 + n) * 1024 + ct * 64 + c8;
            *(uint4*)(g_xf16 + o) = *(const uint4*)&hT[n][c8];
        }
        __syncthreads();
    }
}

// ---------------------------------------------------------------------------
// GEMM core: C[128 pix][128 ch] = A x B^T over K=1024, fp16 single-pass.
// ---------------------------------------------------------------------------
__device__ __forceinline__ void gemm_issue_stage(
    u32 sb, int s, int c, const char* gA, const char* gB)
{
    const int t = threadIdx.x;
    const char* gsrc[2] = {gA, gB};
    u32 stb = sb + s * STAGE_BYTES;
    #pragma unroll
    for (int arr = 0; arr < 2; ++arr) {
        #pragma unroll
        for (int r2 = 0; r2 < 2; ++r2) {
            int ch = t + r2 * 256;
            int row = ch >> 2, part = ch & 3;
            u32 dst = stb + arr * 8192 + row * 64 + ((part ^ ((row >> 1) & 3)) << 4);
            const char* src = gsrc[arr] + (size_t)row * 2048 + c * 64 + part * 16;
            cpa16(dst, src);
        }
    }
    CP_COMMIT();
}

__device__ __forceinline__ void gemm_compute_stage(u32 sb, int s, float acc[4][4][4],
                                                   int wm, int wn, int lane)
{
    u32 stb = sb + s * STAGE_BYTES;
    u32 pA = stb, pB = stb + 8192;
    const int arow = lane & 15;
    const int akb  = (lane >> 4) << 4;
    const int brow = (lane & 7) + ((lane & 16) >> 1);
    const int bkb  = (lane & 8) << 1;
    #pragma unroll
    for (int ks = 0; ks < 2; ++ks) {
        int kb = ks * 32;
        u32 A[4][4], B[4][2];
        #pragma unroll
        for (int i = 0; i < 4; ++i)
            ldsm_x4(A[i], sw_addr(pA, wm + i * 16 + arow, kb + akb));
        #pragma unroll
        for (int jp = 0; jp < 2; ++jp) {
            u32 r[4];
            ldsm_x4(r, sw_addr(pB, wn + jp * 16 + brow, kb + bkb));
            B[jp*2][0] = r[0]; B[jp*2][1] = r[1];
            B[jp*2+1][0] = r[2]; B[jp*2+1][1] = r[3];
        }
        #pragma unroll
        for (int i = 0; i < 4; ++i)
            #pragma unroll
            for (int j = 0; j < 4; ++j) mma16816(acc[i][j], A[i], B[j]);
    }
}

#define GEMM_MAINLOOP(gA, gB, acc)                                              \
    do {                                                                        \
        gemm_issue_stage(sb, 0, 0, gA, gB);                                     \
        gemm_issue_stage(sb, 1, 1, gA, gB);                                     \
        gemm_issue_stage(sb, 2, 2, gA, gB);                                     \
        for (int c = 0; c < 32; ++c) {                                          \
            CP_WAIT2();                                                         \
            __syncthreads();                                                    \
            gemm_compute_stage(sb, c & 3, acc, wm, wn, lane);                   \
            if (c + 3 < 32) gemm_issue_stage(sb, (c + 3) & 3, c + 3, gA, gB);   \
            else CP_COMMIT();                                                   \
        }                                                                       \
    } while (0)

// ---------------------------------------------------------------------------
// QKV GEMM: grid (24 ntiles, 512 pixel-groups). out fp16 q/k/v [pixel][ch]+bias
// 2 CTAs/SM (regs capped at 128; single-pass frag budget ~113 fits).
// ---------------------------------------------------------------------------
__global__ void __launch_bounds__(256, 2) qkv_gemm_kernel(
    const float* __restrict__ bq, const float* __restrict__ bk,
    const float* __restrict__ bv)
{
    extern __shared__ char smc[];
    const u32 sb = smem_u32(smc);
    const int t = threadIdx.x, wid = t >> 5, lane = t & 31;
    const int grp = lane >> 2, tig = lane & 3;
    const int wm = (wid & 1) << 6, wn = (wid >> 1) << 5;
    const int nt = blockIdx.x, mg = blockIdx.y;

    const char* gA = (const char*)g_xf16 + (size_t)mg * 128 * 2048;
    const char* gB = (const char*)g_wf16 + (size_t)nt * 128 * 2048;

    float acc[4][4][4];
    #pragma unroll
    for (int i = 0; i < 4; ++i)
        #pragma unroll
        for (int j = 0; j < 4; ++j) { acc[i][j][0]=0.f; acc[i][j][1]=0.f; acc[i][j][2]=0.f; acc[i][j][3]=0.f; }

    GEMM_MAINLOOP(gA, gB, acc);

    const int sel = nt >> 3;
    const int cbase = (nt & 7) * 128;
    const float* bias = (sel == 0) ? bq : (sel == 1) ? bk : bv;
    u16* out = g_qkv16 + (size_t)sel * QKVSZ;
    #pragma unroll
    for (int i = 0; i < 4; ++i) {
        int prow = mg * 128 + wm + i * 16 + grp;
        #pragma unroll
        for (int j = 0; j < 4; ++j) {
            int col = cbase + wn + j * 8 + tig * 2;
            float b0 = bias[col], b1 = bias[col + 1];
            *(u32*)(out + (size_t)prow * 1024 + col) = packh2(acc[i][j][0] + b0, acc[i][j][1] + b1);
            *(u32*)(out + (size_t)(prow + 8) * 1024 + col) = packh2(acc[i][j][2] + b0, acc[i][j][3] + b1);
        }
    }
}

// ---------------------------------------------------------------------------
// Proj GEMM: grid (8 ntiles, 512 pixel-groups). A = attn out fp16.
// Epilogue: smem transpose -> residual r = g*(out+bias) + (1-g)*x  [b][c][n].
// ---------------------------------------------------------------------------
__global__ void __launch_bounds__(256, 2) proj_gemm_kernel(
    const float* __restrict__ bp, const float* __restrict__ x,
    const float* __restrict__ gamma_p)
{
    extern __shared__ char smc[];
    const u32 sb = smem_u32(smc);
    const int t = threadIdx.x, wid = t >> 5, lane = t & 31;
    const int grp = lane >> 2, tig = lane & 3;
    const int wm = (wid & 1) << 6, wn = (wid >> 1) << 5;
    const int nt = blockIdx.x, mg = blockIdx.y;

    const char* gA = (const char*)g_of16 + (size_t)mg * 128 * 2048;
    const char* gB = (const char*)g_wf16 + (size_t)(3072 + nt * 128) * 2048;

    float acc[4][4][4];
    #pragma unroll
    for (int i = 0; i < 4; ++i)
        #pragma unroll
        for (int j = 0; j < 4; ++j) { acc[i][j][0]=0.f; acc[i][j][1]=0.f; acc[i][j][2]=0.f; acc[i][j][3]=0.f; }

    GEMM_MAINLOOP(gA, gB, acc);

    const float g = gamma_p[0], og = 1.0f - g;
    __syncthreads();
    float* tile = (float*)smc;
    #pragma unroll
    for (int half = 0; half < 2; ++half) {
        if ((wm >> 6) == half) {
            #pragma unroll
            for (int i = 0; i < 4; ++i) {
                int pm = i * 16 + grp;
                #pragma unroll
                for (int j = 0; j < 4; ++j) {
                    int cc = wn + j * 8 + tig * 2;
                    *(float2*)&tile[pm * 130 + cc] = make_float2(acc[i][j][0], acc[i][j][1]);
                    *(float2*)&tile[(pm + 8) * 130 + cc] = make_float2(acc[i][j][2], acc[i][j][3]);
                }
            }
        }
        __syncthreads();
        int b = mg * 2 + half;
        #pragma unroll
        for (int it = 0; it < 8; ++it) {
            int idx = it * 256 + t;
            int cc = idx >> 4, n4 = (idx & 15) << 2;
            int ch = nt * 128 + cc;
            float bi = bp[ch];
            size_t off = (size_t)b * 65536 + (size_t)ch * 64 + n4;
            float4 xv = *(const float4*)(x + off);
            float4 v;
            v.x = g * (tile[(n4 + 0) * 130 + cc] + bi) + og * xv.x;
            v.y = g * (tile[(n4 + 1) * 130 + cc] + bi) + og * xv.y;
            v.z = g * (tile[(n4 + 2) * 130 + cc] + bi) + og * xv.z;
            v.w = g * (tile[(n4 + 3) * 130 + cc] + bi) + og * xv.w;
            *(float4*)(g_res + off) = v;
        }
        __syncthreads();
    }
}

// ---------------------------------------------------------------------------
// Attention (tensor-core): one CTA per (b,h), 128 threads / 4 warps.
// ---------------------------------------------------------------------------
__global__ void __launch_bounds__(128) attn_kernel(const float* __restrict__ temp_p)
{
    __shared__ __align__(128) u16 qs[4096];   // [n][d] fp16, sw128
    __shared__ __align__(128) u16 kk[4096];   // [m][d]
    __shared__ __align__(128) u16 vv[4096];   // [m][d]
    __shared__ float scq[64], sck[64];

    const int t = threadIdx.x, lane = t & 31, wid = t >> 5;
    const int b = blockIdx.x >> 4, h = blockIdx.x & 15;
    const u32 q0 = smem_u32(qs), k0 = smem_u32(kk), v0 = smem_u32(vv);

    // ---- load q/k/v tiles (64 x 64 fp16 each) via cp.async ----
    {
        u32 bases[3] = {q0, k0, v0};
        #pragma unroll
        for (int i = 0; i < 12; ++i) {
            int idx = t + i * 128;           // 0..1535
            int arr = idx >> 9, rem = idx & 511;
            int row = rem >> 3, ch = rem & 7;
            u32 dst = bases[arr] + row * 128 + ((ch ^ (row & 7)) << 4);
            const char* src = (const char*)(g_qkv16 + (size_t)arr * QKVSZ)
                            + ((size_t)(b * 64 + row) * 1024 + h * 64) * 2 + ch * 16;
            cpa16(dst, src);
        }
        CP_COMMIT();
        CP_WAIT0();
        __syncthreads();
    }

    // ---- per-d column norms over the spatial axis (fp32) ----
    {
        float tinv = 1.0f / (temp_p[0] + 1e-6f);
        int d = t & 63;
        const __half* base = (const __half*)((t < 64) ? qs : kk);
        int cb = d >> 3, io = (d * 2) & 15;
        float s = 0.f;
        #pragma unroll 8
        for (int n = 0; n < 64; ++n) {
            int bi = (n * 128 + ((cb ^ (n & 7)) << 4) + io) >> 1;
            float v = __half2float(base[bi]);
            s += v * v;
        }
        float inv = 1.0f / fmaxf(sqrtf(s), 1e-12f);
        if (t < 64) scq[d] = inv; else sck[d] = inv;
        __syncthreads();
        if (t < 64) scq[d] = scq[d] * sck[d] * tinv;
        __syncthreads();
    }

    // ---- fold combined scale into q (fp16, in place) ----
    {
        u32* qw = (u32*)qs;
        #pragma unroll
        for (int i = 0; i < 16; ++i) {
            int idx = t + i * 128;
            int row = idx >> 5, pos = idx & 31;
            int ui = (row * 128 + (((pos >> 2) ^ (row & 7)) << 4) + (pos & 3) * 4) >> 2;
            float2 f = __half22float2(*(__half2*)&qw[ui]);
            f.x *= scq[pos * 2];
            f.y *= scq[pos * 2 + 1];
            qw[ui] = packh2(f.x, f.y);
        }
        __syncthreads();
    }

    // ---- S = qhat^T khat ----
    const int wm = wid << 4;
    float sa[8][4];
    #pragma unroll
    for (int j = 0; j < 8; ++j) { sa[j][0]=0.f; sa[j][1]=0.f; sa[j][2]=0.f; sa[j][3]=0.f; }
    {
        const int arow = lane & 15, akb = (lane >> 4) << 4;
        const int br = (lane & 7) + ((lane & 16) >> 1), bkb = (lane & 8) << 1;
        #pragma unroll
        for (int ks = 0; ks < 4; ++ks) {
            int kb = ks * 32;
            u32 A[4];
            ldsm_x4(A, sw128(q0, wm + arow, kb + akb));
            #pragma unroll
            for (int jp = 0; jp < 4; ++jp) {
                u32 r[4];
                ldsm_x4(r, sw128(k0, jp * 16 + br, kb + bkb));
                mma16816(sa[jp * 2], A, r);
                mma16816(sa[jp * 2 + 1], A, r + 2);
            }
        }
    }

    // ---- softmax + repack P into A-fragments ----
    u32 pa[4][4];
    {
        float mx0 = -1e30f, mx1 = -1e30f;
        #pragma unroll
        for (int j = 0; j < 8; ++j) {
            mx0 = fmaxf(mx0, fmaxf(sa[j][0], sa[j][1]));
            mx1 = fmaxf(mx1, fmaxf(sa[j][2], sa[j][3]));
        }
        #pragma unroll
        for (int o = 1; o <= 2; o <<= 1) {
            mx0 = fmaxf(mx0, __shfl_xor_sync(0xffffffffu, mx0, o));
            mx1 = fmaxf(mx1, __shfl_xor_sync(0xffffffffu, mx1, o));
        }
        float sum0 = 0.f, sum1 = 0.f;
        #pragma unroll
        for (int j = 0; j < 8; ++j) {
            sa[j][0] = __expf(sa[j][0] - mx0); sum0 += sa[j][0];
            sa[j][1] = __expf(sa[j][1] - mx0); sum0 += sa[j][1];
            sa[j][2] = __expf(sa[j][2] - mx1); sum1 += sa[j][2];
            sa[j][3] = __expf(sa[j][3] - mx1); sum1 += sa[j][3];
        }
        #pragma unroll
        for (int o = 1; o <= 2; o <<= 1) {
            sum0 += __shfl_xor_sync(0xffffffffu, sum0, o);
            sum1 += __shfl_xor_sync(0xffffffffu, sum1, o);
        }
        float r0 = 1.0f / sum0, r1 = 1.0f / sum1;
        #pragma unroll
        for (int ks = 0; ks < 4; ++ks) {
            pa[ks][0] = packh2(sa[2*ks][0] * r0, sa[2*ks][1] * r0);
            pa[ks][1] = packh2(sa[2*ks][2] * r1, sa[2*ks][3] * r1);
            pa[ks][2] = packh2(sa[2*ks+1][0] * r0, sa[2*ks+1][1] * r0);
            pa[ks][3] = packh2(sa[2*ks+1][2] * r1, sa[2*ks+1][3] * r1);
        }
    }

    // ---- O = P V ----
    float oa[8][4];
    #pragma unroll
    for (int j = 0; j < 8; ++j) { oa[j][0]=0.f; oa[j][1]=0.f; oa[j][2]=0.f; oa[j][3]=0.f; }
    {
        const int vrow = lane & 15, vdb = (lane >> 4) << 4;
        #pragma unroll
        for (int ks = 0; ks < 4; ++ks) {
            #pragma unroll
            for (int Dp = 0; Dp < 4; ++Dp) {
                u32 r[4];
                ldsm_x4t(r, sw128(v0, ks * 16 + vrow, Dp * 32 + vdb));
                mma16816(oa[Dp * 2], pa[ks], r);
                mma16816(oa[Dp * 2 + 1], pa[ks], r + 2);
            }
        }
    }
    __syncthreads();

    // ---- bounce O through smem, coalesced fp16 writes ----
    {
        u32* bn = (u32*)qs;
        int grp = lane >> 2, tg = lane & 3;
        #pragma unroll
        for (int jd = 0; jd < 8; ++jd) {
            int c = jd * 4 + tg;
            bn[(wm + grp) * 33 + c]     = packh2(oa[jd][0], oa[jd][1]);
            bn[(wm + grp + 8) * 33 + c] = packh2(oa[jd][2], oa[jd][3]);
        }
        __syncthreads();
        u16* outg = g_of16 + (size_t)(b * 64) * 1024 + h * 64;
        #pragma unroll
        for (int i = 0; i < 16; ++i) {
            int idx = t + i * 128;
            int row = idx >> 5, c = idx & 31;
            *(u32*)(outg + (size_t)row * 1024 + c * 2) = bn[row * 33 + c];
        }
    }
}

// ---------------------------------------------------------------------------
// Fused LayerNorm: one CTA per batch, 512 threads, two passes over g_res.
// ---------------------------------------------------------------------------
__global__ void __launch_bounds__(512) ln_kernel(
    const float* __restrict__ lnw, const float* __restrict__ lnb,
    float* __restrict__ y)
{
    __shared__ float r1[16], r2[16];
    const int b = blockIdx.x, t = threadIdx.x;
    const float* rb = g_res + (size_t)b * 65536;
    float s1 = 0.f, s2 = 0.f;
    #pragma unroll 4
    for (int i = t * 4; i < 65536; i += 2048) {
        float4 p = *(const float4*)(rb + i);
        s1 += p.x + p.y + p.z + p.w;
        s2 += p.x * p.x + p.y * p.y + p.z * p.z + p.w * p.w;
    }
    #pragma unroll
    for (int o = 16; o; o >>= 1) {
        s1 += __shfl_xor_sync(0xffffffffu, s1, o);
        s2 += __shfl_xor_sync(0xffffffffu, s2, o);
    }
    if ((t & 31) == 0) { r1[t >> 5] = s1; r2[t >> 5] = s2; }
    __syncthreads();
    if (t < 16) {
        s1 = r1[t]; s2 = r2[t];
        #pragma unroll
        for (int o = 8; o; o >>= 1) {
            s1 += __shfl_xor_sync(0x0000ffffu, s1, o);
            s2 += __shfl_xor_sync(0x0000ffffu, s2, o);
        }
        if (t == 0) {
            float mu  = s1 * (1.0f / 65536.0f);
            float var = s2 * (1.0f / 65536.0f) - mu * mu;
            r1[0] = mu;
            r2[0] = rsqrtf(var + 1e-5f);
        }
    }
    __syncthreads();
    const float mu = r1[0], rs = r2[0];
    float* yb = y + (size_t)b * 65536;
    #pragma unroll 4
    for (int i = t * 4; i < 65536; i += 2048) {
        float4 p = *(const float4*)(rb + i);
        float4 w = *(const float4*)(lnw + i);
        float4 lb = *(const float4*)(lnb + i);
        float4 o;
        o.x = (p.x - mu) * rs * w.x + lb.x;
        o.y = (p.y - mu) * rs * w.y + lb.y;
        o.z = (p.z - mu) * rs * w.z + lb.z;
        o.w = (p.w - mu) * rs * w.w + lb.w;
        *(float4*)(yb + i) = o;
    }
}

// ---------------------------------------------------------------------------
extern "C" void kernel_launch(void* const* d_in, const int* in_sizes, int n_in,
                              void* d_out, int out_size)
{
    const float* x     = (const float*)d_in[0];
    const float* Wq    = (const float*)d_in[1];
    const float* bq    = (const float*)d_in[2];
    const float* Wk    = (const float*)d_in[3];
    const float* bk    = (const float*)d_in[4];
    const float* Wv    = (const float*)d_in[5];
    const float* bv    = (const float*)d_in[6];
    const float* Wp    = (const float*)d_in[7];
    const float* bp    = (const float*)d_in[8];
    const float* gamma = (const float*)d_in[9];
    const float* temp  = (const float*)d_in[10];
    const float* lnw   = (const float*)d_in[11];
    const float* lnb   = (const float*)d_in[12];
    float* y = (float*)d_out;

    cudaFuncSetAttribute(qkv_gemm_kernel, cudaFuncAttributeMaxDynamicSharedMemorySize, SM_GEMM);
    cudaFuncSetAttribute(proj_gemm_kernel, cudaFuncAttributeMaxDynamicSharedMemorySize, SM_GEMM);

    prep_w_kernel<<<4096, 256>>>(Wq, Wk, Wv, Wp);
    prep_x_kernel<<<BB, 256>>>(x);
    qkv_gemm_kernel<<<dim3(24, 512), 256, SM_GEMM>>>(bq, bk, bv);
    attn_kernel<<<BB * NH, 128>>>(temp);
    proj_gemm_kernel<<<dim3(8, 512), 256, SM_GEMM>>>(bp, x, gamma);
    ln_kernel<<<BB, 512>>>(lnw, lnb, y);
}

// round 13
// speedup vs baseline: 4.1957x; 1.0232x over previous
#include <cuda_runtime.h>
#include <cuda_fp16.h>

#define NH   16
#define NN   64
#define CC   1024
#define BB   1024

typedef unsigned int u32;
typedef unsigned long long u64;
typedef unsigned short u16;

#define QKVSZ 67108864ull          // 1024*64*1024 elems

// Scratch (allocation-free rule: device globals)
__device__ u16    g_xf16[(size_t)BB * NN * CC];    // x transposed, fp16 [pixel][ch]
__device__ u16    g_wf16[(size_t)4096 * CC];       // Wq,Wk,Wv,Wp fused rows, fp16 RN
__device__ u16    g_qkv16[3ull * QKVSZ];           // q,k,v fp16 [pixel][ch]
__device__ u16    g_of16[(size_t)BB * NN * CC];    // attn out fp16 [pixel][ch]
__device__ float  g_res [(size_t)BB * CC * NN];    // residual r [b][c][n]
__device__ float2 g_partial[BB * 8];               // per-(b, ntile) partial (sum, sumsq)

// ---------------------------------------------------------------------------
// helpers
// ---------------------------------------------------------------------------
__device__ __forceinline__ u32 smem_u32(const void* p) {
    u32 a;
    asm("{ .reg .u64 t; cvta.to.shared.u64 t, %1; cvt.u32.u64 %0, t; }" : "=r"(a) : "l"(p));
    return a;
}
__device__ __forceinline__ void cpa16(u32 dst, const void* src) {
    asm volatile("cp.async.cg.shared.global [%0], [%1], 16;" :: "r"(dst), "l"(src));
}
#define CP_COMMIT() asm volatile("cp.async.commit_group;" ::: "memory")
#define CP_WAIT2()  asm volatile("cp.async.wait_group 2;" ::: "memory")
#define CP_WAIT0()  asm volatile("cp.async.wait_group 0;" ::: "memory")

__device__ __forceinline__ void ldsm_x4(u32* r, u32 addr) {
    asm volatile("ldmatrix.sync.aligned.m8n8.x4.shared.b16 {%0,%1,%2,%3}, [%4];"
        : "=r"(r[0]), "=r"(r[1]), "=r"(r[2]), "=r"(r[3]) : "r"(addr));
}
__device__ __forceinline__ void ldsm_x4t(u32* r, u32 addr) {
    asm volatile("ldmatrix.sync.aligned.m8n8.x4.trans.shared.b16 {%0,%1,%2,%3}, [%4];"
        : "=r"(r[0]), "=r"(r[1]), "=r"(r[2]), "=r"(r[3]) : "r"(addr));
}
__device__ __forceinline__ void mma16816(float* c, const u32* a, const u32* b) {
    asm volatile("mma.sync.aligned.m16n8k16.row.col.f32.f16.f16.f32 "
        "{%0,%1,%2,%3}, {%4,%5,%6,%7}, {%8,%9}, {%0,%1,%2,%3};"
        : "+f"(c[0]), "+f"(c[1]), "+f"(c[2]), "+f"(c[3])
        : "r"(a[0]), "r"(a[1]), "r"(a[2]), "r"(a[3]), "r"(b[0]), "r"(b[1]));
}
// GEMM smem swizzle: rows of 64B (4 chunks), chunk ^= (row>>1)&3
__device__ __forceinline__ u32 sw_addr(u32 base, int row, int kbyte) {
    int chunk = kbyte >> 4, in = kbyte & 15;
    return base + row * 64 + ((chunk ^ ((row >> 1) & 3)) << 4) + in;
}
// attn smem swizzle: rows of 128B (8 chunks), chunk ^= row&7
__device__ __forceinline__ u32 sw128(u32 base, int row, int kbyte) {
    int chunk = kbyte >> 4, in = kbyte & 15;
    return base + row * 128 + ((chunk ^ (row & 7)) << 4) + in;
}
__device__ __forceinline__ u16 f16r(float f) {
    __half h = __float2half_rn(f);
    return *reinterpret_cast<u16*>(&h);
}
__device__ __forceinline__ u32 packh2(float lo, float hi) {
    u32 r;
    asm("cvt.rn.f16x2.f32 %0, %1, %2;" : "=r"(r) : "f"(hi), "f"(lo));
    return r;
}

// GEMM smem: 4 stages x 16KB (A 8K | B 8K per stage)
#define STAGE_BYTES 16384
#define SM_GEMM     (4 * STAGE_BYTES)

// ---------------------------------------------------------------------------
// prep_w: 4 weight matrices -> fused fp16 [4096][1024]
// ---------------------------------------------------------------------------
__global__ void __launch_bounds__(256) prep_w_kernel(
    const float* __restrict__ Wq, const float* __restrict__ Wk,
    const float* __restrict__ Wv, const float* __restrict__ Wp)
{
    int blk = blockIdx.x;
    int mat = blk >> 10;
    const float* src = (mat == 0) ? Wq : (mat == 1) ? Wk : (mat == 2) ? Wv : Wp;
    size_t idx = ((size_t)(blk & 1023) * 256 + threadIdx.x) * 4;
    float4 v = *(const float4*)(src + idx);
    size_t o = (size_t)mat * 1048576 + idx;
    ushort4 h;
    h.x = f16r(v.x); h.y = f16r(v.y); h.z = f16r(v.z); h.w = f16r(v.w);
    *(ushort4*)(g_wf16 + o) = h;
}

// ---------------------------------------------------------------------------
// prep_x: x[b][c][n] -> transposed fp16 [pixel=b*64+n][c]
// ---------------------------------------------------------------------------
__global__ void __launch_bounds__(256) prep_x_kernel(const float* __restrict__ x) {
    __shared__ u16 hT[64][72];
    const int b = blockIdx.x, t = threadIdx.x;
    const float* xb = x + (size_t)b * 65536;
    for (int ct = 0; ct < 16; ++ct) {
        #pragma unroll
        for (int i = 0; i < 16; ++i) {
            int idx = i * 256 + t, c = idx >> 6, n = idx & 63;
            hT[n][c] = f16r(xb[(ct * 64 + c) * 64 + n]);
        }
        __syncthreads();
        #pragma unroll
        for (int i = 0; i < 2; ++i) {
            int idx = i * 256 + t;
            int n = idx >> 3, c8 = (idx & 7) << 3;
            size_t o = (size_t)(b * 64 + n) * 1024 + ct * 64 + c8;
            *(uint4*)(g_xf16 + o) = *(const uint4*)&hT[n][c8];
        }
        __syncthreads();
    }
}

// ---------------------------------------------------------------------------
// GEMM core: C[128 pix][128 ch] = A x B^T over K=1024, fp16 single-pass.
// ---------------------------------------------------------------------------
__device__ __forceinline__ void gemm_issue_stage(
    u32 sb, int s, int c, const char* gA, const char* gB)
{
    const int t = threadIdx.x;
    const char* gsrc[2] = {gA, gB};
    u32 stb = sb + s * STAGE_BYTES;
    #pragma unroll
    for (int arr = 0; arr < 2; ++arr) {
        #pragma unroll
        for (int r2 = 0; r2 < 2; ++r2) {
            int ch = t + r2 * 256;
            int row = ch >> 2, part = ch & 3;
            u32 dst = stb + arr * 8192 + row * 64 + ((part ^ ((row >> 1) & 3)) << 4);
            const char* src = gsrc[arr] + (size_t)row * 2048 + c * 64 + part * 16;
            cpa16(dst, src);
        }
    }
    CP_COMMIT();
}

__device__ __forceinline__ void gemm_compute_stage(u32 sb, int s, float acc[4][4][4],
                                                   int wm, int wn, int lane)
{
    u32 stb = sb + s * STAGE_BYTES;
    u32 pA = stb, pB = stb + 8192;
    const int arow = lane & 15;
    const int akb  = (lane >> 4) << 4;
    const int brow = (lane & 7) + ((lane & 16) >> 1);
    const int bkb  = (lane & 8) << 1;
    #pragma unroll
    for (int ks = 0; ks < 2; ++ks) {
        int kb = ks * 32;
        u32 A[4][4], B[4][2];
        #pragma unroll
        for (int i = 0; i < 4; ++i)
            ldsm_x4(A[i], sw_addr(pA, wm + i * 16 + arow, kb + akb));
        #pragma unroll
        for (int jp = 0; jp < 2; ++jp) {
            u32 r[4];
            ldsm_x4(r, sw_addr(pB, wn + jp * 16 + brow, kb + bkb));
            B[jp*2][0] = r[0]; B[jp*2][1] = r[1];
            B[jp*2+1][0] = r[2]; B[jp*2+1][1] = r[3];
        }
        #pragma unroll
        for (int i = 0; i < 4; ++i)
            #pragma unroll
            for (int j = 0; j < 4; ++j) mma16816(acc[i][j], A[i], B[j]);
    }
}

#define GEMM_MAINLOOP(gA, gB, acc)                                              \
    do {                                                                        \
        gemm_issue_stage(sb, 0, 0, gA, gB);                                     \
        gemm_issue_stage(sb, 1, 1, gA, gB);                                     \
        gemm_issue_stage(sb, 2, 2, gA, gB);                                     \
        for (int c = 0; c < 32; ++c) {                                          \
            CP_WAIT2();                                                         \
            __syncthreads();                                                    \
            gemm_compute_stage(sb, c & 3, acc, wm, wn, lane);                   \
            if (c + 3 < 32) gemm_issue_stage(sb, (c + 3) & 3, c + 3, gA, gB);   \
            else CP_COMMIT();                                                   \
        }                                                                       \
    } while (0)

// ---------------------------------------------------------------------------
// QKV GEMM: grid (24 ntiles, 512 pixel-groups). out fp16 q/k/v [pixel][ch]+bias
// ---------------------------------------------------------------------------
__global__ void __launch_bounds__(256, 2) qkv_gemm_kernel(
    const float* __restrict__ bq, const float* __restrict__ bk,
    const float* __restrict__ bv)
{
    extern __shared__ char smc[];
    const u32 sb = smem_u32(smc);
    const int t = threadIdx.x, wid = t >> 5, lane = t & 31;
    const int grp = lane >> 2, tig = lane & 3;
    const int wm = (wid & 1) << 6, wn = (wid >> 1) << 5;
    const int nt = blockIdx.x, mg = blockIdx.y;

    const char* gA = (const char*)g_xf16 + (size_t)mg * 128 * 2048;
    const char* gB = (const char*)g_wf16 + (size_t)nt * 128 * 2048;

    float acc[4][4][4];
    #pragma unroll
    for (int i = 0; i < 4; ++i)
        #pragma unroll
        for (int j = 0; j < 4; ++j) { acc[i][j][0]=0.f; acc[i][j][1]=0.f; acc[i][j][2]=0.f; acc[i][j][3]=0.f; }

    GEMM_MAINLOOP(gA, gB, acc);

    const int sel = nt >> 3;
    const int cbase = (nt & 7) * 128;
    const float* bias = (sel == 0) ? bq : (sel == 1) ? bk : bv;
    u16* out = g_qkv16 + (size_t)sel * QKVSZ;
    #pragma unroll
    for (int i = 0; i < 4; ++i) {
        int prow = mg * 128 + wm + i * 16 + grp;
        #pragma unroll
        for (int j = 0; j < 4; ++j) {
            int col = cbase + wn + j * 8 + tig * 2;
            float b0 = bias[col], b1 = bias[col + 1];
            *(u32*)(out + (size_t)prow * 1024 + col) = packh2(acc[i][j][0] + b0, acc[i][j][1] + b1);
            *(u32*)(out + (size_t)(prow + 8) * 1024 + col) = packh2(acc[i][j][2] + b0, acc[i][j][3] + b1);
        }
    }
}

// ---------------------------------------------------------------------------
// Proj GEMM: grid (8 ntiles, 512 pixel-groups). A = attn out fp16.
// Epilogue: smem transpose -> residual r = g*(out+bias) + (1-g)*x  [b][c][n],
// plus deterministic per-(batch, ntile) partial LN stats -> g_partial.
// ---------------------------------------------------------------------------
__global__ void __launch_bounds__(256, 2) proj_gemm_kernel(
    const float* __restrict__ bp, const float* __restrict__ x,
    const float* __restrict__ gamma_p)
{
    extern __shared__ char smc[];
    __shared__ float red1[8], red2[8];
    const u32 sb = smem_u32(smc);
    const int t = threadIdx.x, wid = t >> 5, lane = t & 31;
    const int grp = lane >> 2, tig = lane & 3;
    const int wm = (wid & 1) << 6, wn = (wid >> 1) << 5;
    const int nt = blockIdx.x, mg = blockIdx.y;

    const char* gA = (const char*)g_of16 + (size_t)mg * 128 * 2048;
    const char* gB = (const char*)g_wf16 + (size_t)(3072 + nt * 128) * 2048;

    float acc[4][4][4];
    #pragma unroll
    for (int i = 0; i < 4; ++i)
        #pragma unroll
        for (int j = 0; j < 4; ++j) { acc[i][j][0]=0.f; acc[i][j][1]=0.f; acc[i][j][2]=0.f; acc[i][j][3]=0.f; }

    GEMM_MAINLOOP(gA, gB, acc);

    const float g = gamma_p[0], og = 1.0f - g;
    __syncthreads();
    float* tile = (float*)smc;
    #pragma unroll
    for (int half = 0; half < 2; ++half) {
        if ((wm >> 6) == half) {
            #pragma unroll
            for (int i = 0; i < 4; ++i) {
                int pm = i * 16 + grp;
                #pragma unroll
                for (int j = 0; j < 4; ++j) {
                    int cc = wn + j * 8 + tig * 2;
                    *(float2*)&tile[pm * 130 + cc] = make_float2(acc[i][j][0], acc[i][j][1]);
                    *(float2*)&tile[(pm + 8) * 130 + cc] = make_float2(acc[i][j][2], acc[i][j][3]);
                }
            }
        }
        __syncthreads();
        int b = mg * 2 + half;
        float s1 = 0.f, s2 = 0.f;
        #pragma unroll
        for (int it = 0; it < 8; ++it) {
            int idx = it * 256 + t;
            int cc = idx >> 4, n4 = (idx & 15) << 2;
            int ch = nt * 128 + cc;
            float bi = bp[ch];
            size_t off = (size_t)b * 65536 + (size_t)ch * 64 + n4;
            float4 xv = *(const float4*)(x + off);
            float4 v;
            v.x = g * (tile[(n4 + 0) * 130 + cc] + bi) + og * xv.x;
            v.y = g * (tile[(n4 + 1) * 130 + cc] + bi) + og * xv.y;
            v.z = g * (tile[(n4 + 2) * 130 + cc] + bi) + og * xv.z;
            v.w = g * (tile[(n4 + 3) * 130 + cc] + bi) + og * xv.w;
            *(float4*)(g_res + off) = v;
            s1 += v.x + v.y + v.z + v.w;
            s2 += v.x * v.x + v.y * v.y + v.z * v.z + v.w * v.w;
        }
        // deterministic CTA reduction of partial stats
        #pragma unroll
        for (int o = 16; o; o >>= 1) {
            s1 += __shfl_xor_sync(0xffffffffu, s1, o);
            s2 += __shfl_xor_sync(0xffffffffu, s2, o);
        }
        if (lane == 0) { red1[wid] = s1; red2[wid] = s2; }
        __syncthreads();
        if (t == 0) {
            float a1 = 0.f, a2 = 0.f;
            #pragma unroll
            for (int w = 0; w < 8; ++w) { a1 += red1[w]; a2 += red2[w]; }
            g_partial[b * 8 + nt] = make_float2(a1, a2);
        }
        __syncthreads();
    }
}

// ---------------------------------------------------------------------------
// Attention (tensor-core): one CTA per (b,h), 128 threads / 4 warps.
// ---------------------------------------------------------------------------
__global__ void __launch_bounds__(128) attn_kernel(const float* __restrict__ temp_p)
{
    __shared__ __align__(128) u16 qs[4096];   // [n][d] fp16, sw128
    __shared__ __align__(128) u16 kk[4096];   // [m][d]
    __shared__ __align__(128) u16 vv[4096];   // [m][d]
    __shared__ float scq[64], sck[64];

    const int t = threadIdx.x, lane = t & 31, wid = t >> 5;
    const int b = blockIdx.x >> 4, h = blockIdx.x & 15;
    const u32 q0 = smem_u32(qs), k0 = smem_u32(kk), v0 = smem_u32(vv);

    // ---- load q/k/v tiles (64 x 64 fp16 each) via cp.async ----
    {
        u32 bases[3] = {q0, k0, v0};
        #pragma unroll
        for (int i = 0; i < 12; ++i) {
            int idx = t + i * 128;           // 0..1535
            int arr = idx >> 9, rem = idx & 511;
            int row = rem >> 3, ch = rem & 7;
            u32 dst = bases[arr] + row * 128 + ((ch ^ (row & 7)) << 4);
            const char* src = (const char*)(g_qkv16 + (size_t)arr * QKVSZ)
                            + ((size_t)(b * 64 + row) * 1024 + h * 64) * 2 + ch * 16;
            cpa16(dst, src);
        }
        CP_COMMIT();
        CP_WAIT0();
        __syncthreads();
    }

    // ---- per-d column norms over the spatial axis (fp32) ----
    {
        float tinv = 1.0f / (temp_p[0] + 1e-6f);
        int d = t & 63;
        const __half* base = (const __half*)((t < 64) ? qs : kk);
        int cb = d >> 3, io = (d * 2) & 15;
        float s = 0.f;
        #pragma unroll 8
        for (int n = 0; n < 64; ++n) {
            int bi = (n * 128 + ((cb ^ (n & 7)) << 4) + io) >> 1;
            float v = __half2float(base[bi]);
            s += v * v;
        }
        float inv = 1.0f / fmaxf(sqrtf(s), 1e-12f);
        if (t < 64) scq[d] = inv; else sck[d] = inv;
        __syncthreads();
        if (t < 64) scq[d] = scq[d] * sck[d] * tinv;
        __syncthreads();
    }

    // ---- fold combined scale into q (fp16, in place) ----
    {
        u32* qw = (u32*)qs;
        #pragma unroll
        for (int i = 0; i < 16; ++i) {
            int idx = t + i * 128;
            int row = idx >> 5, pos = idx & 31;
            int ui = (row * 128 + (((pos >> 2) ^ (row & 7)) << 4) + (pos & 3) * 4) >> 2;
            float2 f = __half22float2(*(__half2*)&qw[ui]);
            f.x *= scq[pos * 2];
            f.y *= scq[pos * 2 + 1];
            qw[ui] = packh2(f.x, f.y);
        }
        __syncthreads();
    }

    // ---- S = qhat^T khat ----
    const int wm = wid << 4;
    float sa[8][4];
    #pragma unroll
    for (int j = 0; j < 8; ++j) { sa[j][0]=0.f; sa[j][1]=0.f; sa[j][2]=0.f; sa[j][3]=0.f; }
    {
        const int arow = lane & 15, akb = (lane >> 4) << 4;
        const int br = (lane & 7) + ((lane & 16) >> 1), bkb = (lane & 8) << 1;
        #pragma unroll
        for (int ks = 0; ks < 4; ++ks) {
            int kb = ks * 32;
            u32 A[4];
            ldsm_x4(A, sw128(q0, wm + arow, kb + akb));
            #pragma unroll
            for (int jp = 0; jp < 4; ++jp) {
                u32 r[4];
                ldsm_x4(r, sw128(k0, jp * 16 + br, kb + bkb));
                mma16816(sa[jp * 2], A, r);
                mma16816(sa[jp * 2 + 1], A, r + 2);
            }
        }
    }

    // ---- softmax + repack P into A-fragments ----
    u32 pa[4][4];
    {
        float mx0 = -1e30f, mx1 = -1e30f;
        #pragma unroll
        for (int j = 0; j < 8; ++j) {
            mx0 = fmaxf(mx0, fmaxf(sa[j][0], sa[j][1]));
            mx1 = fmaxf(mx1, fmaxf(sa[j][2], sa[j][3]));
        }
        #pragma unroll
        for (int o = 1; o <= 2; o <<= 1) {
            mx0 = fmaxf(mx0, __shfl_xor_sync(0xffffffffu, mx0, o));
            mx1 = fmaxf(mx1, __shfl_xor_sync(0xffffffffu, mx1, o));
        }
        float sum0 = 0.f, sum1 = 0.f;
        #pragma unroll
        for (int j = 0; j < 8; ++j) {
            sa[j][0] = __expf(sa[j][0] - mx0); sum0 += sa[j][0];
            sa[j][1] = __expf(sa[j][1] - mx0); sum0 += sa[j][1];
            sa[j][2] = __expf(sa[j][2] - mx1); sum1 += sa[j][2];
            sa[j][3] = __expf(sa[j][3] - mx1); sum1 += sa[j][3];
        }
        #pragma unroll
        for (int o = 1; o <= 2; o <<= 1) {
            sum0 += __shfl_xor_sync(0xffffffffu, sum0, o);
            sum1 += __shfl_xor_sync(0xffffffffu, sum1, o);
        }
        float r0 = 1.0f / sum0, r1 = 1.0f / sum1;
        #pragma unroll
        for (int ks = 0; ks < 4; ++ks) {
            pa[ks][0] = packh2(sa[2*ks][0] * r0, sa[2*ks][1] * r0);
            pa[ks][1] = packh2(sa[2*ks][2] * r1, sa[2*ks][3] * r1);
            pa[ks][2] = packh2(sa[2*ks+1][0] * r0, sa[2*ks+1][1] * r0);
            pa[ks][3] = packh2(sa[2*ks+1][2] * r1, sa[2*ks+1][3] * r1);
        }
    }

    // ---- O = P V ----
    float oa[8][4];
    #pragma unroll
    for (int j = 0; j < 8; ++j) { oa[j][0]=0.f; oa[j][1]=0.f; oa[j][2]=0.f; oa[j][3]=0.f; }
    {
        const int vrow = lane & 15, vdb = (lane >> 4) << 4;
        #pragma unroll
        for (int ks = 0; ks < 4; ++ks) {
            #pragma unroll
            for (int Dp = 0; Dp < 4; ++Dp) {
                u32 r[4];
                ldsm_x4t(r, sw128(v0, ks * 16 + vrow, Dp * 32 + vdb));
                mma16816(oa[Dp * 2], pa[ks], r);
                mma16816(oa[Dp * 2 + 1], pa[ks], r + 2);
            }
        }
    }
    __syncthreads();

    // ---- bounce O through smem, coalesced fp16 writes ----
    {
        u32* bn = (u32*)qs;
        int grp = lane >> 2, tg = lane & 3;
        #pragma unroll
        for (int jd = 0; jd < 8; ++jd) {
            int c = jd * 4 + tg;
            bn[(wm + grp) * 33 + c]     = packh2(oa[jd][0], oa[jd][1]);
            bn[(wm + grp + 8) * 33 + c] = packh2(oa[jd][2], oa[jd][3]);
        }
        __syncthreads();
        u16* outg = g_of16 + (size_t)(b * 64) * 1024 + h * 64;
        #pragma unroll
        for (int i = 0; i < 16; ++i) {
            int idx = t + i * 128;
            int row = idx >> 5, c = idx & 31;
            *(u32*)(outg + (size_t)row * 1024 + c * 2) = bn[row * 33 + c];
        }
    }
}

// ---------------------------------------------------------------------------
// LN apply: one CTA per batch, 512 threads. Stats from g_partial (8 per batch),
// single pass over g_res.  y = (r - mu) * rstd * ln_w + ln_b
// ---------------------------------------------------------------------------
__global__ void __launch_bounds__(512) ln_kernel(
    const float* __restrict__ lnw, const float* __restrict__ lnb,
    float* __restrict__ y)
{
    __shared__ float sh[2];
    const int b = blockIdx.x, t = threadIdx.x;
    if (t == 0) {
        float s1 = 0.f, s2 = 0.f;
        #pragma unroll
        for (int w = 0; w < 8; ++w) {
            float2 p = g_partial[b * 8 + w];
            s1 += p.x; s2 += p.y;
        }
        float mu  = s1 * (1.0f / 65536.0f);
        float var = s2 * (1.0f / 65536.0f) - mu * mu;
        sh[0] = mu;
        sh[1] = rsqrtf(var + 1e-5f);
    }
    __syncthreads();
    const float mu = sh[0], rs = sh[1];
    const float* rb = g_res + (size_t)b * 65536;
    float* yb = y + (size_t)b * 65536;
    #pragma unroll 4
    for (int i = t * 4; i < 65536; i += 2048) {
        float4 p = *(const float4*)(rb + i);
        float4 w = *(const float4*)(lnw + i);
        float4 lb = *(const float4*)(lnb + i);
        float4 o;
        o.x = (p.x - mu) * rs * w.x + lb.x;
        o.y = (p.y - mu) * rs * w.y + lb.y;
        o.z = (p.z - mu) * rs * w.z + lb.z;
        o.w = (p.w - mu) * rs * w.w + lb.w;
        *(float4*)(yb + i) = o;
    }
}

// ---------------------------------------------------------------------------
extern "C" void kernel_launch(void* const* d_in, const int* in_sizes, int n_in,
                              void* d_out, int out_size)
{
    const float* x     = (const float*)d_in[0];
    const float* Wq    = (const float*)d_in[1];
    const float* bq    = (const float*)d_in[2];
    const float* Wk    = (const float*)d_in[3];
    const float* bk    = (const float*)d_in[4];
    const float* Wv    = (const float*)d_in[5];
    const float* bv    = (const float*)d_in[6];
    const float* Wp    = (const float*)d_in[7];
    const float* bp    = (const float*)d_in[8];
    const float* gamma = (const float*)d_in[9];
    const float* temp  = (const float*)d_in[10];
    const float* lnw   = (const float*)d_in[11];
    const float* lnb   = (const float*)d_in[12];
    float* y = (float*)d_out;

    cudaFuncSetAttribute(qkv_gemm_kernel, cudaFuncAttributeMaxDynamicSharedMemorySize, SM_GEMM);
    cudaFuncSetAttribute(proj_gemm_kernel, cudaFuncAttributeMaxDynamicSharedMemorySize, SM_GEMM);

    prep_w_kernel<<<4096, 256>>>(Wq, Wk, Wv, Wp);
    prep_x_kernel<<<BB, 256>>>(x);
    qkv_gemm_kernel<<<dim3(24, 512), 256, SM_GEMM>>>(bq, bk, bv);
    attn_kernel<<<BB * NH, 128>>>(temp);
    proj_gemm_kernel<<<dim3(8, 512), 256, SM_GEMM>>>(bp, x, gamma);
    ln_kernel<<<BB, 512>>>(lnw, lnb, y);
}

// round 14
// speedup vs baseline: 4.1994x; 1.0009x over previous
#include <cuda_runtime.h>
#include <cuda_fp16.h>

#define NH   16
#define NN   64
#define CC   1024
#define BB   1024

typedef unsigned int u32;
typedef unsigned long long u64;
typedef unsigned short u16;

#define QKVSZ 67108864ull          // 1024*64*1024 elems

// Scratch (allocation-free rule: device globals)
__device__ u16    g_xf16[(size_t)BB * NN * CC];    // x transposed, fp16 [pixel][ch]
__device__ u16    g_wf16[(size_t)4096 * CC];       // Wq,Wk,Wv,Wp fused rows, fp16 RN
__device__ u16    g_qkv16[3ull * QKVSZ];           // q,k,v fp16 [pixel][ch]
__device__ u16    g_of16[(size_t)BB * NN * CC];    // attn out fp16 [pixel][ch]
__device__ u16    g_res16[(size_t)BB * CC * NN];   // residual r fp16 [b][c][n]
__device__ float2 g_partial[BB * 8];               // per-(b, ntile) partial (sum, sumsq)

// ---------------------------------------------------------------------------
// helpers
// ---------------------------------------------------------------------------
__device__ __forceinline__ u32 smem_u32(const void* p) {
    u32 a;
    asm("{ .reg .u64 t; cvta.to.shared.u64 t, %1; cvt.u32.u64 %0, t; }" : "=r"(a) : "l"(p));
    return a;
}
__device__ __forceinline__ void cpa16(u32 dst, const void* src) {
    asm volatile("cp.async.cg.shared.global [%0], [%1], 16;" :: "r"(dst), "l"(src));
}
#define CP_COMMIT() asm volatile("cp.async.commit_group;" ::: "memory")
#define CP_WAIT2()  asm volatile("cp.async.wait_group 2;" ::: "memory")
#define CP_WAIT0()  asm volatile("cp.async.wait_group 0;" ::: "memory")

__device__ __forceinline__ void ldsm_x4(u32* r, u32 addr) {
    asm volatile("ldmatrix.sync.aligned.m8n8.x4.shared.b16 {%0,%1,%2,%3}, [%4];"
        : "=r"(r[0]), "=r"(r[1]), "=r"(r[2]), "=r"(r[3]) : "r"(addr));
}
__device__ __forceinline__ void ldsm_x4t(u32* r, u32 addr) {
    asm volatile("ldmatrix.sync.aligned.m8n8.x4.trans.shared.b16 {%0,%1,%2,%3}, [%4];"
        : "=r"(r[0]), "=r"(r[1]), "=r"(r[2]), "=r"(r[3]) : "r"(addr));
}
__device__ __forceinline__ void mma16816(float* c, const u32* a, const u32* b) {
    asm volatile("mma.sync.aligned.m16n8k16.row.col.f32.f16.f16.f32 "
        "{%0,%1,%2,%3}, {%4,%5,%6,%7}, {%8,%9}, {%0,%1,%2,%3};"
        : "+f"(c[0]), "+f"(c[1]), "+f"(c[2]), "+f"(c[3])
        : "r"(a[0]), "r"(a[1]), "r"(a[2]), "r"(a[3]), "r"(b[0]), "r"(b[1]));
}
// GEMM smem swizzle: rows of 64B (4 chunks), chunk ^= (row>>1)&3
__device__ __forceinline__ u32 sw_addr(u32 base, int row, int kbyte) {
    int chunk = kbyte >> 4, in = kbyte & 15;
    return base + row * 64 + ((chunk ^ ((row >> 1) & 3)) << 4) + in;
}
// attn smem swizzle: rows of 128B (8 chunks), chunk ^= row&7
__device__ __forceinline__ u32 sw128(u32 base, int row, int kbyte) {
    int chunk = kbyte >> 4, in = kbyte & 15;
    return base + row * 128 + ((chunk ^ (row & 7)) << 4) + in;
}
__device__ __forceinline__ u16 f16r(float f) {
    __half h = __float2half_rn(f);
    return *reinterpret_cast<u16*>(&h);
}
__device__ __forceinline__ u32 packh2(float lo, float hi) {
    u32 r;
    asm("cvt.rn.f16x2.f32 %0, %1, %2;" : "=r"(r) : "f"(hi), "f"(lo));
    return r;
}

// GEMM smem: 4 stages x 16KB (A 8K | B 8K per stage)
#define STAGE_BYTES 16384
#define SM_GEMM     (4 * STAGE_BYTES)

// ---------------------------------------------------------------------------
// prep_w: 4 weight matrices -> fused fp16 [4096][1024]
// ---------------------------------------------------------------------------
__global__ void __launch_bounds__(256) prep_w_kernel(
    const float* __restrict__ Wq, const float* __restrict__ Wk,
    const float* __restrict__ Wv, const float* __restrict__ Wp)
{
    int blk = blockIdx.x;
    int mat = blk >> 10;
    const float* src = (mat == 0) ? Wq : (mat == 1) ? Wk : (mat == 2) ? Wv : Wp;
    size_t idx = ((size_t)(blk & 1023) * 256 + threadIdx.x) * 4;
    float4 v = *(const float4*)(src + idx);
    size_t o = (size_t)mat * 1048576 + idx;
    ushort4 h;
    h.x = f16r(v.x); h.y = f16r(v.y); h.z = f16r(v.z); h.w = f16r(v.w);
    *(ushort4*)(g_wf16 + o) = h;
}

// ---------------------------------------------------------------------------
// prep_x: x[b][c][n] -> transposed fp16 [pixel=b*64+n][c]
// ---------------------------------------------------------------------------
__global__ void __launch_bounds__(256) prep_x_kernel(const float* __restrict__ x) {
    __shared__ u16 hT[64][72];
    const int b = blockIdx.x, t = threadIdx.x;
    const float* xb = x + (size_t)b * 65536;
    for (int ct = 0; ct < 16; ++ct) {
        #pragma unroll
        for (int i = 0; i < 16; ++i) {
            int idx = i * 256 + t, c = idx >> 6, n = idx & 63;
            hT[n][c] = f16r(xb[(ct * 64 + c) * 64 + n]);
        }
        __syncthreads();
        #pragma unroll
        for (int i = 0; i < 2; ++i) {
            int idx = i * 256 + t;
            int n = idx >> 3, c8 = (idx & 7) << 3;
            size_t o = (size_t)(b * 64 + n) * 1024 + ct * 64 + c8;
            *(uint4*)(g_xf16 + o) = *(const uint4*)&hT[n][c8];
        }
        __syncthreads();
    }
}

// ---------------------------------------------------------------------------
// GEMM core: C[128 pix][128 ch] = A x B^T over K=1024, fp16 single-pass.
// ---------------------------------------------------------------------------
__device__ __forceinline__ void gemm_issue_stage(
    u32 sb, int s, int c, const char* gA, const char* gB)
{
    const int t = threadIdx.x;
    const char* gsrc[2] = {gA, gB};
    u32 stb = sb + s * STAGE_BYTES;
    #pragma unroll
    for (int arr = 0; arr < 2; ++arr) {
        #pragma unroll
        for (int r2 = 0; r2 < 2; ++r2) {
            int ch = t + r2 * 256;
            int row = ch >> 2, part = ch & 3;
            u32 dst = stb + arr * 8192 + row * 64 + ((part ^ ((row >> 1) & 3)) << 4);
            const char* src = gsrc[arr] + (size_t)row * 2048 + c * 64 + part * 16;
            cpa16(dst, src);
        }
    }
    CP_COMMIT();
}

__device__ __forceinline__ void gemm_compute_stage(u32 sb, int s, float acc[4][4][4],
                                                   int wm, int wn, int lane)
{
    u32 stb = sb + s * STAGE_BYTES;
    u32 pA = stb, pB = stb + 8192;
    const int arow = lane & 15;
    const int akb  = (lane >> 4) << 4;
    const int brow = (lane & 7) + ((lane & 16) >> 1);
    const int bkb  = (lane & 8) << 1;
    #pragma unroll
    for (int ks = 0; ks < 2; ++ks) {
        int kb = ks * 32;
        u32 A[4][4], B[4][2];
        #pragma unroll
        for (int i = 0; i < 4; ++i)
            ldsm_x4(A[i], sw_addr(pA, wm + i * 16 + arow, kb + akb));
        #pragma unroll
        for (int jp = 0; jp < 2; ++jp) {
            u32 r[4];
            ldsm_x4(r, sw_addr(pB, wn + jp * 16 + brow, kb + bkb));
            B[jp*2][0] = r[0]; B[jp*2][1] = r[1];
            B[jp*2+1][0] = r[2]; B[jp*2+1][1] = r[3];
        }
        #pragma unroll
        for (int i = 0; i < 4; ++i)
            #pragma unroll
            for (int j = 0; j < 4; ++j) mma16816(acc[i][j], A[i], B[j]);
    }
}

#define GEMM_MAINLOOP(gA, gB, acc)                                              \
    do {                                                                        \
        gemm_issue_stage(sb, 0, 0, gA, gB);                                     \
        gemm_issue_stage(sb, 1, 1, gA, gB);                                     \
        gemm_issue_stage(sb, 2, 2, gA, gB);                                     \
        for (int c = 0; c < 32; ++c) {                                          \
            CP_WAIT2();                                                         \
            __syncthreads();                                                    \
            gemm_compute_stage(sb, c & 3, acc, wm, wn, lane);                   \
            if (c + 3 < 32) gemm_issue_stage(sb, (c + 3) & 3, c + 3, gA, gB);   \
            else CP_COMMIT();                                                   \
        }                                                                       \
    } while (0)

// ---------------------------------------------------------------------------
// QKV GEMM: grid (24 ntiles, 512 pixel-groups). out fp16 q/k/v [pixel][ch]+bias
// ---------------------------------------------------------------------------
__global__ void __launch_bounds__(256, 2) qkv_gemm_kernel(
    const float* __restrict__ bq, const float* __restrict__ bk,
    const float* __restrict__ bv)
{
    extern __shared__ char smc[];
    const u32 sb = smem_u32(smc);
    const int t = threadIdx.x, wid = t >> 5, lane = t & 31;
    const int grp = lane >> 2, tig = lane & 3;
    const int wm = (wid & 1) << 6, wn = (wid >> 1) << 5;
    const int nt = blockIdx.x, mg = blockIdx.y;

    const char* gA = (const char*)g_xf16 + (size_t)mg * 128 * 2048;
    const char* gB = (const char*)g_wf16 + (size_t)nt * 128 * 2048;

    float acc[4][4][4];
    #pragma unroll
    for (int i = 0; i < 4; ++i)
        #pragma unroll
        for (int j = 0; j < 4; ++j) { acc[i][j][0]=0.f; acc[i][j][1]=0.f; acc[i][j][2]=0.f; acc[i][j][3]=0.f; }

    GEMM_MAINLOOP(gA, gB, acc);

    const int sel = nt >> 3;
    const int cbase = (nt & 7) * 128;
    const float* bias = (sel == 0) ? bq : (sel == 1) ? bk : bv;
    u16* out = g_qkv16 + (size_t)sel * QKVSZ;
    #pragma unroll
    for (int i = 0; i < 4; ++i) {
        int prow = mg * 128 + wm + i * 16 + grp;
        #pragma unroll
        for (int j = 0; j < 4; ++j) {
            int col = cbase + wn + j * 8 + tig * 2;
            float b0 = bias[col], b1 = bias[col + 1];
            *(u32*)(out + (size_t)prow * 1024 + col) = packh2(acc[i][j][0] + b0, acc[i][j][1] + b1);
            *(u32*)(out + (size_t)(prow + 8) * 1024 + col) = packh2(acc[i][j][2] + b0, acc[i][j][3] + b1);
        }
    }
}

// ---------------------------------------------------------------------------
// Proj GEMM: grid (8 ntiles, 512 pixel-groups). A = attn out fp16.
// Epilogue: smem transpose -> residual r = g*(out+bias) + (1-g)*x -> fp16
// [b][c][n], plus deterministic per-(batch, ntile) LN partials (fp32, pre-round).
// ---------------------------------------------------------------------------
__global__ void __launch_bounds__(256, 2) proj_gemm_kernel(
    const float* __restrict__ bp, const float* __restrict__ x,
    const float* __restrict__ gamma_p)
{
    extern __shared__ char smc[];
    __shared__ float red1[8], red2[8];
    const u32 sb = smem_u32(smc);
    const int t = threadIdx.x, wid = t >> 5, lane = t & 31;
    const int grp = lane >> 2, tig = lane & 3;
    const int wm = (wid & 1) << 6, wn = (wid >> 1) << 5;
    const int nt = blockIdx.x, mg = blockIdx.y;

    const char* gA = (const char*)g_of16 + (size_t)mg * 128 * 2048;
    const char* gB = (const char*)g_wf16 + (size_t)(3072 + nt * 128) * 2048;

    float acc[4][4][4];
    #pragma unroll
    for (int i = 0; i < 4; ++i)
        #pragma unroll
        for (int j = 0; j < 4; ++j) { acc[i][j][0]=0.f; acc[i][j][1]=0.f; acc[i][j][2]=0.f; acc[i][j][3]=0.f; }

    GEMM_MAINLOOP(gA, gB, acc);

    const float g = gamma_p[0], og = 1.0f - g;
    __syncthreads();
    float* tile = (float*)smc;
    #pragma unroll
    for (int half = 0; half < 2; ++half) {
        if ((wm >> 6) == half) {
            #pragma unroll
            for (int i = 0; i < 4; ++i) {
                int pm = i * 16 + grp;
                #pragma unroll
                for (int j = 0; j < 4; ++j) {
                    int cc = wn + j * 8 + tig * 2;
                    *(float2*)&tile[pm * 130 + cc] = make_float2(acc[i][j][0], acc[i][j][1]);
                    *(float2*)&tile[(pm + 8) * 130 + cc] = make_float2(acc[i][j][2], acc[i][j][3]);
                }
            }
        }
        __syncthreads();
        int b = mg * 2 + half;
        float s1 = 0.f, s2 = 0.f;
        #pragma unroll
        for (int it = 0; it < 8; ++it) {
            int idx = it * 256 + t;
            int cc = idx >> 4, n4 = (idx & 15) << 2;
            int ch = nt * 128 + cc;
            float bi = bp[ch];
            size_t off = (size_t)b * 65536 + (size_t)ch * 64 + n4;
            float4 xv = *(const float4*)(x + off);
            float4 v;
            v.x = g * (tile[(n4 + 0) * 130 + cc] + bi) + og * xv.x;
            v.y = g * (tile[(n4 + 1) * 130 + cc] + bi) + og * xv.y;
            v.z = g * (tile[(n4 + 2) * 130 + cc] + bi) + og * xv.z;
            v.w = g * (tile[(n4 + 3) * 130 + cc] + bi) + og * xv.w;
            ushort4 hv;
            hv.x = f16r(v.x); hv.y = f16r(v.y); hv.z = f16r(v.z); hv.w = f16r(v.w);
            *(ushort4*)(g_res16 + off) = hv;
            s1 += v.x + v.y + v.z + v.w;
            s2 += v.x * v.x + v.y * v.y + v.z * v.z + v.w * v.w;
        }
        // deterministic CTA reduction of partial stats
        #pragma unroll
        for (int o = 16; o; o >>= 1) {
            s1 += __shfl_xor_sync(0xffffffffu, s1, o);
            s2 += __shfl_xor_sync(0xffffffffu, s2, o);
        }
        if (lane == 0) { red1[wid] = s1; red2[wid] = s2; }
        __syncthreads();
        if (t == 0) {
            float a1 = 0.f, a2 = 0.f;
            #pragma unroll
            for (int w = 0; w < 8; ++w) { a1 += red1[w]; a2 += red2[w]; }
            g_partial[b * 8 + nt] = make_float2(a1, a2);
        }
        __syncthreads();
    }
}

// ---------------------------------------------------------------------------
// Attention (tensor-core): one CTA per (b,h), 128 threads / 4 warps.
// ---------------------------------------------------------------------------
__global__ void __launch_bounds__(128) attn_kernel(const float* __restrict__ temp_p)
{
    __shared__ __align__(128) u16 qs[4096];   // [n][d] fp16, sw128
    __shared__ __align__(128) u16 kk[4096];   // [m][d]
    __shared__ __align__(128) u16 vv[4096];   // [m][d]
    __shared__ float scq[64], sck[64];

    const int t = threadIdx.x, lane = t & 31, wid = t >> 5;
    const int b = blockIdx.x >> 4, h = blockIdx.x & 15;
    const u32 q0 = smem_u32(qs), k0 = smem_u32(kk), v0 = smem_u32(vv);

    // ---- load q/k/v tiles (64 x 64 fp16 each) via cp.async ----
    {
        u32 bases[3] = {q0, k0, v0};
        #pragma unroll
        for (int i = 0; i < 12; ++i) {
            int idx = t + i * 128;           // 0..1535
            int arr = idx >> 9, rem = idx & 511;
            int row = rem >> 3, ch = rem & 7;
            u32 dst = bases[arr] + row * 128 + ((ch ^ (row & 7)) << 4);
            const char* src = (const char*)(g_qkv16 + (size_t)arr * QKVSZ)
                            + ((size_t)(b * 64 + row) * 1024 + h * 64) * 2 + ch * 16;
            cpa16(dst, src);
        }
        CP_COMMIT();
        CP_WAIT0();
        __syncthreads();
    }

    // ---- per-d column sums of squares (vectorized: u32 loads, d-pairs) ----
    // warps 0-1: q, warps 2-3: k. Each thread: d-pair dp, half of n rows.
    {
        float tinv = 1.0f / (temp_p[0] + 1e-6f);
        const u16* barr = (wid < 2) ? qs : kk;
        const int dp = ((wid & 1) << 4) + (lane & 15);   // 0..31
        const int half = lane >> 4;                       // 0: rows 0-31, 1: 32-63
        const int cb = dp >> 2;
        const int io = (dp * 4) & 15;
        float sx = 0.f, sy = 0.f;
        #pragma unroll 8
        for (int i = 0; i < 32; ++i) {
            int row = half * 32 + i;
            u32 off = (u32)(row * 128 + ((cb ^ (row & 7)) << 4) + io) >> 1;
            u32 v = *(const u32*)(barr + off);
            float2 f = __half22float2(*(__half2*)&v);
            sx += f.x * f.x;
            sy += f.y * f.y;
        }
        sx += __shfl_xor_sync(0xffffffffu, sx, 16);
        sy += __shfl_xor_sync(0xffffffffu, sy, 16);
        if (lane < 16) {
            float2 inv;
            inv.x = 1.0f / fmaxf(sqrtf(sx), 1e-12f);
            inv.y = 1.0f / fmaxf(sqrtf(sy), 1e-12f);
            if (wid < 2) *(float2*)&scq[dp * 2] = inv;
            else         *(float2*)&sck[dp * 2] = inv;
        }
        __syncthreads();
        if (t < 64) scq[t] = scq[t] * sck[t] * tinv;
        __syncthreads();
    }

    // ---- fold combined scale into q (fp16, in place) ----
    {
        u32* qw = (u32*)qs;
        #pragma unroll
        for (int i = 0; i < 16; ++i) {
            int idx = t + i * 128;
            int row = idx >> 5, pos = idx & 31;
            int ui = (row * 128 + (((pos >> 2) ^ (row & 7)) << 4) + (pos & 3) * 4) >> 2;
            float2 f = __half22float2(*(__half2*)&qw[ui]);
            f.x *= scq[pos * 2];
            f.y *= scq[pos * 2 + 1];
            qw[ui] = packh2(f.x, f.y);
        }
        __syncthreads();
    }

    // ---- S = qhat^T khat ----
    const int wm = wid << 4;
    float sa[8][4];
    #pragma unroll
    for (int j = 0; j < 8; ++j) { sa[j][0]=0.f; sa[j][1]=0.f; sa[j][2]=0.f; sa[j][3]=0.f; }
    {
        const int arow = lane & 15, akb = (lane >> 4) << 4;
        const int br = (lane & 7) + ((lane & 16) >> 1), bkb = (lane & 8) << 1;
        #pragma unroll
        for (int ks = 0; ks < 4; ++ks) {
            int kb = ks * 32;
            u32 A[4];
            ldsm_x4(A, sw128(q0, wm + arow, kb + akb));
            #pragma unroll
            for (int jp = 0; jp < 4; ++jp) {
                u32 r[4];
                ldsm_x4(r, sw128(k0, jp * 16 + br, kb + bkb));
                mma16816(sa[jp * 2], A, r);
                mma16816(sa[jp * 2 + 1], A, r + 2);
            }
        }
    }

    // ---- softmax + repack P into A-fragments ----
    u32 pa[4][4];
    {
        float mx0 = -1e30f, mx1 = -1e30f;
        #pragma unroll
        for (int j = 0; j < 8; ++j) {
            mx0 = fmaxf(mx0, fmaxf(sa[j][0], sa[j][1]));
            mx1 = fmaxf(mx1, fmaxf(sa[j][2], sa[j][3]));
        }
        #pragma unroll
        for (int o = 1; o <= 2; o <<= 1) {
            mx0 = fmaxf(mx0, __shfl_xor_sync(0xffffffffu, mx0, o));
            mx1 = fmaxf(mx1, __shfl_xor_sync(0xffffffffu, mx1, o));
        }
        float sum0 = 0.f, sum1 = 0.f;
        #pragma unroll
        for (int j = 0; j < 8; ++j) {
            sa[j][0] = __expf(sa[j][0] - mx0); sum0 += sa[j][0];
            sa[j][1] = __expf(sa[j][1] - mx0); sum0 += sa[j][1];
            sa[j][2] = __expf(sa[j][2] - mx1); sum1 += sa[j][2];
            sa[j][3] = __expf(sa[j][3] - mx1); sum1 += sa[j][3];
        }
        #pragma unroll
        for (int o = 1; o <= 2; o <<= 1) {
            sum0 += __shfl_xor_sync(0xffffffffu, sum0, o);
            sum1 += __shfl_xor_sync(0xffffffffu, sum1, o);
        }
        float r0 = 1.0f / sum0, r1 = 1.0f / sum1;
        #pragma unroll
        for (int ks = 0; ks < 4; ++ks) {
            pa[ks][0] = packh2(sa[2*ks][0] * r0, sa[2*ks][1] * r0);
            pa[ks][1] = packh2(sa[2*ks][2] * r1, sa[2*ks][3] * r1);
            pa[ks][2] = packh2(sa[2*ks+1][0] * r0, sa[2*ks+1][1] * r0);
            pa[ks][3] = packh2(sa[2*ks+1][2] * r1, sa[2*ks+1][3] * r1);
        }
    }

    // ---- O = P V ----
    float oa[8][4];
    #pragma unroll
    for (int j = 0; j < 8; ++j) { oa[j][0]=0.f; oa[j][1]=0.f; oa[j][2]=0.f; oa[j][3]=0.f; }
    {
        const int vrow = lane & 15, vdb = (lane >> 4) << 4;
        #pragma unroll
        for (int ks = 0; ks < 4; ++ks) {
            #pragma unroll
            for (int Dp = 0; Dp < 4; ++Dp) {
                u32 r[4];
                ldsm_x4t(r, sw128(v0, ks * 16 + vrow, Dp * 32 + vdb));
                mma16816(oa[Dp * 2], pa[ks], r);
                mma16816(oa[Dp * 2 + 1], pa[ks], r + 2);
            }
        }
    }
    __syncthreads();

    // ---- bounce O through smem, coalesced fp16 writes ----
    {
        u32* bn = (u32*)qs;
        int grp = lane >> 2, tg = lane & 3;
        #pragma unroll
        for (int jd = 0; jd < 8; ++jd) {
            int c = jd * 4 + tg;
            bn[(wm + grp) * 33 + c]     = packh2(oa[jd][0], oa[jd][1]);
            bn[(wm + grp + 8) * 33 + c] = packh2(oa[jd][2], oa[jd][3]);
        }
        __syncthreads();
        u16* outg = g_of16 + (size_t)(b * 64) * 1024 + h * 64;
        #pragma unroll
        for (int i = 0; i < 16; ++i) {
            int idx = t + i * 128;
            int row = idx >> 5, c = idx & 31;
            *(u32*)(outg + (size_t)row * 1024 + c * 2) = bn[row * 33 + c];
        }
    }
}

// ---------------------------------------------------------------------------
// LN apply: one CTA per batch, 512 threads. Stats from g_partial (8 per batch),
// single pass over fp16 residual.  y = (r - mu) * rstd * ln_w + ln_b
// ---------------------------------------------------------------------------
__global__ void __launch_bounds__(512) ln_kernel(
    const float* __restrict__ lnw, const float* __restrict__ lnb,
    float* __restrict__ y)
{
    __shared__ float sh[2];
    const int b = blockIdx.x, t = threadIdx.x;
    if (t == 0) {
        float s1 = 0.f, s2 = 0.f;
        #pragma unroll
        for (int w = 0; w < 8; ++w) {
            float2 p = g_partial[b * 8 + w];
            s1 += p.x; s2 += p.y;
        }
        float mu  = s1 * (1.0f / 65536.0f);
        float var = s2 * (1.0f / 65536.0f) - mu * mu;
        sh[0] = mu;
        sh[1] = rsqrtf(var + 1e-5f);
    }
    __syncthreads();
    const float mu = sh[0], rs = sh[1];
    const u16* rb = g_res16 + (size_t)b * 65536;
    float* yb = y + (size_t)b * 65536;
    #pragma unroll 2
    for (int i = t * 8; i < 65536; i += 4096) {
        uint4 pr = *(const uint4*)(rb + i);      // 8 fp16 residuals
        float2 p0 = __half22float2(*(__half2*)&pr.x);
        float2 p1 = __half22float2(*(__half2*)&pr.y);
        float2 p2 = __half22float2(*(__half2*)&pr.z);
        float2 p3 = __half22float2(*(__half2*)&pr.w);
        float4 w0 = *(const float4*)(lnw + i);
        float4 w1 = *(const float4*)(lnw + i + 4);
        float4 b0 = *(const float4*)(lnb + i);
        float4 b1 = *(const float4*)(lnb + i + 4);
        float4 o0, o1;
        o0.x = (p0.x - mu) * rs * w0.x + b0.x;
        o0.y = (p0.y - mu) * rs * w0.y + b0.y;
        o0.z = (p1.x - mu) * rs * w0.z + b0.z;
        o0.w = (p1.y - mu) * rs * w0.w + b0.w;
        o1.x = (p2.x - mu) * rs * w1.x + b1.x;
        o1.y = (p2.y - mu) * rs * w1.y + b1.y;
        o1.z = (p3.x - mu) * rs * w1.z + b1.z;
        o1.w = (p3.y - mu) * rs * w1.w + b1.w;
        *(float4*)(yb + i) = o0;
        *(float4*)(yb + i + 4) = o1;
    }
}

// ---------------------------------------------------------------------------
extern "C" void kernel_launch(void* const* d_in, const int* in_sizes, int n_in,
                              void* d_out, int out_size)
{
    const float* x     = (const float*)d_in[0];
    const float* Wq    = (const float*)d_in[1];
    const float* bq    = (const float*)d_in[2];
    const float* Wk    = (const float*)d_in[3];
    const float* bk    = (const float*)d_in[4];
    const float* Wv    = (const float*)d_in[5];
    const float* bv    = (const float*)d_in[6];
    const float* Wp    = (const float*)d_in[7];
    const float* bp    = (const float*)d_in[8];
    const float* gamma = (const float*)d_in[9];
    const float* temp  = (const float*)d_in[10];
    const float* lnw   = (const float*)d_in[11];
    const float* lnb   = (const float*)d_in[12];
    float* y = (float*)d_out;

    cudaFuncSetAttribute(qkv_gemm_kernel, cudaFuncAttributeMaxDynamicSharedMemorySize, SM_GEMM);
    cudaFuncSetAttribute(proj_gemm_kernel, cudaFuncAttributeMaxDynamicSharedMemorySize, SM_GEMM);

    prep_w_kernel<<<4096, 256>>>(Wq, Wk, Wv, Wp);
    prep_x_kernel<<<BB, 256>>>(x);
    qkv_gemm_kernel<<<dim3(24, 512), 256, SM_GEMM>>>(bq, bk, bv);
    attn_kernel<<<BB * NH, 128>>>(temp);
    proj_gemm_kernel<<<dim3(8, 512), 256, SM_GEMM>>>(bp, x, gamma);
    ln_kernel<<<BB, 512>>>(lnw, lnb, y);
}